// round 5
// baseline (speedup 1.0000x reference)
#include <cuda_runtime.h>
#include <math.h>
#include <stdint.h>

#define B_SZ   8
#define T_SEQ  1024
#define D_MOD  256
#define M_ROWS (B_SZ * T_SEQ)   // 8192

// ---------------------------------------------------------------------------
// Scratch
// ---------------------------------------------------------------------------
#define OFF_QKV    0ul
#define OFF_ATTN   6291456ul
#define OFF_TMP    8388608ul
#define OFF_X      10485760ul
#define OFF_COMB   12582912ul
#define OFF_H      18874368ul
#define OFF_DELTAS 23068672ul
#define OFF_STATES 25165824ul
#define OFF_FFNIN  27262976ul
#define OFF_F      29360128ul
#define SCRATCH_TOTAL 37748736ul

__device__ float d_scratch[SCRATCH_TOTAL];

__device__ __forceinline__ float gelu_f(float x) {
    return 0.5f * x * (1.0f + erff(x * 0.70710678118654752f));
}

__device__ __forceinline__ uint32_t f2tf32(float x) {
    uint32_t r;
    asm("cvt.rna.tf32.f32 %0, %1;" : "=r"(r) : "f"(x));
    return r;
}

#define MMA_TF32(d, a, b) \
    asm volatile("mma.sync.aligned.m16n8k8.row.col.f32.tf32.tf32.f32 " \
                 "{%0,%1,%2,%3}, {%4,%5,%6,%7}, {%8,%9}, {%0,%1,%2,%3};" \
                 : "+f"(d[0]), "+f"(d[1]), "+f"(d[2]), "+f"(d[3]) \
                 : "r"(a[0]), "r"(a[1]), "r"(a[2]), "r"(a[3]), \
                   "r"(b[0]), "r"(b[1]))

// Fast exp(s/8): FMA-pipe only, no MUFU.
__device__ __forceinline__ float fexp_s8(float s) {
    const float y = s * 0.1803368801111244f;
    const float rnd = y + 12582912.0f;
    const int   i   = __float_as_int(rnd);
    const float nf  = rnd - 12582912.0f;
    const float f   = y - nf;
    float p = 1.3333558146e-3f;
    p = fmaf(p, f, 9.6181291076e-3f);
    p = fmaf(p, f, 5.5504108665e-2f);
    p = fmaf(p, f, 2.4022650696e-1f);
    p = fmaf(p, f, 6.9314718056e-1f);
    p = fmaf(p, f, 1.0f);
    const float scale = __int_as_float((i << 23) + 0x3f800000);
    return p * scale;
}

// ---------------------------------------------------------------------------
// TF32 GEMM v3: 3-stage cp.async pipeline, 1 syncthreads per k-tile,
// raw fp32 bits fed to tf32 mma. Template BN in {128, 64} for occupancy.
// C[M,N] = epi( A[M,K] @ W[N,K]^T + bias[N] )
// BM=128, BK=32, 256 threads, 8 warps 2(m) x 4(n); warp tile 64 x (BN/4).
// ---------------------------------------------------------------------------
#define ISSUE_TILE(k0, sidx)                                                   \
    {                                                                          \
        _Pragma("unroll")                                                      \
        for (int i = 0; i < 4; i++) {                                          \
            uint32_t da = smem_base + (uint32_t)((sidx) * STAGE + (mrow0 + 32 * i) * 36 + kq) * 4; \
            const float* ga = A + (size_t)(bm + mrow0 + 32 * i) * lda + (k0) + kq; \
            asm volatile("cp.async.cg.shared.global [%0], [%1], 16;" :: "r"(da), "l"(ga)); \
        }                                                                      \
        _Pragma("unroll")                                                      \
        for (int i = 0; i < BN / 32; i++) {                                    \
            uint32_t db = smem_base + (uint32_t)((sidx) * STAGE + 128 * 36 + (mrow0 + 32 * i) * 36 + kq) * 4; \
            const float* gw = W + (size_t)(bn + mrow0 + 32 * i) * (size_t)K + (k0) + kq; \
            asm volatile("cp.async.cg.shared.global [%0], [%1], 16;" :: "r"(db), "l"(gw)); \
        }                                                                      \
        asm volatile("cp.async.commit_group;");                                \
    }

template<int EPI, int BN>
__global__ void __launch_bounds__(256) mma_gemm(
    const float* __restrict__ A, int lda,
    const float* __restrict__ W,
    const float* __restrict__ bias,
    const float* __restrict__ addend, int ld_add,
    float* __restrict__ C, int ldc,
    int K)
{
    constexpr int NI    = BN / 32;          // n mma tiles per warp
    constexpr int STAGE = (128 + BN) * 36;  // u32 per stage (A + B)
    extern __shared__ uint32_t sm[];
    const uint32_t smem_base = (uint32_t)__cvta_generic_to_shared(sm);

    const int tid  = threadIdx.x;
    const int bm   = blockIdx.y * 128;
    const int bn   = blockIdx.x * BN;
    const int wid  = tid >> 5;
    const int lane = tid & 31;
    const int wm64 = (wid & 1) * 64;
    const int wn   = (wid >> 1) * (BN / 4);
    const int r    = lane >> 2;
    const int t    = lane & 3;

    const int kq    = (tid & 7) * 4;
    const int mrow0 = tid >> 3;

    float acc[4][NI][4];
    #pragma unroll
    for (int mi = 0; mi < 4; mi++)
        #pragma unroll
        for (int ni = 0; ni < NI; ni++)
            #pragma unroll
            for (int c = 0; c < 4; c++) acc[mi][ni][c] = 0.0f;

    const int ntiles = K >> 5;   // >= 8 for all layers here

    ISSUE_TILE(0, 0);
    ISSUE_TILE(32, 1);

    int sidx = 0;
    for (int kt = 0; kt < ntiles; kt++) {
        if (kt == ntiles - 1) {
            asm volatile("cp.async.wait_group 0;");
        } else {
            asm volatile("cp.async.wait_group 1;");
        }
        __syncthreads();

        if (kt + 2 < ntiles) {
            int ws = sidx + 2; if (ws >= 3) ws -= 3;
            ISSUE_TILE((kt + 2) * 32, ws);
        }

        const uint32_t* Ab = sm + sidx * STAGE;
        const uint32_t* Bb = Ab + 128 * 36;

        #pragma unroll
        for (int ks = 0; ks < 4; ks++) {
            const int kb = ks * 8;
            uint32_t a[4][4], b[NI][2];
            #pragma unroll
            for (int mi = 0; mi < 4; mi++) {
                int idx = (wm64 + mi * 16 + r) * 36 + kb + t;
                a[mi][0] = Ab[idx];
                a[mi][1] = Ab[idx + 8 * 36];
                a[mi][2] = Ab[idx + 4];
                a[mi][3] = Ab[idx + 8 * 36 + 4];
            }
            #pragma unroll
            for (int ni = 0; ni < NI; ni++) {
                int idx = (wn + ni * 8 + r) * 36 + kb + t;
                b[ni][0] = Bb[idx];
                b[ni][1] = Bb[idx + 4];
            }
            #pragma unroll
            for (int mi = 0; mi < 4; mi++)
                #pragma unroll
                for (int ni = 0; ni < NI; ni++)
                    MMA_TF32(acc[mi][ni], a[mi], b[ni]);
        }
        sidx++; if (sidx == 3) sidx = 0;
    }

    #pragma unroll
    for (int mi = 0; mi < 4; mi++) {
        const int row0 = bm + wm64 + mi * 16 + r;
        const int row1 = row0 + 8;
        #pragma unroll
        for (int ni = 0; ni < NI; ni++) {
            const int col = bn + wn + ni * 8 + 2 * t;
            const float2 bb = *(const float2*)(bias + col);
            float v00 = acc[mi][ni][0] + bb.x;
            float v01 = acc[mi][ni][1] + bb.y;
            float v10 = acc[mi][ni][2] + bb.x;
            float v11 = acc[mi][ni][3] + bb.y;
            if (EPI == 1) {
                const float2 r0 = *(const float2*)(addend + (size_t)row0 * ld_add + col);
                const float2 r1 = *(const float2*)(addend + (size_t)row1 * ld_add + col);
                v00 += r0.x; v01 += r0.y; v10 += r1.x; v11 += r1.y;
            }
            if (EPI == 2) {
                v00 = gelu_f(v00); v01 = gelu_f(v01);
                v10 = gelu_f(v10); v11 = gelu_f(v11);
            }
            if (EPI == 3) {
                const float2 r0 = *(const float2*)(addend + (size_t)row0 * ld_add + col);
                const float2 r1 = *(const float2*)(addend + (size_t)row1 * ld_add + col);
                v00 = r0.x + 0.3f * v00; v01 = r0.y + 0.3f * v01;
                v10 = r1.x + 0.3f * v10; v11 = r1.y + 0.3f * v11;
            }
            *(float2*)(C + (size_t)row0 * ldc + col) = make_float2(v00, v01);
            *(float2*)(C + (size_t)row1 * ldc + col) = make_float2(v10, v11);
        }
    }
}

#define GEMM_SMEM_128 (3 * (128 + 128) * 36 * 4)   // 110592 B
#define GEMM_SMEM_64  (3 * (128 + 64)  * 36 * 4)   // 82944 B

// ---------------------------------------------------------------------------
// TF32 mma causal flash-attention (unchanged from R3/R4).
// ---------------------------------------------------------------------------
__global__ void __launch_bounds__(256) attn_mma_kernel(
    const float* __restrict__ qkv, float* __restrict__ attn_out)
{
    __shared__ uint32_t Ks[64 * 68];
    __shared__ uint32_t Vs[64 * 72];

    const int bh = blockIdx.y;
    const int b  = bh >> 2;
    const int h  = bh & 3;
    const int qbase = blockIdx.x * 128;
    const int tid  = threadIdx.x;
    const int wid  = tid >> 5;
    const int lane = tid & 31;
    const int r    = lane >> 2;
    const int t    = lane & 3;
    const float* base = qkv + (size_t)b * T_SEQ * 768;

    const int qrow0 = qbase + wid * 16 + r;
    const int qrow1 = qrow0 + 8;

    uint32_t aq[8][4];
    {
        const float* q0 = base + (size_t)qrow0 * 768 + h * 64;
        const float* q1 = base + (size_t)qrow1 * 768 + h * 64;
        #pragma unroll
        for (int ks = 0; ks < 8; ks++) {
            aq[ks][0] = f2tf32(q0[ks * 8 + t]);
            aq[ks][1] = f2tf32(q1[ks * 8 + t]);
            aq[ks][2] = f2tf32(q0[ks * 8 + t + 4]);
            aq[ks][3] = f2tf32(q1[ks * 8 + t + 4]);
        }
    }

    float oacc[8][4];
    #pragma unroll
    for (int ni = 0; ni < 8; ni++)
        #pragma unroll
        for (int c = 0; c < 4; c++) oacc[ni][c] = 0.0f;
    float lsum0 = 0.0f, lsum1 = 0.0f;

    const int ntiles   = 2 * blockIdx.x + 2;
    const int wrow_max = qbase + wid * 16 + 15;
    const unsigned FULL = 0xffffffffu;
    const int s0 = (lane & ~3) | (t >> 1);
    const int s1 = s0 + 2;

    for (int jt = 0; jt < ntiles; jt++) {
        const int j0 = jt * 64;
        __syncthreads();
        #pragma unroll
        for (int i = 0; i < 4; i++) {
            int idx = tid + i * 256;
            int row = idx >> 4;
            int c4  = (idx & 15) * 4;
            const float* kp = base + (size_t)(j0 + row) * 768 + 256 + h * 64 + c4;
            float4 kv = *(const float4*)kp;
            uint4 kt4 = make_uint4(f2tf32(kv.x), f2tf32(kv.y), f2tf32(kv.z), f2tf32(kv.w));
            *(uint4*)&Ks[row * 68 + c4] = kt4;
            float4 vv = *(const float4*)(kp + 256);
            uint4 vt4 = make_uint4(f2tf32(vv.x), f2tf32(vv.y), f2tf32(vv.z), f2tf32(vv.w));
            *(uint4*)&Vs[row * 72 + c4] = vt4;
        }
        __syncthreads();

        if (j0 > wrow_max) continue;

        float sc[8][4];
        #pragma unroll
        for (int ni = 0; ni < 8; ni++)
            #pragma unroll
            for (int c = 0; c < 4; c++) sc[ni][c] = 0.0f;
        #pragma unroll
        for (int ks = 0; ks < 8; ks++) {
            #pragma unroll
            for (int ni = 0; ni < 8; ni++) {
                uint32_t bfr[2];
                const int key = ni * 8 + r;
                bfr[0] = Ks[key * 68 + ks * 8 + t];
                bfr[1] = Ks[key * 68 + ks * 8 + t + 4];
                MMA_TF32(sc[ni], aq[ks], bfr);
            }
        }

        #pragma unroll
        for (int ni = 0; ni < 8; ni++) {
            const int col0 = j0 + ni * 8 + 2 * t;
            float p0 = (col0     <= qrow0) ? fexp_s8(sc[ni][0]) : 0.0f;
            float p1 = (col0 + 1 <= qrow0) ? fexp_s8(sc[ni][1]) : 0.0f;
            float p2 = (col0     <= qrow1) ? fexp_s8(sc[ni][2]) : 0.0f;
            float p3 = (col0 + 1 <= qrow1) ? fexp_s8(sc[ni][3]) : 0.0f;
            lsum0 += p0 + p1;
            lsum1 += p2 + p3;
            sc[ni][0] = p0; sc[ni][1] = p1; sc[ni][2] = p2; sc[ni][3] = p3;
        }

        #pragma unroll
        for (int ks = 0; ks < 8; ks++) {
            uint32_t ap[4];
            float e, o;
            e = __shfl_sync(FULL, sc[ks][0], s0);
            o = __shfl_sync(FULL, sc[ks][1], s0);
            ap[0] = f2tf32((t & 1) ? o : e);
            e = __shfl_sync(FULL, sc[ks][2], s0);
            o = __shfl_sync(FULL, sc[ks][3], s0);
            ap[1] = f2tf32((t & 1) ? o : e);
            e = __shfl_sync(FULL, sc[ks][0], s1);
            o = __shfl_sync(FULL, sc[ks][1], s1);
            ap[2] = f2tf32((t & 1) ? o : e);
            e = __shfl_sync(FULL, sc[ks][2], s1);
            o = __shfl_sync(FULL, sc[ks][3], s1);
            ap[3] = f2tf32((t & 1) ? o : e);
            #pragma unroll
            for (int ni = 0; ni < 8; ni++) {
                uint32_t bfr[2];
                bfr[0] = Vs[(ks * 8 + t)     * 72 + ni * 8 + r];
                bfr[1] = Vs[(ks * 8 + t + 4) * 72 + ni * 8 + r];
                MMA_TF32(oacc[ni], ap, bfr);
            }
        }
    }

    lsum0 += __shfl_xor_sync(FULL, lsum0, 1);
    lsum0 += __shfl_xor_sync(FULL, lsum0, 2);
    lsum1 += __shfl_xor_sync(FULL, lsum1, 1);
    lsum1 += __shfl_xor_sync(FULL, lsum1, 2);
    const float inv0 = 1.0f / lsum0;
    const float inv1 = 1.0f / lsum1;

    float* op0 = attn_out + ((size_t)b * T_SEQ + qrow0) * 256 + h * 64;
    float* op1 = attn_out + ((size_t)b * T_SEQ + qrow1) * 256 + h * 64;
    #pragma unroll
    for (int ni = 0; ni < 8; ni++) {
        *(float2*)(op0 + ni * 8 + 2 * t) = make_float2(oacc[ni][0] * inv0, oacc[ni][1] * inv0);
        *(float2*)(op1 + ni * 8 + 2 * t) = make_float2(oacc[ni][2] * inv1, oacc[ni][3] * inv1);
    }
}

// ---------------------------------------------------------------------------
// LayerNorm, warp-per-row (unchanged).
// ---------------------------------------------------------------------------
__global__ void __launch_bounds__(256) ln_warp_kernel(
    const float* __restrict__ in, long ld_in,
    const float* __restrict__ gamma, const float* __restrict__ beta,
    float* __restrict__ out, long ld_out, int nrows)
{
    const int wid = threadIdx.x >> 5, lane = threadIdx.x & 31;
    const int row = blockIdx.x * 8 + wid;
    if (row >= nrows) return;
    const float* ip = in + (size_t)row * ld_in + lane * 8;
    float4 v0 = ((const float4*)ip)[0];
    float4 v1 = ((const float4*)ip)[1];

    float s  = v0.x + v0.y + v0.z + v0.w + v1.x + v1.y + v1.z + v1.w;
    float sq = v0.x*v0.x + v0.y*v0.y + v0.z*v0.z + v0.w*v0.w
             + v1.x*v1.x + v1.y*v1.y + v1.z*v1.z + v1.w*v1.w;
    #pragma unroll
    for (int o = 16; o > 0; o >>= 1) {
        s  += __shfl_xor_sync(0xffffffffu, s,  o);
        sq += __shfl_xor_sync(0xffffffffu, sq, o);
    }
    const float mean = s * (1.0f / 256.0f);
    const float var  = sq * (1.0f / 256.0f) - mean * mean;
    const float rstd = rsqrtf(var + 1e-5f);

    const float4 g0 = ((const float4*)(gamma + lane * 8))[0];
    const float4 g1 = ((const float4*)(gamma + lane * 8))[1];
    const float4 b0 = ((const float4*)(beta  + lane * 8))[0];
    const float4 b1 = ((const float4*)(beta  + lane * 8))[1];
    float4 r0, r1;
    r0.x = (v0.x - mean) * rstd * g0.x + b0.x;
    r0.y = (v0.y - mean) * rstd * g0.y + b0.y;
    r0.z = (v0.z - mean) * rstd * g0.z + b0.z;
    r0.w = (v0.w - mean) * rstd * g0.w + b0.w;
    r1.x = (v1.x - mean) * rstd * g1.x + b1.x;
    r1.y = (v1.y - mean) * rstd * g1.y + b1.y;
    r1.z = (v1.z - mean) * rstd * g1.z + b1.z;
    r1.w = (v1.w - mean) * rstd * g1.w + b1.w;
    float* op = out + (size_t)row * ld_out + lane * 8;
    ((float4*)op)[0] = r0;
    ((float4*)op)[1] = r1;
}

__global__ void __launch_bounds__(256) conv_kernel(
    const float* __restrict__ x, const float* __restrict__ cw,
    const float* __restrict__ cb, float* __restrict__ comb)
{
    const int idx = blockIdx.x * 256 + threadIdx.x;
    const int d = idx & 255;
    const int t = (idx >> 8) & 1023;
    const int b = idx >> 18;
    float r = cb[d];
    #pragma unroll
    for (int w = 0; w < 8; w++) {
        int tt = t - 7 + w;
        if (tt >= 0) r = fmaf(cw[d * 8 + w], x[((size_t)b * 1024 + tt) * 256 + d], r);
    }
    comb[((size_t)b * 1024 + t) * 768 + 256 + d] = r;
}

// ---------------------------------------------------------------------------
// EMA, chunk-parallel: 0.9^256 ~ 2e-12, so each 128-step chunk recomputes
// from a 256-step lookback starting at c=0. grid (B, T/128), block 256 (=d).
// ---------------------------------------------------------------------------
__global__ void __launch_bounds__(256) ema_kernel(
    const float* __restrict__ x, float* __restrict__ comb)
{
    const int b = blockIdx.x, chunk = blockIdx.y, d = threadIdx.x;
    const int t0 = chunk * 128;
    int start = t0 - 256; if (start < 0) start = 0;
    const float* xp = x + (size_t)b * 1024 * 256 + d;
    float c = 0.0f;
    #pragma unroll 8
    for (int t = start; t < t0; t++)
        c = fmaf(0.9f, c, 0.1f * xp[(size_t)t * 256]);
    float* op = comb + (size_t)b * 1024 * 768 + 512 + d;
    #pragma unroll 8
    for (int t = t0; t < t0 + 128; t++) {
        c = fmaf(0.9f, c, 0.1f * xp[(size_t)t * 256]);
        op[(size_t)t * 768] = c;
    }
}

__global__ void __launch_bounds__(256) cumsum_kernel(
    const float* __restrict__ deltas, const float* __restrict__ seq,
    float* __restrict__ states)
{
    const int b = blockIdx.x, d = threadIdx.x;
    float c = seq[b * 256 + d];
    const float* dp = deltas + (size_t)b * 1024 * 256 + d;
    float* sp = states + (size_t)b * 1024 * 256 + d;
    #pragma unroll 8
    for (int t = 0; t < 1024; t++) {
        c = fmaf(0.5f, dp[(size_t)t * 256], c);
        sp[(size_t)t * 256] = c;
    }
}

__global__ void traj_kernel(const float* __restrict__ comb, float* __restrict__ out)
{
    const int b = blockIdx.x, d = threadIdx.x;
    out[b * 256 + d] = comb[((size_t)b * 1024 + 1023) * 768 + 512 + d];
}

// ---------------------------------------------------------------------------
// Launch
// ---------------------------------------------------------------------------
extern "C" void kernel_launch(void* const* d_in, const int* in_sizes, int n_in,
                              void* d_out, int out_size)
{
    const float* x_in       = (const float*)d_in[0];
    const float* seq_state  = (const float*)d_in[1];
    const float* in_proj_w  = (const float*)d_in[3];
    const float* in_proj_b  = (const float*)d_in[4];
    const float* out_proj_w = (const float*)d_in[5];
    const float* out_proj_b = (const float*)d_in[6];
    const float* conv_w     = (const float*)d_in[7];
    const float* conv_b     = (const float*)d_in[8];
    const float* p2s_w      = (const float*)d_in[9];
    const float* p2s_b      = (const float*)d_in[10];
    const float* s2p_w      = (const float*)d_in[11];
    const float* s2p_b      = (const float*)d_in[12];
    const float* tw1        = (const float*)d_in[13];
    const float* tb1        = (const float*)d_in[14];
    const float* tw2        = (const float*)d_in[15];
    const float* tb2        = (const float*)d_in[16];
    const float* fw1        = (const float*)d_in[17];
    const float* fb1        = (const float*)d_in[18];
    const float* fw2        = (const float*)d_in[19];
    const float* fb2        = (const float*)d_in[20];
    const float* ln1s = (const float*)d_in[21];
    const float* ln1b = (const float*)d_in[22];
    const float* ln2s = (const float*)d_in[23];
    const float* ln2b = (const float*)d_in[24];
    const float* ln3s = (const float*)d_in[25];
    const float* ln3b = (const float*)d_in[26];
    const float* ln4s = (const float*)d_in[27];
    const float* ln4b = (const float*)d_in[28];
    float* out = (float*)d_out;

    float* scr = nullptr;
    cudaGetSymbolAddress((void**)&scr, d_scratch);
    float* qkv    = scr + OFF_QKV;
    float* attn   = scr + OFF_ATTN;
    float* tmp    = scr + OFF_TMP;
    float* xb     = scr + OFF_X;
    float* comb   = scr + OFF_COMB;
    float* hb     = scr + OFF_H;
    float* deltas = scr + OFF_DELTAS;
    float* states = scr + OFF_STATES;
    float* ffnin  = scr + OFF_FFNIN;
    float* fbuf   = scr + OFF_F;

    static bool attr_set = false;
    if (!attr_set) {
        cudaFuncSetAttribute(mma_gemm<0,128>, cudaFuncAttributeMaxDynamicSharedMemorySize, GEMM_SMEM_128);
        cudaFuncSetAttribute(mma_gemm<2,128>, cudaFuncAttributeMaxDynamicSharedMemorySize, GEMM_SMEM_128);
        cudaFuncSetAttribute(mma_gemm<0,64>,  cudaFuncAttributeMaxDynamicSharedMemorySize, GEMM_SMEM_64);
        cudaFuncSetAttribute(mma_gemm<1,64>,  cudaFuncAttributeMaxDynamicSharedMemorySize, GEMM_SMEM_64);
        cudaFuncSetAttribute(mma_gemm<3,64>,  cudaFuncAttributeMaxDynamicSharedMemorySize, GEMM_SMEM_64);
        attr_set = true;
    }

    // 1. qkv = x @ in_proj_w^T + b                 [8192,768], K=256
    mma_gemm<0,128><<<dim3(6, 64), 256, GEMM_SMEM_128>>>(x_in, 256, in_proj_w, in_proj_b,
                                                         nullptr, 0, qkv, 768, 256);
    // 2. causal attention (tf32 mma)
    attn_mma_kernel<<<dim3(8, 32), 256>>>(qkv, attn);
    // 3. out_proj + residual                       N=256, K=256
    mma_gemm<1,64><<<dim3(4, 64), 256, GEMM_SMEM_64>>>(attn, 256, out_proj_w, out_proj_b,
                                                       x_in, 256, tmp, 256, 256);
    // 4. x = LN1(tmp)
    ln_warp_kernel<<<1024, 256>>>(tmp, 256, ln1s, ln1b, xb, 256, 8192);
    // 5. conv -> combined[:,256:512]
    conv_kernel<<<8192, 256>>>(xb, conv_w, conv_b, comb);
    // 6. EMA -> combined[:,512:768]  (chunk-parallel)
    ema_kernel<<<dim3(8, 8), 256>>>(xb, comb);
    // 7. combined[:,0:256] = x + 0.3*(x @ p2s^T + b)   N=256, K=256
    mma_gemm<3,64><<<dim3(4, 64), 256, GEMM_SMEM_64>>>(xb, 256, p2s_w, p2s_b,
                                                       xb, 256, comb, 768, 256);
    // 8. h = gelu(comb @ tw1^T + b1)               N=512, K=768
    mma_gemm<2,128><<<dim3(4, 64), 256, GEMM_SMEM_128>>>(comb, 768, tw1, tb1,
                                                         nullptr, 0, hb, 512, 768);
    // 9. deltas = h @ tw2^T + b2                   N=256, K=512
    mma_gemm<0,64><<<dim3(4, 64), 256, GEMM_SMEM_64>>>(hb, 512, tw2, tb2,
                                                       nullptr, 0, deltas, 256, 512);
    // 10. states = seq + 0.5*cumsum(deltas)
    cumsum_kernel<<<8, 256>>>(deltas, seq_state, states);
    // 11. states = LN3(states)
    ln_warp_kernel<<<1024, 256>>>(states, 256, ln3s, ln3b, states, 256, 8192);
    // 12. ffn_in = x + 0.3*(states @ s2p^T + b)    N=256, K=256
    mma_gemm<3,64><<<dim3(4, 64), 256, GEMM_SMEM_64>>>(states, 256, s2p_w, s2p_b,
                                                       xb, 256, ffnin, 256, 256);
    // 13. f = gelu(ffn_in @ fw1^T + b1)            N=1024, K=256
    mma_gemm<2,128><<<dim3(8, 64), 256, GEMM_SMEM_128>>>(ffnin, 256, fw1, fb1,
                                                         nullptr, 0, fbuf, 1024, 256);
    // 14. tmp = x + f @ fw2^T + b2                 N=256, K=1024
    mma_gemm<1,64><<<dim3(4, 64), 256, GEMM_SMEM_64>>>(fbuf, 1024, fw2, fb2,
                                                       xb, 256, tmp, 256, 1024);
    // 15. LN2 -> out
    ln_warp_kernel<<<1024, 256>>>(tmp, 256, ln2s, ln2b, out, 256, 8192);
    // 16. LN4(states[:, -1, :])
    ln_warp_kernel<<<1, 256>>>(states + (size_t)1023 * 256, (long)1024 * 256,
                               ln4s, ln4b, out + (size_t)M_ROWS * 256, 256, 8);
    // 17. trajectory summary
    traj_kernel<<<8, 256>>>(comb, out + (size_t)M_ROWS * 256 + 2048);
}

// round 6
// speedup vs baseline: 1.0846x; 1.0846x over previous
#include <cuda_runtime.h>
#include <math.h>
#include <stdint.h>

#define B_SZ   8
#define T_SEQ  1024
#define D_MOD  256
#define M_ROWS (B_SZ * T_SEQ)   // 8192

// ---------------------------------------------------------------------------
// Scratch
// ---------------------------------------------------------------------------
#define OFF_QKV    0ul
#define OFF_ATTN   6291456ul
#define OFF_TMP    8388608ul
#define OFF_X      10485760ul
#define OFF_COMB   12582912ul
#define OFF_H      18874368ul
#define OFF_DELTAS 23068672ul
#define OFF_STATES 25165824ul
#define OFF_FFNIN  27262976ul
#define OFF_F      29360128ul
#define SCRATCH_TOTAL 37748736ul

__device__ float d_scratch[SCRATCH_TOTAL];

__device__ __forceinline__ float gelu_f(float x) {
    return 0.5f * x * (1.0f + erff(x * 0.70710678118654752f));
}

__device__ __forceinline__ uint32_t f2tf32(float x) {
    uint32_t r;
    asm("cvt.rna.tf32.f32 %0, %1;" : "=r"(r) : "f"(x));
    return r;
}

#define MMA_TF32(d, a, b) \
    asm volatile("mma.sync.aligned.m16n8k8.row.col.f32.tf32.tf32.f32 " \
                 "{%0,%1,%2,%3}, {%4,%5,%6,%7}, {%8,%9}, {%0,%1,%2,%3};" \
                 : "+f"(d[0]), "+f"(d[1]), "+f"(d[2]), "+f"(d[3]) \
                 : "r"(a[0]), "r"(a[1]), "r"(a[2]), "r"(a[3]), \
                   "r"(b[0]), "r"(b[1]))

// Fast exp(s/8): FMA-pipe only, no MUFU.
__device__ __forceinline__ float fexp_s8(float s) {
    const float y = s * 0.1803368801111244f;
    const float rnd = y + 12582912.0f;
    const int   i   = __float_as_int(rnd);
    const float nf  = rnd - 12582912.0f;
    const float f   = y - nf;
    float p = 1.3333558146e-3f;
    p = fmaf(p, f, 9.6181291076e-3f);
    p = fmaf(p, f, 5.5504108665e-2f);
    p = fmaf(p, f, 2.4022650696e-1f);
    p = fmaf(p, f, 6.9314718056e-1f);
    p = fmaf(p, f, 1.0f);
    const float scale = __int_as_float((i << 23) + 0x3f800000);
    return p * scale;
}

// ---------------------------------------------------------------------------
// TF32 GEMM (R4 config + occupancy 2): cp.async double-buffered, BM=BN=128,
// BK=32, 256 threads, warp tile 64x32 (NI=4 keeps mainloop tensor-bound).
// __launch_bounds__(256,2): two CTAs/SM so sync/wait bubbles overlap.
// C[M,N] = epi( A[M,K] @ W[N,K]^T + bias[N] )
// ---------------------------------------------------------------------------
#define GEMM_TS (128 * 36)

#define ISSUE_TILE(k0, bufbase)                                                \
    {                                                                          \
        _Pragma("unroll")                                                      \
        for (int i = 0; i < 4; i++) {                                          \
            uint32_t da = smem_base + (uint32_t)(((bufbase) + (mrow0 + 32 * i) * 36 + kq) * 4); \
            const float* ga = A + (size_t)(bm + mrow0 + 32 * i) * lda + (k0) + kq; \
            asm volatile("cp.async.cg.shared.global [%0], [%1], 16;" :: "r"(da), "l"(ga)); \
            uint32_t db = smem_base + (uint32_t)(((bufbase) + GEMM_TS + (mrow0 + 32 * i) * 36 + kq) * 4); \
            const float* gw = W + (size_t)(bn + mrow0 + 32 * i) * (size_t)K + (k0) + kq; \
            asm volatile("cp.async.cg.shared.global [%0], [%1], 16;" :: "r"(db), "l"(gw)); \
        }                                                                      \
        asm volatile("cp.async.commit_group;");                                \
    }

template<int EPI>
__global__ void __launch_bounds__(256, 2) mma_gemm(
    const float* __restrict__ A, int lda,
    const float* __restrict__ W,
    const float* __restrict__ bias,
    const float* __restrict__ addend, int ld_add,
    float* __restrict__ C, int ldc,
    int K)
{
    extern __shared__ uint32_t sm[];
    const uint32_t smem_base = (uint32_t)__cvta_generic_to_shared(sm);

    const int tid  = threadIdx.x;
    const int bm   = blockIdx.y * 128;
    const int bn   = blockIdx.x * 128;
    const int wid  = tid >> 5;
    const int lane = tid & 31;
    const int wm64 = (wid & 1) * 64;
    const int wn32 = (wid >> 1) * 32;
    const int r    = lane >> 2;
    const int t    = lane & 3;

    const int kq    = (tid & 7) * 4;
    const int mrow0 = tid >> 3;

    float acc[4][4][4];
    #pragma unroll
    for (int mi = 0; mi < 4; mi++)
        #pragma unroll
        for (int ni = 0; ni < 4; ni++)
            #pragma unroll
            for (int c = 0; c < 4; c++) acc[mi][ni][c] = 0.0f;

    const int ntiles = K >> 5;

    ISSUE_TILE(0, 0);

    for (int kt = 0; kt < ntiles; kt++) {
        if (kt + 1 < ntiles) {
            ISSUE_TILE((kt + 1) * 32, ((kt + 1) & 1) * 2 * GEMM_TS);
            asm volatile("cp.async.wait_group 1;");
        } else {
            asm volatile("cp.async.wait_group 0;");
        }
        __syncthreads();

        const uint32_t* Ab = sm + (kt & 1) * 2 * GEMM_TS;
        const uint32_t* Bb = Ab + GEMM_TS;

        #pragma unroll
        for (int ks = 0; ks < 4; ks++) {
            const int kb = ks * 8;
            uint32_t a[4][4], b[4][2];
            #pragma unroll
            for (int mi = 0; mi < 4; mi++) {
                int idx = (wm64 + mi * 16 + r) * 36 + kb + t;
                a[mi][0] = Ab[idx];
                a[mi][1] = Ab[idx + 8 * 36];
                a[mi][2] = Ab[idx + 4];
                a[mi][3] = Ab[idx + 8 * 36 + 4];
            }
            #pragma unroll
            for (int ni = 0; ni < 4; ni++) {
                int idx = (wn32 + ni * 8 + r) * 36 + kb + t;
                b[ni][0] = Bb[idx];
                b[ni][1] = Bb[idx + 4];
            }
            #pragma unroll
            for (int mi = 0; mi < 4; mi++)
                #pragma unroll
                for (int ni = 0; ni < 4; ni++)
                    MMA_TF32(acc[mi][ni], a[mi], b[ni]);
        }
        __syncthreads();
    }

    #pragma unroll
    for (int mi = 0; mi < 4; mi++) {
        const int row0 = bm + wm64 + mi * 16 + r;
        const int row1 = row0 + 8;
        #pragma unroll
        for (int ni = 0; ni < 4; ni++) {
            const int col = bn + wn32 + ni * 8 + 2 * t;
            const float2 bb = *(const float2*)(bias + col);
            float v00 = acc[mi][ni][0] + bb.x;
            float v01 = acc[mi][ni][1] + bb.y;
            float v10 = acc[mi][ni][2] + bb.x;
            float v11 = acc[mi][ni][3] + bb.y;
            if (EPI == 1) {
                const float2 r0 = *(const float2*)(addend + (size_t)row0 * ld_add + col);
                const float2 r1 = *(const float2*)(addend + (size_t)row1 * ld_add + col);
                v00 += r0.x; v01 += r0.y; v10 += r1.x; v11 += r1.y;
            }
            if (EPI == 2) {
                v00 = gelu_f(v00); v01 = gelu_f(v01);
                v10 = gelu_f(v10); v11 = gelu_f(v11);
            }
            if (EPI == 3) {
                const float2 r0 = *(const float2*)(addend + (size_t)row0 * ld_add + col);
                const float2 r1 = *(const float2*)(addend + (size_t)row1 * ld_add + col);
                v00 = r0.x + 0.3f * v00; v01 = r0.y + 0.3f * v01;
                v10 = r1.x + 0.3f * v10; v11 = r1.y + 0.3f * v11;
            }
            *(float2*)(C + (size_t)row0 * ldc + col) = make_float2(v00, v01);
            *(float2*)(C + (size_t)row1 * ldc + col) = make_float2(v10, v11);
        }
    }
}

#define GEMM_SMEM (2 * 2 * GEMM_TS * 4)   // 73728 bytes -> 2 CTAs/SM

// ---------------------------------------------------------------------------
// TF32 mma causal flash-attention (unchanged).
// ---------------------------------------------------------------------------
__global__ void __launch_bounds__(256) attn_mma_kernel(
    const float* __restrict__ qkv, float* __restrict__ attn_out)
{
    __shared__ uint32_t Ks[64 * 68];
    __shared__ uint32_t Vs[64 * 72];

    const int bh = blockIdx.y;
    const int b  = bh >> 2;
    const int h  = bh & 3;
    const int qbase = blockIdx.x * 128;
    const int tid  = threadIdx.x;
    const int wid  = tid >> 5;
    const int lane = tid & 31;
    const int r    = lane >> 2;
    const int t    = lane & 3;
    const float* base = qkv + (size_t)b * T_SEQ * 768;

    const int qrow0 = qbase + wid * 16 + r;
    const int qrow1 = qrow0 + 8;

    uint32_t aq[8][4];
    {
        const float* q0 = base + (size_t)qrow0 * 768 + h * 64;
        const float* q1 = base + (size_t)qrow1 * 768 + h * 64;
        #pragma unroll
        for (int ks = 0; ks < 8; ks++) {
            aq[ks][0] = f2tf32(q0[ks * 8 + t]);
            aq[ks][1] = f2tf32(q1[ks * 8 + t]);
            aq[ks][2] = f2tf32(q0[ks * 8 + t + 4]);
            aq[ks][3] = f2tf32(q1[ks * 8 + t + 4]);
        }
    }

    float oacc[8][4];
    #pragma unroll
    for (int ni = 0; ni < 8; ni++)
        #pragma unroll
        for (int c = 0; c < 4; c++) oacc[ni][c] = 0.0f;
    float lsum0 = 0.0f, lsum1 = 0.0f;

    const int ntiles   = 2 * blockIdx.x + 2;
    const int wrow_max = qbase + wid * 16 + 15;
    const unsigned FULL = 0xffffffffu;
    const int s0 = (lane & ~3) | (t >> 1);
    const int s1 = s0 + 2;

    for (int jt = 0; jt < ntiles; jt++) {
        const int j0 = jt * 64;
        __syncthreads();
        #pragma unroll
        for (int i = 0; i < 4; i++) {
            int idx = tid + i * 256;
            int row = idx >> 4;
            int c4  = (idx & 15) * 4;
            const float* kp = base + (size_t)(j0 + row) * 768 + 256 + h * 64 + c4;
            float4 kv = *(const float4*)kp;
            uint4 kt4 = make_uint4(f2tf32(kv.x), f2tf32(kv.y), f2tf32(kv.z), f2tf32(kv.w));
            *(uint4*)&Ks[row * 68 + c4] = kt4;
            float4 vv = *(const float4*)(kp + 256);
            uint4 vt4 = make_uint4(f2tf32(vv.x), f2tf32(vv.y), f2tf32(vv.z), f2tf32(vv.w));
            *(uint4*)&Vs[row * 72 + c4] = vt4;
        }
        __syncthreads();

        if (j0 > wrow_max) continue;

        float sc[8][4];
        #pragma unroll
        for (int ni = 0; ni < 8; ni++)
            #pragma unroll
            for (int c = 0; c < 4; c++) sc[ni][c] = 0.0f;
        #pragma unroll
        for (int ks = 0; ks < 8; ks++) {
            #pragma unroll
            for (int ni = 0; ni < 8; ni++) {
                uint32_t bfr[2];
                const int key = ni * 8 + r;
                bfr[0] = Ks[key * 68 + ks * 8 + t];
                bfr[1] = Ks[key * 68 + ks * 8 + t + 4];
                MMA_TF32(sc[ni], aq[ks], bfr);
            }
        }

        #pragma unroll
        for (int ni = 0; ni < 8; ni++) {
            const int col0 = j0 + ni * 8 + 2 * t;
            float p0 = (col0     <= qrow0) ? fexp_s8(sc[ni][0]) : 0.0f;
            float p1 = (col0 + 1 <= qrow0) ? fexp_s8(sc[ni][1]) : 0.0f;
            float p2 = (col0     <= qrow1) ? fexp_s8(sc[ni][2]) : 0.0f;
            float p3 = (col0 + 1 <= qrow1) ? fexp_s8(sc[ni][3]) : 0.0f;
            lsum0 += p0 + p1;
            lsum1 += p2 + p3;
            sc[ni][0] = p0; sc[ni][1] = p1; sc[ni][2] = p2; sc[ni][3] = p3;
        }

        #pragma unroll
        for (int ks = 0; ks < 8; ks++) {
            uint32_t ap[4];
            float e, o;
            e = __shfl_sync(FULL, sc[ks][0], s0);
            o = __shfl_sync(FULL, sc[ks][1], s0);
            ap[0] = f2tf32((t & 1) ? o : e);
            e = __shfl_sync(FULL, sc[ks][2], s0);
            o = __shfl_sync(FULL, sc[ks][3], s0);
            ap[1] = f2tf32((t & 1) ? o : e);
            e = __shfl_sync(FULL, sc[ks][0], s1);
            o = __shfl_sync(FULL, sc[ks][1], s1);
            ap[2] = f2tf32((t & 1) ? o : e);
            e = __shfl_sync(FULL, sc[ks][2], s1);
            o = __shfl_sync(FULL, sc[ks][3], s1);
            ap[3] = f2tf32((t & 1) ? o : e);
            #pragma unroll
            for (int ni = 0; ni < 8; ni++) {
                uint32_t bfr[2];
                bfr[0] = Vs[(ks * 8 + t)     * 72 + ni * 8 + r];
                bfr[1] = Vs[(ks * 8 + t + 4) * 72 + ni * 8 + r];
                MMA_TF32(oacc[ni], ap, bfr);
            }
        }
    }

    lsum0 += __shfl_xor_sync(FULL, lsum0, 1);
    lsum0 += __shfl_xor_sync(FULL, lsum0, 2);
    lsum1 += __shfl_xor_sync(FULL, lsum1, 1);
    lsum1 += __shfl_xor_sync(FULL, lsum1, 2);
    const float inv0 = 1.0f / lsum0;
    const float inv1 = 1.0f / lsum1;

    float* op0 = attn_out + ((size_t)b * T_SEQ + qrow0) * 256 + h * 64;
    float* op1 = attn_out + ((size_t)b * T_SEQ + qrow1) * 256 + h * 64;
    #pragma unroll
    for (int ni = 0; ni < 8; ni++) {
        *(float2*)(op0 + ni * 8 + 2 * t) = make_float2(oacc[ni][0] * inv0, oacc[ni][1] * inv0);
        *(float2*)(op1 + ni * 8 + 2 * t) = make_float2(oacc[ni][2] * inv1, oacc[ni][3] * inv1);
    }
}

// ---------------------------------------------------------------------------
// LayerNorm, warp-per-row (unchanged).
// ---------------------------------------------------------------------------
__global__ void __launch_bounds__(256) ln_warp_kernel(
    const float* __restrict__ in, long ld_in,
    const float* __restrict__ gamma, const float* __restrict__ beta,
    float* __restrict__ out, long ld_out, int nrows)
{
    const int wid = threadIdx.x >> 5, lane = threadIdx.x & 31;
    const int row = blockIdx.x * 8 + wid;
    if (row >= nrows) return;
    const float* ip = in + (size_t)row * ld_in + lane * 8;
    float4 v0 = ((const float4*)ip)[0];
    float4 v1 = ((const float4*)ip)[1];

    float s  = v0.x + v0.y + v0.z + v0.w + v1.x + v1.y + v1.z + v1.w;
    float sq = v0.x*v0.x + v0.y*v0.y + v0.z*v0.z + v0.w*v0.w
             + v1.x*v1.x + v1.y*v1.y + v1.z*v1.z + v1.w*v1.w;
    #pragma unroll
    for (int o = 16; o > 0; o >>= 1) {
        s  += __shfl_xor_sync(0xffffffffu, s,  o);
        sq += __shfl_xor_sync(0xffffffffu, sq, o);
    }
    const float mean = s * (1.0f / 256.0f);
    const float var  = sq * (1.0f / 256.0f) - mean * mean;
    const float rstd = rsqrtf(var + 1e-5f);

    const float4 g0 = ((const float4*)(gamma + lane * 8))[0];
    const float4 g1 = ((const float4*)(gamma + lane * 8))[1];
    const float4 b0 = ((const float4*)(beta  + lane * 8))[0];
    const float4 b1 = ((const float4*)(beta  + lane * 8))[1];
    float4 r0, r1;
    r0.x = (v0.x - mean) * rstd * g0.x + b0.x;
    r0.y = (v0.y - mean) * rstd * g0.y + b0.y;
    r0.z = (v0.z - mean) * rstd * g0.z + b0.z;
    r0.w = (v0.w - mean) * rstd * g0.w + b0.w;
    r1.x = (v1.x - mean) * rstd * g1.x + b1.x;
    r1.y = (v1.y - mean) * rstd * g1.y + b1.y;
    r1.z = (v1.z - mean) * rstd * g1.z + b1.z;
    r1.w = (v1.w - mean) * rstd * g1.w + b1.w;
    float* op = out + (size_t)row * ld_out + lane * 8;
    ((float4*)op)[0] = r0;
    ((float4*)op)[1] = r1;
}

__global__ void __launch_bounds__(256) conv_kernel(
    const float* __restrict__ x, const float* __restrict__ cw,
    const float* __restrict__ cb, float* __restrict__ comb)
{
    const int idx = blockIdx.x * 256 + threadIdx.x;
    const int d = idx & 255;
    const int t = (idx >> 8) & 1023;
    const int b = idx >> 18;
    float r = cb[d];
    #pragma unroll
    for (int w = 0; w < 8; w++) {
        int tt = t - 7 + w;
        if (tt >= 0) r = fmaf(cw[d * 8 + w], x[((size_t)b * 1024 + tt) * 256 + d], r);
    }
    comb[((size_t)b * 1024 + t) * 768 + 256 + d] = r;
}

// ---------------------------------------------------------------------------
// EMA, chunk-parallel (0.9^256 ~ 2e-12 lookback truncation).
// ---------------------------------------------------------------------------
__global__ void __launch_bounds__(256) ema_kernel(
    const float* __restrict__ x, float* __restrict__ comb)
{
    const int b = blockIdx.x, chunk = blockIdx.y, d = threadIdx.x;
    const int t0 = chunk * 128;
    int start = t0 - 256; if (start < 0) start = 0;
    const float* xp = x + (size_t)b * 1024 * 256 + d;
    float c = 0.0f;
    #pragma unroll 8
    for (int t = start; t < t0; t++)
        c = fmaf(0.9f, c, 0.1f * xp[(size_t)t * 256]);
    float* op = comb + (size_t)b * 1024 * 768 + 512 + d;
    #pragma unroll 8
    for (int t = t0; t < t0 + 128; t++) {
        c = fmaf(0.9f, c, 0.1f * xp[(size_t)t * 256]);
        op[(size_t)t * 768] = c;
    }
}

__global__ void __launch_bounds__(256) cumsum_kernel(
    const float* __restrict__ deltas, const float* __restrict__ seq,
    float* __restrict__ states)
{
    const int b = blockIdx.x, d = threadIdx.x;
    float c = seq[b * 256 + d];
    const float* dp = deltas + (size_t)b * 1024 * 256 + d;
    float* sp = states + (size_t)b * 1024 * 256 + d;
    #pragma unroll 8
    for (int t = 0; t < 1024; t++) {
        c = fmaf(0.5f, dp[(size_t)t * 256], c);
        sp[(size_t)t * 256] = c;
    }
}

__global__ void traj_kernel(const float* __restrict__ comb, float* __restrict__ out)
{
    const int b = blockIdx.x, d = threadIdx.x;
    out[b * 256 + d] = comb[((size_t)b * 1024 + 1023) * 768 + 512 + d];
}

// ---------------------------------------------------------------------------
// Launch
// ---------------------------------------------------------------------------
extern "C" void kernel_launch(void* const* d_in, const int* in_sizes, int n_in,
                              void* d_out, int out_size)
{
    const float* x_in       = (const float*)d_in[0];
    const float* seq_state  = (const float*)d_in[1];
    const float* in_proj_w  = (const float*)d_in[3];
    const float* in_proj_b  = (const float*)d_in[4];
    const float* out_proj_w = (const float*)d_in[5];
    const float* out_proj_b = (const float*)d_in[6];
    const float* conv_w     = (const float*)d_in[7];
    const float* conv_b     = (const float*)d_in[8];
    const float* p2s_w      = (const float*)d_in[9];
    const float* p2s_b      = (const float*)d_in[10];
    const float* s2p_w      = (const float*)d_in[11];
    const float* s2p_b      = (const float*)d_in[12];
    const float* tw1        = (const float*)d_in[13];
    const float* tb1        = (const float*)d_in[14];
    const float* tw2        = (const float*)d_in[15];
    const float* tb2        = (const float*)d_in[16];
    const float* fw1        = (const float*)d_in[17];
    const float* fb1        = (const float*)d_in[18];
    const float* fw2        = (const float*)d_in[19];
    const float* fb2        = (const float*)d_in[20];
    const float* ln1s = (const float*)d_in[21];
    const float* ln1b = (const float*)d_in[22];
    const float* ln2s = (const float*)d_in[23];
    const float* ln2b = (const float*)d_in[24];
    const float* ln3s = (const float*)d_in[25];
    const float* ln3b = (const float*)d_in[26];
    const float* ln4s = (const float*)d_in[27];
    const float* ln4b = (const float*)d_in[28];
    float* out = (float*)d_out;

    float* scr = nullptr;
    cudaGetSymbolAddress((void**)&scr, d_scratch);
    float* qkv    = scr + OFF_QKV;
    float* attn   = scr + OFF_ATTN;
    float* tmp    = scr + OFF_TMP;
    float* xb     = scr + OFF_X;
    float* comb   = scr + OFF_COMB;
    float* hb     = scr + OFF_H;
    float* deltas = scr + OFF_DELTAS;
    float* states = scr + OFF_STATES;
    float* ffnin  = scr + OFF_FFNIN;
    float* fbuf   = scr + OFF_F;

    static bool attr_set = false;
    if (!attr_set) {
        cudaFuncSetAttribute(mma_gemm<0>, cudaFuncAttributeMaxDynamicSharedMemorySize, GEMM_SMEM);
        cudaFuncSetAttribute(mma_gemm<1>, cudaFuncAttributeMaxDynamicSharedMemorySize, GEMM_SMEM);
        cudaFuncSetAttribute(mma_gemm<2>, cudaFuncAttributeMaxDynamicSharedMemorySize, GEMM_SMEM);
        cudaFuncSetAttribute(mma_gemm<3>, cudaFuncAttributeMaxDynamicSharedMemorySize, GEMM_SMEM);
        attr_set = true;
    }

    // 1. qkv = x @ in_proj_w^T + b
    mma_gemm<0><<<dim3(6, 64), 256, GEMM_SMEM>>>(x_in, 256, in_proj_w, in_proj_b,
                                                 nullptr, 0, qkv, 768, 256);
    // 2. causal attention (tf32 mma)
    attn_mma_kernel<<<dim3(8, 32), 256>>>(qkv, attn);
    // 3. out_proj + residual
    mma_gemm<1><<<dim3(2, 64), 256, GEMM_SMEM>>>(attn, 256, out_proj_w, out_proj_b,
                                                 x_in, 256, tmp, 256, 256);
    // 4. x = LN1(tmp)
    ln_warp_kernel<<<1024, 256>>>(tmp, 256, ln1s, ln1b, xb, 256, 8192);
    // 5. conv -> combined[:,256:512]
    conv_kernel<<<8192, 256>>>(xb, conv_w, conv_b, comb);
    // 6. EMA -> combined[:,512:768]  (chunk-parallel)
    ema_kernel<<<dim3(8, 8), 256>>>(xb, comb);
    // 7. combined[:,0:256] = x + 0.3*(x @ p2s^T + b)
    mma_gemm<3><<<dim3(2, 64), 256, GEMM_SMEM>>>(xb, 256, p2s_w, p2s_b,
                                                 xb, 256, comb, 768, 256);
    // 8. h = gelu(comb @ tw1^T + b1)
    mma_gemm<2><<<dim3(4, 64), 256, GEMM_SMEM>>>(comb, 768, tw1, tb1,
                                                 nullptr, 0, hb, 512, 768);
    // 9. deltas = h @ tw2^T + b2
    mma_gemm<0><<<dim3(2, 64), 256, GEMM_SMEM>>>(hb, 512, tw2, tb2,
                                                 nullptr, 0, deltas, 256, 512);
    // 10. states = seq + 0.5*cumsum(deltas)
    cumsum_kernel<<<8, 256>>>(deltas, seq_state, states);
    // 11. states = LN3(states)
    ln_warp_kernel<<<1024, 256>>>(states, 256, ln3s, ln3b, states, 256, 8192);
    // 12. ffn_in = x + 0.3*(states @ s2p^T + b)
    mma_gemm<3><<<dim3(2, 64), 256, GEMM_SMEM>>>(states, 256, s2p_w, s2p_b,
                                                 xb, 256, ffnin, 256, 256);
    // 13. f = gelu(ffn_in @ fw1^T + b1)
    mma_gemm<2><<<dim3(8, 64), 256, GEMM_SMEM>>>(ffnin, 256, fw1, fb1,
                                                 nullptr, 0, fbuf, 1024, 256);
    // 14. tmp = x + f @ fw2^T + b2
    mma_gemm<1><<<dim3(2, 64), 256, GEMM_SMEM>>>(fbuf, 1024, fw2, fb2,
                                                 xb, 256, tmp, 256, 1024);
    // 15. LN2 -> out
    ln_warp_kernel<<<1024, 256>>>(tmp, 256, ln2s, ln2b, out, 256, 8192);
    // 16. LN4(states[:, -1, :])
    ln_warp_kernel<<<1, 256>>>(states + (size_t)1023 * 256, (long)1024 * 256,
                               ln4s, ln4b, out + (size_t)M_ROWS * 256, 256, 8);
    // 17. trajectory summary
    traj_kernel<<<8, 256>>>(comb, out + (size_t)M_ROWS * 256 + 2048);
}

// round 7
// speedup vs baseline: 1.1806x; 1.0885x over previous
#include <cuda_runtime.h>
#include <math.h>
#include <stdint.h>

#define B_SZ   8
#define T_SEQ  1024
#define D_MOD  256
#define M_ROWS (B_SZ * T_SEQ)   // 8192

// ---------------------------------------------------------------------------
// Scratch
// ---------------------------------------------------------------------------
#define OFF_QKV    0ul
#define OFF_ATTN   6291456ul
#define OFF_TMP    8388608ul
#define OFF_X      10485760ul
#define OFF_COMB   12582912ul
#define OFF_H      18874368ul
#define OFF_DELTAS 23068672ul
#define OFF_STATES 25165824ul
#define OFF_FFNIN  27262976ul
#define OFF_F      29360128ul
#define OFF_CSUM   37748736ul                 // [8*8, 256] chunk sums
#define SCRATCH_TOTAL 37765120ul

__device__ float d_scratch[SCRATCH_TOTAL];

__device__ __forceinline__ float gelu_f(float x) {
    return 0.5f * x * (1.0f + erff(x * 0.70710678118654752f));
}

__device__ __forceinline__ uint32_t f2tf32(float x) {
    uint32_t r;
    asm("cvt.rna.tf32.f32 %0, %1;" : "=r"(r) : "f"(x));
    return r;
}

#define MMA_TF32(d, a, b) \
    asm volatile("mma.sync.aligned.m16n8k8.row.col.f32.tf32.tf32.f32 " \
                 "{%0,%1,%2,%3}, {%4,%5,%6,%7}, {%8,%9}, {%0,%1,%2,%3};" \
                 : "+f"(d[0]), "+f"(d[1]), "+f"(d[2]), "+f"(d[3]) \
                 : "r"(a[0]), "r"(a[1]), "r"(a[2]), "r"(a[3]), \
                   "r"(b[0]), "r"(b[1]))

// Fast exp(s/8): FMA-pipe only, no MUFU.
__device__ __forceinline__ float fexp_s8(float s) {
    const float y = s * 0.1803368801111244f;
    const float rnd = y + 12582912.0f;
    const int   i   = __float_as_int(rnd);
    const float nf  = rnd - 12582912.0f;
    const float f   = y - nf;
    float p = 1.3333558146e-3f;
    p = fmaf(p, f, 9.6181291076e-3f);
    p = fmaf(p, f, 5.5504108665e-2f);
    p = fmaf(p, f, 2.4022650696e-1f);
    p = fmaf(p, f, 6.9314718056e-1f);
    p = fmaf(p, f, 1.0f);
    const float scale = __int_as_float((i << 23) + 0x3f800000);
    return p * scale;
}

// ---------------------------------------------------------------------------
// TF32 GEMM v4: 3-stage cp.async, ONE syncthreads per k-tile, BN=128,
// warp tile 64x32, __launch_bounds__(256,2) -> 2 CTAs/SM (3*36864B*2 < 228KB).
// C[M,N] = epi( A[M,K] @ W[N,K]^T + bias[N] )
// ---------------------------------------------------------------------------
#define GEMM_TS (128 * 36)              // u32 per A (or B) tile
#define GEMM_STAGE (2 * GEMM_TS)        // u32 per stage (A + B)
#define GEMM_SMEM (3 * GEMM_STAGE * 4)  // 110592 bytes

#define ISSUE_TILE(k0, sidx)                                                   \
    {                                                                          \
        _Pragma("unroll")                                                      \
        for (int i = 0; i < 4; i++) {                                          \
            uint32_t da = smem_base + (uint32_t)(((sidx) * GEMM_STAGE + (mrow0 + 32 * i) * 36 + kq) * 4); \
            const float* ga = A + (size_t)(bm + mrow0 + 32 * i) * lda + (k0) + kq; \
            asm volatile("cp.async.cg.shared.global [%0], [%1], 16;" :: "r"(da), "l"(ga)); \
            uint32_t db = smem_base + (uint32_t)(((sidx) * GEMM_STAGE + GEMM_TS + (mrow0 + 32 * i) * 36 + kq) * 4); \
            const float* gw = W + (size_t)(bn + mrow0 + 32 * i) * (size_t)K + (k0) + kq; \
            asm volatile("cp.async.cg.shared.global [%0], [%1], 16;" :: "r"(db), "l"(gw)); \
        }                                                                      \
        asm volatile("cp.async.commit_group;");                                \
    }

template<int EPI>
__global__ void __launch_bounds__(256, 2) mma_gemm(
    const float* __restrict__ A, int lda,
    const float* __restrict__ W,
    const float* __restrict__ bias,
    const float* __restrict__ addend, int ld_add,
    float* __restrict__ C, int ldc,
    int K)
{
    extern __shared__ uint32_t sm[];
    const uint32_t smem_base = (uint32_t)__cvta_generic_to_shared(sm);

    const int tid  = threadIdx.x;
    const int bm   = blockIdx.y * 128;
    const int bn   = blockIdx.x * 128;
    const int wid  = tid >> 5;
    const int lane = tid & 31;
    const int wm64 = (wid & 1) * 64;
    const int wn32 = (wid >> 1) * 32;
    const int r    = lane >> 2;
    const int t    = lane & 3;

    const int kq    = (tid & 7) * 4;
    const int mrow0 = tid >> 3;

    float acc[4][4][4];
    #pragma unroll
    for (int mi = 0; mi < 4; mi++)
        #pragma unroll
        for (int ni = 0; ni < 4; ni++)
            #pragma unroll
            for (int c = 0; c < 4; c++) acc[mi][ni][c] = 0.0f;

    const int ntiles = K >> 5;   // >= 8 for all layers here

    ISSUE_TILE(0, 0);
    ISSUE_TILE(32, 1);

    int sidx = 0;
    for (int kt = 0; kt < ntiles; kt++) {
        if (kt == ntiles - 1) {
            asm volatile("cp.async.wait_group 0;");
        } else {
            asm volatile("cp.async.wait_group 1;");
        }
        __syncthreads();

        if (kt + 2 < ntiles) {
            int ws = sidx + 2; if (ws >= 3) ws -= 3;
            ISSUE_TILE((kt + 2) * 32, ws);
        }

        const uint32_t* Ab = sm + sidx * GEMM_STAGE;
        const uint32_t* Bb = Ab + GEMM_TS;

        #pragma unroll
        for (int ks = 0; ks < 4; ks++) {
            const int kb = ks * 8;
            uint32_t a[4][4], b[4][2];
            #pragma unroll
            for (int mi = 0; mi < 4; mi++) {
                int idx = (wm64 + mi * 16 + r) * 36 + kb + t;
                a[mi][0] = Ab[idx];
                a[mi][1] = Ab[idx + 8 * 36];
                a[mi][2] = Ab[idx + 4];
                a[mi][3] = Ab[idx + 8 * 36 + 4];
            }
            #pragma unroll
            for (int ni = 0; ni < 4; ni++) {
                int idx = (wn32 + ni * 8 + r) * 36 + kb + t;
                b[ni][0] = Bb[idx];
                b[ni][1] = Bb[idx + 4];
            }
            #pragma unroll
            for (int mi = 0; mi < 4; mi++)
                #pragma unroll
                for (int ni = 0; ni < 4; ni++)
                    MMA_TF32(acc[mi][ni], a[mi], b[ni]);
        }
        sidx++; if (sidx == 3) sidx = 0;
    }

    #pragma unroll
    for (int mi = 0; mi < 4; mi++) {
        const int row0 = bm + wm64 + mi * 16 + r;
        const int row1 = row0 + 8;
        #pragma unroll
        for (int ni = 0; ni < 4; ni++) {
            const int col = bn + wn32 + ni * 8 + 2 * t;
            const float2 bb = *(const float2*)(bias + col);
            float v00 = acc[mi][ni][0] + bb.x;
            float v01 = acc[mi][ni][1] + bb.y;
            float v10 = acc[mi][ni][2] + bb.x;
            float v11 = acc[mi][ni][3] + bb.y;
            if (EPI == 1) {
                const float2 r0 = *(const float2*)(addend + (size_t)row0 * ld_add + col);
                const float2 r1 = *(const float2*)(addend + (size_t)row1 * ld_add + col);
                v00 += r0.x; v01 += r0.y; v10 += r1.x; v11 += r1.y;
            }
            if (EPI == 2) {
                v00 = gelu_f(v00); v01 = gelu_f(v01);
                v10 = gelu_f(v10); v11 = gelu_f(v11);
            }
            if (EPI == 3) {
                const float2 r0 = *(const float2*)(addend + (size_t)row0 * ld_add + col);
                const float2 r1 = *(const float2*)(addend + (size_t)row1 * ld_add + col);
                v00 = r0.x + 0.3f * v00; v01 = r0.y + 0.3f * v01;
                v10 = r1.x + 0.3f * v10; v11 = r1.y + 0.3f * v11;
            }
            *(float2*)(C + (size_t)row0 * ldc + col) = make_float2(v00, v01);
            *(float2*)(C + (size_t)row1 * ldc + col) = make_float2(v10, v11);
        }
    }
}

// ---------------------------------------------------------------------------
// TF32 mma causal flash-attention (unchanged).
// ---------------------------------------------------------------------------
__global__ void __launch_bounds__(256) attn_mma_kernel(
    const float* __restrict__ qkv, float* __restrict__ attn_out)
{
    __shared__ uint32_t Ks[64 * 68];
    __shared__ uint32_t Vs[64 * 72];

    const int bh = blockIdx.y;
    const int b  = bh >> 2;
    const int h  = bh & 3;
    const int qbase = blockIdx.x * 128;
    const int tid  = threadIdx.x;
    const int wid  = tid >> 5;
    const int lane = tid & 31;
    const int r    = lane >> 2;
    const int t    = lane & 3;
    const float* base = qkv + (size_t)b * T_SEQ * 768;

    const int qrow0 = qbase + wid * 16 + r;
    const int qrow1 = qrow0 + 8;

    uint32_t aq[8][4];
    {
        const float* q0 = base + (size_t)qrow0 * 768 + h * 64;
        const float* q1 = base + (size_t)qrow1 * 768 + h * 64;
        #pragma unroll
        for (int ks = 0; ks < 8; ks++) {
            aq[ks][0] = f2tf32(q0[ks * 8 + t]);
            aq[ks][1] = f2tf32(q1[ks * 8 + t]);
            aq[ks][2] = f2tf32(q0[ks * 8 + t + 4]);
            aq[ks][3] = f2tf32(q1[ks * 8 + t + 4]);
        }
    }

    float oacc[8][4];
    #pragma unroll
    for (int ni = 0; ni < 8; ni++)
        #pragma unroll
        for (int c = 0; c < 4; c++) oacc[ni][c] = 0.0f;
    float lsum0 = 0.0f, lsum1 = 0.0f;

    const int ntiles   = 2 * blockIdx.x + 2;
    const int wrow_max = qbase + wid * 16 + 15;
    const unsigned FULL = 0xffffffffu;
    const int s0 = (lane & ~3) | (t >> 1);
    const int s1 = s0 + 2;

    for (int jt = 0; jt < ntiles; jt++) {
        const int j0 = jt * 64;
        __syncthreads();
        #pragma unroll
        for (int i = 0; i < 4; i++) {
            int idx = tid + i * 256;
            int row = idx >> 4;
            int c4  = (idx & 15) * 4;
            const float* kp = base + (size_t)(j0 + row) * 768 + 256 + h * 64 + c4;
            float4 kv = *(const float4*)kp;
            uint4 kt4 = make_uint4(f2tf32(kv.x), f2tf32(kv.y), f2tf32(kv.z), f2tf32(kv.w));
            *(uint4*)&Ks[row * 68 + c4] = kt4;
            float4 vv = *(const float4*)(kp + 256);
            uint4 vt4 = make_uint4(f2tf32(vv.x), f2tf32(vv.y), f2tf32(vv.z), f2tf32(vv.w));
            *(uint4*)&Vs[row * 72 + c4] = vt4;
        }
        __syncthreads();

        if (j0 > wrow_max) continue;

        float sc[8][4];
        #pragma unroll
        for (int ni = 0; ni < 8; ni++)
            #pragma unroll
            for (int c = 0; c < 4; c++) sc[ni][c] = 0.0f;
        #pragma unroll
        for (int ks = 0; ks < 8; ks++) {
            #pragma unroll
            for (int ni = 0; ni < 8; ni++) {
                uint32_t bfr[2];
                const int key = ni * 8 + r;
                bfr[0] = Ks[key * 68 + ks * 8 + t];
                bfr[1] = Ks[key * 68 + ks * 8 + t + 4];
                MMA_TF32(sc[ni], aq[ks], bfr);
            }
        }

        #pragma unroll
        for (int ni = 0; ni < 8; ni++) {
            const int col0 = j0 + ni * 8 + 2 * t;
            float p0 = (col0     <= qrow0) ? fexp_s8(sc[ni][0]) : 0.0f;
            float p1 = (col0 + 1 <= qrow0) ? fexp_s8(sc[ni][1]) : 0.0f;
            float p2 = (col0     <= qrow1) ? fexp_s8(sc[ni][2]) : 0.0f;
            float p3 = (col0 + 1 <= qrow1) ? fexp_s8(sc[ni][3]) : 0.0f;
            lsum0 += p0 + p1;
            lsum1 += p2 + p3;
            sc[ni][0] = p0; sc[ni][1] = p1; sc[ni][2] = p2; sc[ni][3] = p3;
        }

        #pragma unroll
        for (int ks = 0; ks < 8; ks++) {
            uint32_t ap[4];
            float e, o;
            e = __shfl_sync(FULL, sc[ks][0], s0);
            o = __shfl_sync(FULL, sc[ks][1], s0);
            ap[0] = f2tf32((t & 1) ? o : e);
            e = __shfl_sync(FULL, sc[ks][2], s0);
            o = __shfl_sync(FULL, sc[ks][3], s0);
            ap[1] = f2tf32((t & 1) ? o : e);
            e = __shfl_sync(FULL, sc[ks][0], s1);
            o = __shfl_sync(FULL, sc[ks][1], s1);
            ap[2] = f2tf32((t & 1) ? o : e);
            e = __shfl_sync(FULL, sc[ks][2], s1);
            o = __shfl_sync(FULL, sc[ks][3], s1);
            ap[3] = f2tf32((t & 1) ? o : e);
            #pragma unroll
            for (int ni = 0; ni < 8; ni++) {
                uint32_t bfr[2];
                bfr[0] = Vs[(ks * 8 + t)     * 72 + ni * 8 + r];
                bfr[1] = Vs[(ks * 8 + t + 4) * 72 + ni * 8 + r];
                MMA_TF32(oacc[ni], ap, bfr);
            }
        }
    }

    lsum0 += __shfl_xor_sync(FULL, lsum0, 1);
    lsum0 += __shfl_xor_sync(FULL, lsum0, 2);
    lsum1 += __shfl_xor_sync(FULL, lsum1, 1);
    lsum1 += __shfl_xor_sync(FULL, lsum1, 2);
    const float inv0 = 1.0f / lsum0;
    const float inv1 = 1.0f / lsum1;

    float* op0 = attn_out + ((size_t)b * T_SEQ + qrow0) * 256 + h * 64;
    float* op1 = attn_out + ((size_t)b * T_SEQ + qrow1) * 256 + h * 64;
    #pragma unroll
    for (int ni = 0; ni < 8; ni++) {
        *(float2*)(op0 + ni * 8 + 2 * t) = make_float2(oacc[ni][0] * inv0, oacc[ni][1] * inv0);
        *(float2*)(op1 + ni * 8 + 2 * t) = make_float2(oacc[ni][2] * inv1, oacc[ni][3] * inv1);
    }
}

// ---------------------------------------------------------------------------
// LayerNorm, warp-per-row (unchanged).
// ---------------------------------------------------------------------------
__global__ void __launch_bounds__(256) ln_warp_kernel(
    const float* __restrict__ in, long ld_in,
    const float* __restrict__ gamma, const float* __restrict__ beta,
    float* __restrict__ out, long ld_out, int nrows)
{
    const int wid = threadIdx.x >> 5, lane = threadIdx.x & 31;
    const int row = blockIdx.x * 8 + wid;
    if (row >= nrows) return;
    const float* ip = in + (size_t)row * ld_in + lane * 8;
    float4 v0 = ((const float4*)ip)[0];
    float4 v1 = ((const float4*)ip)[1];

    float s  = v0.x + v0.y + v0.z + v0.w + v1.x + v1.y + v1.z + v1.w;
    float sq = v0.x*v0.x + v0.y*v0.y + v0.z*v0.z + v0.w*v0.w
             + v1.x*v1.x + v1.y*v1.y + v1.z*v1.z + v1.w*v1.w;
    #pragma unroll
    for (int o = 16; o > 0; o >>= 1) {
        s  += __shfl_xor_sync(0xffffffffu, s,  o);
        sq += __shfl_xor_sync(0xffffffffu, sq, o);
    }
    const float mean = s * (1.0f / 256.0f);
    const float var  = sq * (1.0f / 256.0f) - mean * mean;
    const float rstd = rsqrtf(var + 1e-5f);

    const float4 g0 = ((const float4*)(gamma + lane * 8))[0];
    const float4 g1 = ((const float4*)(gamma + lane * 8))[1];
    const float4 b0 = ((const float4*)(beta  + lane * 8))[0];
    const float4 b1 = ((const float4*)(beta  + lane * 8))[1];
    float4 r0, r1;
    r0.x = (v0.x - mean) * rstd * g0.x + b0.x;
    r0.y = (v0.y - mean) * rstd * g0.y + b0.y;
    r0.z = (v0.z - mean) * rstd * g0.z + b0.z;
    r0.w = (v0.w - mean) * rstd * g0.w + b0.w;
    r1.x = (v1.x - mean) * rstd * g1.x + b1.x;
    r1.y = (v1.y - mean) * rstd * g1.y + b1.y;
    r1.z = (v1.z - mean) * rstd * g1.z + b1.z;
    r1.w = (v1.w - mean) * rstd * g1.w + b1.w;
    float* op = out + (size_t)row * ld_out + lane * 8;
    ((float4*)op)[0] = r0;
    ((float4*)op)[1] = r1;
}

__global__ void __launch_bounds__(256) conv_kernel(
    const float* __restrict__ x, const float* __restrict__ cw,
    const float* __restrict__ cb, float* __restrict__ comb)
{
    const int idx = blockIdx.x * 256 + threadIdx.x;
    const int d = idx & 255;
    const int t = (idx >> 8) & 1023;
    const int b = idx >> 18;
    float r = cb[d];
    #pragma unroll
    for (int w = 0; w < 8; w++) {
        int tt = t - 7 + w;
        if (tt >= 0) r = fmaf(cw[d * 8 + w], x[((size_t)b * 1024 + tt) * 256 + d], r);
    }
    comb[((size_t)b * 1024 + t) * 768 + 256 + d] = r;
}

// ---------------------------------------------------------------------------
// EMA, chunk-parallel (0.9^256 ~ 2e-12 lookback truncation).
// ---------------------------------------------------------------------------
__global__ void __launch_bounds__(256) ema_kernel(
    const float* __restrict__ x, float* __restrict__ comb)
{
    const int b = blockIdx.x, chunk = blockIdx.y, d = threadIdx.x;
    const int t0 = chunk * 128;
    int start = t0 - 256; if (start < 0) start = 0;
    const float* xp = x + (size_t)b * 1024 * 256 + d;
    float c = 0.0f;
    #pragma unroll 8
    for (int t = start; t < t0; t++)
        c = fmaf(0.9f, c, 0.1f * xp[(size_t)t * 256]);
    float* op = comb + (size_t)b * 1024 * 768 + 512 + d;
    #pragma unroll 8
    for (int t = t0; t < t0 + 128; t++) {
        c = fmaf(0.9f, c, 0.1f * xp[(size_t)t * 256]);
        op[(size_t)t * 768] = c;
    }
}

// ---------------------------------------------------------------------------
// Parallel cumsum: phase 1 per-chunk (128 steps) sums; phase 2 offset + scan.
// states = seq + 0.5 * cumsum(deltas)
// ---------------------------------------------------------------------------
__global__ void __launch_bounds__(256) chunksum_kernel(
    const float* __restrict__ deltas, float* __restrict__ csum)
{
    const int b = blockIdx.x, chunk = blockIdx.y, d = threadIdx.x;
    const float* dp = deltas + ((size_t)b * 1024 + chunk * 128) * 256 + d;
    float s = 0.0f;
    #pragma unroll 8
    for (int t = 0; t < 128; t++) s += dp[(size_t)t * 256];
    csum[(b * 8 + chunk) * 256 + d] = s;
}

__global__ void __launch_bounds__(256) cumsum_kernel(
    const float* __restrict__ deltas, const float* __restrict__ seq,
    const float* __restrict__ csum, float* __restrict__ states)
{
    const int b = blockIdx.x, chunk = blockIdx.y, d = threadIdx.x;
    float c = seq[b * 256 + d];
    for (int cc = 0; cc < 8; cc++)
        if (cc < chunk) c = fmaf(0.5f, csum[(b * 8 + cc) * 256 + d], c);
    const float* dp = deltas + ((size_t)b * 1024 + chunk * 128) * 256 + d;
    float* sp = states + ((size_t)b * 1024 + chunk * 128) * 256 + d;
    #pragma unroll 8
    for (int t = 0; t < 128; t++) {
        c = fmaf(0.5f, dp[(size_t)t * 256], c);
        sp[(size_t)t * 256] = c;
    }
}

__global__ void traj_kernel(const float* __restrict__ comb, float* __restrict__ out)
{
    const int b = blockIdx.x, d = threadIdx.x;
    out[b * 256 + d] = comb[((size_t)b * 1024 + 1023) * 768 + 512 + d];
}

// ---------------------------------------------------------------------------
// Launch
// ---------------------------------------------------------------------------
extern "C" void kernel_launch(void* const* d_in, const int* in_sizes, int n_in,
                              void* d_out, int out_size)
{
    const float* x_in       = (const float*)d_in[0];
    const float* seq_state  = (const float*)d_in[1];
    const float* in_proj_w  = (const float*)d_in[3];
    const float* in_proj_b  = (const float*)d_in[4];
    const float* out_proj_w = (const float*)d_in[5];
    const float* out_proj_b = (const float*)d_in[6];
    const float* conv_w     = (const float*)d_in[7];
    const float* conv_b     = (const float*)d_in[8];
    const float* p2s_w      = (const float*)d_in[9];
    const float* p2s_b      = (const float*)d_in[10];
    const float* s2p_w      = (const float*)d_in[11];
    const float* s2p_b      = (const float*)d_in[12];
    const float* tw1        = (const float*)d_in[13];
    const float* tb1        = (const float*)d_in[14];
    const float* tw2        = (const float*)d_in[15];
    const float* tb2        = (const float*)d_in[16];
    const float* fw1        = (const float*)d_in[17];
    const float* fb1        = (const float*)d_in[18];
    const float* fw2        = (const float*)d_in[19];
    const float* fb2        = (const float*)d_in[20];
    const float* ln1s = (const float*)d_in[21];
    const float* ln1b = (const float*)d_in[22];
    const float* ln2s = (const float*)d_in[23];
    const float* ln2b = (const float*)d_in[24];
    const float* ln3s = (const float*)d_in[25];
    const float* ln3b = (const float*)d_in[26];
    const float* ln4s = (const float*)d_in[27];
    const float* ln4b = (const float*)d_in[28];
    float* out = (float*)d_out;

    float* scr = nullptr;
    cudaGetSymbolAddress((void**)&scr, d_scratch);
    float* qkv    = scr + OFF_QKV;
    float* attn   = scr + OFF_ATTN;
    float* tmp    = scr + OFF_TMP;
    float* xb     = scr + OFF_X;
    float* comb   = scr + OFF_COMB;
    float* hb     = scr + OFF_H;
    float* deltas = scr + OFF_DELTAS;
    float* states = scr + OFF_STATES;
    float* ffnin  = scr + OFF_FFNIN;
    float* fbuf   = scr + OFF_F;
    float* csum   = scr + OFF_CSUM;

    static bool attr_set = false;
    if (!attr_set) {
        cudaFuncSetAttribute(mma_gemm<0>, cudaFuncAttributeMaxDynamicSharedMemorySize, GEMM_SMEM);
        cudaFuncSetAttribute(mma_gemm<1>, cudaFuncAttributeMaxDynamicSharedMemorySize, GEMM_SMEM);
        cudaFuncSetAttribute(mma_gemm<2>, cudaFuncAttributeMaxDynamicSharedMemorySize, GEMM_SMEM);
        cudaFuncSetAttribute(mma_gemm<3>, cudaFuncAttributeMaxDynamicSharedMemorySize, GEMM_SMEM);
        attr_set = true;
    }

    // 1. qkv = x @ in_proj_w^T + b
    mma_gemm<0><<<dim3(6, 64), 256, GEMM_SMEM>>>(x_in, 256, in_proj_w, in_proj_b,
                                                 nullptr, 0, qkv, 768, 256);
    // 2. causal attention (tf32 mma)
    attn_mma_kernel<<<dim3(8, 32), 256>>>(qkv, attn);
    // 3. out_proj + residual
    mma_gemm<1><<<dim3(2, 64), 256, GEMM_SMEM>>>(attn, 256, out_proj_w, out_proj_b,
                                                 x_in, 256, tmp, 256, 256);
    // 4. x = LN1(tmp)
    ln_warp_kernel<<<1024, 256>>>(tmp, 256, ln1s, ln1b, xb, 256, 8192);
    // 5. conv -> combined[:,256:512]
    conv_kernel<<<8192, 256>>>(xb, conv_w, conv_b, comb);
    // 6. EMA -> combined[:,512:768]  (chunk-parallel)
    ema_kernel<<<dim3(8, 8), 256>>>(xb, comb);
    // 7. combined[:,0:256] = x + 0.3*(x @ p2s^T + b)
    mma_gemm<3><<<dim3(2, 64), 256, GEMM_SMEM>>>(xb, 256, p2s_w, p2s_b,
                                                 xb, 256, comb, 768, 256);
    // 8. h = gelu(comb @ tw1^T + b1)
    mma_gemm<2><<<dim3(4, 64), 256, GEMM_SMEM>>>(comb, 768, tw1, tb1,
                                                 nullptr, 0, hb, 512, 768);
    // 9. deltas = h @ tw2^T + b2
    mma_gemm<0><<<dim3(2, 64), 256, GEMM_SMEM>>>(hb, 512, tw2, tb2,
                                                 nullptr, 0, deltas, 256, 512);
    // 10. states = seq + 0.5*cumsum(deltas)  (two-phase parallel)
    chunksum_kernel<<<dim3(8, 8), 256>>>(deltas, csum);
    cumsum_kernel<<<dim3(8, 8), 256>>>(deltas, seq_state, csum, states);
    // 11. states = LN3(states)
    ln_warp_kernel<<<1024, 256>>>(states, 256, ln3s, ln3b, states, 256, 8192);
    // 12. ffn_in = x + 0.3*(states @ s2p^T + b)
    mma_gemm<3><<<dim3(2, 64), 256, GEMM_SMEM>>>(states, 256, s2p_w, s2p_b,
                                                 xb, 256, ffnin, 256, 256);
    // 13. f = gelu(ffn_in @ fw1^T + b1)
    mma_gemm<2><<<dim3(8, 64), 256, GEMM_SMEM>>>(ffnin, 256, fw1, fb1,
                                                 nullptr, 0, fbuf, 1024, 256);
    // 14. tmp = x + f @ fw2^T + b2
    mma_gemm<1><<<dim3(2, 64), 256, GEMM_SMEM>>>(fbuf, 1024, fw2, fb2,
                                                 xb, 256, tmp, 256, 1024);
    // 15. LN2 -> out
    ln_warp_kernel<<<1024, 256>>>(tmp, 256, ln2s, ln2b, out, 256, 8192);
    // 16. LN4(states[:, -1, :])
    ln_warp_kernel<<<1, 256>>>(states + (size_t)1023 * 256, (long)1024 * 256,
                               ln4s, ln4b, out + (size_t)M_ROWS * 256, 256, 8);
    // 17. trajectory summary
    traj_kernel<<<8, 256>>>(comb, out + (size_t)M_ROWS * 256 + 2048);
}

// round 9
// speedup vs baseline: 1.2054x; 1.0210x over previous
#include <cuda_runtime.h>
#include <math.h>
#include <stdint.h>

#define B_SZ   8
#define T_SEQ  1024
#define D_MOD  256
#define M_ROWS (B_SZ * T_SEQ)   // 8192

// ---------------------------------------------------------------------------
// Scratch
// ---------------------------------------------------------------------------
#define OFF_QKV    0ul
#define OFF_ATTN   6291456ul
#define OFF_TMP    8388608ul
#define OFF_X      10485760ul
#define OFF_COMB   12582912ul
#define OFF_H      18874368ul
#define OFF_DELTAS 23068672ul
#define OFF_STATES 25165824ul
#define OFF_FFNIN  27262976ul
#define OFF_F      29360128ul
#define OFF_CSUM   37748736ul
#define SCRATCH_TOTAL 37765120ul

__device__ float d_scratch[SCRATCH_TOTAL];

__device__ __forceinline__ float gelu_f(float x) {
    return 0.5f * x * (1.0f + erff(x * 0.70710678118654752f));
}

__device__ __forceinline__ uint32_t f2tf32(float x) {
    uint32_t r;
    asm("cvt.rna.tf32.f32 %0, %1;" : "=r"(r) : "f"(x));
    return r;
}

#define MMA_TF32(d, a, b) \
    asm volatile("mma.sync.aligned.m16n8k8.row.col.f32.tf32.tf32.f32 " \
                 "{%0,%1,%2,%3}, {%4,%5,%6,%7}, {%8,%9}, {%0,%1,%2,%3};" \
                 : "+f"(d[0]), "+f"(d[1]), "+f"(d[2]), "+f"(d[3]) \
                 : "r"(a[0]), "r"(a[1]), "r"(a[2]), "r"(a[3]), \
                   "r"(b[0]), "r"(b[1]))

// Fast exp(s/8): FMA-pipe only, no MUFU.
__device__ __forceinline__ float fexp_s8(float s) {
    const float y = s * 0.1803368801111244f;
    const float rnd = y + 12582912.0f;
    const int   i   = __float_as_int(rnd);
    const float nf  = rnd - 12582912.0f;
    const float f   = y - nf;
    float p = 1.3333558146e-3f;
    p = fmaf(p, f, 9.6181291076e-3f);
    p = fmaf(p, f, 5.5504108665e-2f);
    p = fmaf(p, f, 2.4022650696e-1f);
    p = fmaf(p, f, 6.9314718056e-1f);
    p = fmaf(p, f, 1.0f);
    const float scale = __int_as_float((i << 23) + 0x3f800000);
    return p * scale;
}

// ---------------------------------------------------------------------------
// TF32 GEMM v4 (R7, best): 3-stage cp.async, one syncthreads per k-tile,
// BM=BN=128, warp tile 64x32, __launch_bounds__(256,2).
// C[M,N] = epi( A[M,K] @ W[N,K]^T + bias[N] )
// ---------------------------------------------------------------------------
#define GEMM_TS (128 * 36)
#define GEMM_STAGE (2 * GEMM_TS)
#define GEMM_SMEM (3 * GEMM_STAGE * 4)  // 110592 bytes

#define ISSUE_TILE(k0, sidx)                                                   \
    {                                                                          \
        _Pragma("unroll")                                                      \
        for (int i = 0; i < 4; i++) {                                          \
            uint32_t da = smem_base + (uint32_t)(((sidx) * GEMM_STAGE + (mrow0 + 32 * i) * 36 + kq) * 4); \
            const float* ga = A + (size_t)(bm + mrow0 + 32 * i) * lda + (k0) + kq; \
            asm volatile("cp.async.cg.shared.global [%0], [%1], 16;" :: "r"(da), "l"(ga)); \
            uint32_t db = smem_base + (uint32_t)(((sidx) * GEMM_STAGE + GEMM_TS + (mrow0 + 32 * i) * 36 + kq) * 4); \
            const float* gw = W + (size_t)(bn + mrow0 + 32 * i) * (size_t)K + (k0) + kq; \
            asm volatile("cp.async.cg.shared.global [%0], [%1], 16;" :: "r"(db), "l"(gw)); \
        }                                                                      \
        asm volatile("cp.async.commit_group;");                                \
    }

template<int EPI>
__global__ void __launch_bounds__(256, 2) mma_gemm(
    const float* __restrict__ A, int lda,
    const float* __restrict__ W,
    const float* __restrict__ bias,
    const float* __restrict__ addend, int ld_add,
    float* __restrict__ C, int ldc,
    int K)
{
    extern __shared__ uint32_t sm[];
    const uint32_t smem_base = (uint32_t)__cvta_generic_to_shared(sm);

    const int tid  = threadIdx.x;
    const int bm   = blockIdx.y * 128;
    const int bn   = blockIdx.x * 128;
    const int wid  = tid >> 5;
    const int lane = tid & 31;
    const int wm64 = (wid & 1) * 64;
    const int wn32 = (wid >> 1) * 32;
    const int r    = lane >> 2;
    const int t    = lane & 3;

    const int kq    = (tid & 7) * 4;
    const int mrow0 = tid >> 3;

    float acc[4][4][4];
    #pragma unroll
    for (int mi = 0; mi < 4; mi++)
        #pragma unroll
        for (int ni = 0; ni < 4; ni++)
            #pragma unroll
            for (int c = 0; c < 4; c++) acc[mi][ni][c] = 0.0f;

    const int ntiles = K >> 5;

    ISSUE_TILE(0, 0);
    ISSUE_TILE(32, 1);

    int sidx = 0;
    for (int kt = 0; kt < ntiles; kt++) {
        if (kt == ntiles - 1) {
            asm volatile("cp.async.wait_group 0;");
        } else {
            asm volatile("cp.async.wait_group 1;");
        }
        __syncthreads();

        if (kt + 2 < ntiles) {
            int ws = sidx + 2; if (ws >= 3) ws -= 3;
            ISSUE_TILE((kt + 2) * 32, ws);
        }

        const uint32_t* Ab = sm + sidx * GEMM_STAGE;
        const uint32_t* Bb = Ab + GEMM_TS;

        #pragma unroll
        for (int ks = 0; ks < 4; ks++) {
            const int kb = ks * 8;
            uint32_t a[4][4], b[4][2];
            #pragma unroll
            for (int mi = 0; mi < 4; mi++) {
                int idx = (wm64 + mi * 16 + r) * 36 + kb + t;
                a[mi][0] = Ab[idx];
                a[mi][1] = Ab[idx + 8 * 36];
                a[mi][2] = Ab[idx + 4];
                a[mi][3] = Ab[idx + 8 * 36 + 4];
            }
            #pragma unroll
            for (int ni = 0; ni < 4; ni++) {
                int idx = (wn32 + ni * 8 + r) * 36 + kb + t;
                b[ni][0] = Bb[idx];
                b[ni][1] = Bb[idx + 4];
            }
            #pragma unroll
            for (int mi = 0; mi < 4; mi++)
                #pragma unroll
                for (int ni = 0; ni < 4; ni++)
                    MMA_TF32(acc[mi][ni], a[mi], b[ni]);
        }
        sidx++; if (sidx == 3) sidx = 0;
    }

    #pragma unroll
    for (int mi = 0; mi < 4; mi++) {
        const int row0 = bm + wm64 + mi * 16 + r;
        const int row1 = row0 + 8;
        #pragma unroll
        for (int ni = 0; ni < 4; ni++) {
            const int col = bn + wn32 + ni * 8 + 2 * t;
            const float2 bb = *(const float2*)(bias + col);
            float v00 = acc[mi][ni][0] + bb.x;
            float v01 = acc[mi][ni][1] + bb.y;
            float v10 = acc[mi][ni][2] + bb.x;
            float v11 = acc[mi][ni][3] + bb.y;
            if (EPI == 1) {
                const float2 r0 = *(const float2*)(addend + (size_t)row0 * ld_add + col);
                const float2 r1 = *(const float2*)(addend + (size_t)row1 * ld_add + col);
                v00 += r0.x; v01 += r0.y; v10 += r1.x; v11 += r1.y;
            }
            if (EPI == 2) {
                v00 = gelu_f(v00); v01 = gelu_f(v01);
                v10 = gelu_f(v10); v11 = gelu_f(v11);
            }
            if (EPI == 3) {
                const float2 r0 = *(const float2*)(addend + (size_t)row0 * ld_add + col);
                const float2 r1 = *(const float2*)(addend + (size_t)row1 * ld_add + col);
                v00 = r0.x + 0.3f * v00; v01 = r0.y + 0.3f * v01;
                v10 = r1.x + 0.3f * v10; v11 = r1.y + 0.3f * v11;
            }
            *(float2*)(C + (size_t)row0 * ldc + col) = make_float2(v00, v01);
            *(float2*)(C + (size_t)row1 * ldc + col) = make_float2(v10, v11);
        }
    }
}

// ---------------------------------------------------------------------------
// TF32 mma causal flash-attention v2: cp.async double-buffered K/V staging,
// raw fp32 in smem (truncation-tf32 fragments), one syncthreads per tile.
// Dynamic smem: 2 stages x (64x68 K + 64x72 V) u32 = 71680 B.
// ---------------------------------------------------------------------------
#define KV_K     (64 * 68)
#define KV_STAGE (64 * 68 + 64 * 72)
#define ATTN_SMEM (2 * KV_STAGE * 4)   // 71680 bytes

#define AT_ISSUE(jt, s)                                                        \
    {                                                                          \
        const int _j0 = (jt) * 64;                                             \
        _Pragma("unroll")                                                      \
        for (int _i = 0; _i < 4; _i++) {                                       \
            int _idx = tid + _i * 256;                                         \
            int _row = _idx >> 4;                                              \
            int _c4  = (_idx & 15) * 4;                                        \
            const float* _kp = base + (size_t)(_j0 + _row) * 768 + 256 + h * 64 + _c4; \
            uint32_t _dk = smem_base + (uint32_t)(((s) * KV_STAGE + _row * 68 + _c4) * 4); \
            asm volatile("cp.async.cg.shared.global [%0], [%1], 16;" :: "r"(_dk), "l"(_kp)); \
            uint32_t _dv = smem_base + (uint32_t)(((s) * KV_STAGE + KV_K + _row * 72 + _c4) * 4); \
            asm volatile("cp.async.cg.shared.global [%0], [%1], 16;" :: "r"(_dv), "l"(_kp + 256)); \
        }                                                                      \
        asm volatile("cp.async.commit_group;");                                \
    }

__global__ void __launch_bounds__(256) attn_mma_kernel(
    const float* __restrict__ qkv, float* __restrict__ attn_out)
{
    extern __shared__ uint32_t dsm[];
    const uint32_t smem_base = (uint32_t)__cvta_generic_to_shared(dsm);

    const int bh = blockIdx.y;
    const int b  = bh >> 2;
    const int h  = bh & 3;
    const int qbase = blockIdx.x * 128;
    const int tid  = threadIdx.x;
    const int wid  = tid >> 5;
    const int lane = tid & 31;
    const int r    = lane >> 2;
    const int t    = lane & 3;
    const float* base = qkv + (size_t)b * T_SEQ * 768;

    const int qrow0 = qbase + wid * 16 + r;
    const int qrow1 = qrow0 + 8;

    uint32_t aq[8][4];
    {
        const float* q0 = base + (size_t)qrow0 * 768 + h * 64;
        const float* q1 = base + (size_t)qrow1 * 768 + h * 64;
        #pragma unroll
        for (int ks = 0; ks < 8; ks++) {
            aq[ks][0] = f2tf32(q0[ks * 8 + t]);
            aq[ks][1] = f2tf32(q1[ks * 8 + t]);
            aq[ks][2] = f2tf32(q0[ks * 8 + t + 4]);
            aq[ks][3] = f2tf32(q1[ks * 8 + t + 4]);
        }
    }

    float oacc[8][4];
    #pragma unroll
    for (int ni = 0; ni < 8; ni++)
        #pragma unroll
        for (int c = 0; c < 4; c++) oacc[ni][c] = 0.0f;
    float lsum0 = 0.0f, lsum1 = 0.0f;

    const int ntiles   = 2 * blockIdx.x + 2;
    const int wrow_max = qbase + wid * 16 + 15;
    const unsigned FULL = 0xffffffffu;
    const int s0 = (lane & ~3) | (t >> 1);
    const int s1 = s0 + 2;

    AT_ISSUE(0, 0);

    for (int jt = 0; jt < ntiles; jt++) {
        const int j0 = jt * 64;
        asm volatile("cp.async.wait_group 0;");
        __syncthreads();

        if (jt + 1 < ntiles) AT_ISSUE(jt + 1, (jt + 1) & 1);

        if (j0 > wrow_max) continue;

        const uint32_t* Ks = dsm + (jt & 1) * KV_STAGE;
        const uint32_t* Vs = Ks + KV_K;

        float sc[8][4];
        #pragma unroll
        for (int ni = 0; ni < 8; ni++)
            #pragma unroll
            for (int c = 0; c < 4; c++) sc[ni][c] = 0.0f;
        #pragma unroll
        for (int ks = 0; ks < 8; ks++) {
            #pragma unroll
            for (int ni = 0; ni < 8; ni++) {
                uint32_t bfr[2];
                const int key = ni * 8 + r;
                bfr[0] = Ks[key * 68 + ks * 8 + t];
                bfr[1] = Ks[key * 68 + ks * 8 + t + 4];
                MMA_TF32(sc[ni], aq[ks], bfr);
            }
        }

        #pragma unroll
        for (int ni = 0; ni < 8; ni++) {
            const int col0 = j0 + ni * 8 + 2 * t;
            float p0 = (col0     <= qrow0) ? fexp_s8(sc[ni][0]) : 0.0f;
            float p1 = (col0 + 1 <= qrow0) ? fexp_s8(sc[ni][1]) : 0.0f;
            float p2 = (col0     <= qrow1) ? fexp_s8(sc[ni][2]) : 0.0f;
            float p3 = (col0 + 1 <= qrow1) ? fexp_s8(sc[ni][3]) : 0.0f;
            lsum0 += p0 + p1;
            lsum1 += p2 + p3;
            sc[ni][0] = p0; sc[ni][1] = p1; sc[ni][2] = p2; sc[ni][3] = p3;
        }

        #pragma unroll
        for (int ks = 0; ks < 8; ks++) {
            uint32_t ap[4];
            float e, o;
            e = __shfl_sync(FULL, sc[ks][0], s0);
            o = __shfl_sync(FULL, sc[ks][1], s0);
            ap[0] = f2tf32((t & 1) ? o : e);
            e = __shfl_sync(FULL, sc[ks][2], s0);
            o = __shfl_sync(FULL, sc[ks][3], s0);
            ap[1] = f2tf32((t & 1) ? o : e);
            e = __shfl_sync(FULL, sc[ks][0], s1);
            o = __shfl_sync(FULL, sc[ks][1], s1);
            ap[2] = f2tf32((t & 1) ? o : e);
            e = __shfl_sync(FULL, sc[ks][2], s1);
            o = __shfl_sync(FULL, sc[ks][3], s1);
            ap[3] = f2tf32((t & 1) ? o : e);
            #pragma unroll
            for (int ni = 0; ni < 8; ni++) {
                uint32_t bfr[2];
                bfr[0] = Vs[(ks * 8 + t)     * 72 + ni * 8 + r];
                bfr[1] = Vs[(ks * 8 + t + 4) * 72 + ni * 8 + r];
                MMA_TF32(oacc[ni], ap, bfr);
            }
        }
    }

    lsum0 += __shfl_xor_sync(FULL, lsum0, 1);
    lsum0 += __shfl_xor_sync(FULL, lsum0, 2);
    lsum1 += __shfl_xor_sync(FULL, lsum1, 1);
    lsum1 += __shfl_xor_sync(FULL, lsum1, 2);
    const float inv0 = 1.0f / lsum0;
    const float inv1 = 1.0f / lsum1;

    float* op0 = attn_out + ((size_t)b * T_SEQ + qrow0) * 256 + h * 64;
    float* op1 = attn_out + ((size_t)b * T_SEQ + qrow1) * 256 + h * 64;
    #pragma unroll
    for (int ni = 0; ni < 8; ni++) {
        *(float2*)(op0 + ni * 8 + 2 * t) = make_float2(oacc[ni][0] * inv0, oacc[ni][1] * inv0);
        *(float2*)(op1 + ni * 8 + 2 * t) = make_float2(oacc[ni][2] * inv1, oacc[ni][3] * inv1);
    }
}

// ---------------------------------------------------------------------------
// LayerNorm, warp-per-row (unchanged).
// ---------------------------------------------------------------------------
__global__ void __launch_bounds__(256) ln_warp_kernel(
    const float* __restrict__ in, long ld_in,
    const float* __restrict__ gamma, const float* __restrict__ beta,
    float* __restrict__ out, long ld_out, int nrows)
{
    const int wid = threadIdx.x >> 5, lane = threadIdx.x & 31;
    const int row = blockIdx.x * 8 + wid;
    if (row >= nrows) return;
    const float* ip = in + (size_t)row * ld_in + lane * 8;
    float4 v0 = ((const float4*)ip)[0];
    float4 v1 = ((const float4*)ip)[1];

    float s  = v0.x + v0.y + v0.z + v0.w + v1.x + v1.y + v1.z + v1.w;
    float sq = v0.x*v0.x + v0.y*v0.y + v0.z*v0.z + v0.w*v0.w
             + v1.x*v1.x + v1.y*v1.y + v1.z*v1.z + v1.w*v1.w;
    #pragma unroll
    for (int o = 16; o > 0; o >>= 1) {
        s  += __shfl_xor_sync(0xffffffffu, s,  o);
        sq += __shfl_xor_sync(0xffffffffu, sq, o);
    }
    const float mean = s * (1.0f / 256.0f);
    const float var  = sq * (1.0f / 256.0f) - mean * mean;
    const float rstd = rsqrtf(var + 1e-5f);

    const float4 g0 = ((const float4*)(gamma + lane * 8))[0];
    const float4 g1 = ((const float4*)(gamma + lane * 8))[1];
    const float4 b0 = ((const float4*)(beta  + lane * 8))[0];
    const float4 b1 = ((const float4*)(beta  + lane * 8))[1];
    float4 r0, r1;
    r0.x = (v0.x - mean) * rstd * g0.x + b0.x;
    r0.y = (v0.y - mean) * rstd * g0.y + b0.y;
    r0.z = (v0.z - mean) * rstd * g0.z + b0.z;
    r0.w = (v0.w - mean) * rstd * g0.w + b0.w;
    r1.x = (v1.x - mean) * rstd * g1.x + b1.x;
    r1.y = (v1.y - mean) * rstd * g1.y + b1.y;
    r1.z = (v1.z - mean) * rstd * g1.z + b1.z;
    r1.w = (v1.w - mean) * rstd * g1.w + b1.w;
    float* op = out + (size_t)row * ld_out + lane * 8;
    ((float4*)op)[0] = r0;
    ((float4*)op)[1] = r1;
}

__global__ void __launch_bounds__(256) conv_kernel(
    const float* __restrict__ x, const float* __restrict__ cw,
    const float* __restrict__ cb, float* __restrict__ comb)
{
    const int idx = blockIdx.x * 256 + threadIdx.x;
    const int d = idx & 255;
    const int t = (idx >> 8) & 1023;
    const int b = idx >> 18;
    float r = cb[d];
    #pragma unroll
    for (int w = 0; w < 8; w++) {
        int tt = t - 7 + w;
        if (tt >= 0) r = fmaf(cw[d * 8 + w], x[((size_t)b * 1024 + tt) * 256 + d], r);
    }
    comb[((size_t)b * 1024 + t) * 768 + 256 + d] = r;
}

__global__ void __launch_bounds__(256) ema_kernel(
    const float* __restrict__ x, float* __restrict__ comb)
{
    const int b = blockIdx.x, chunk = blockIdx.y, d = threadIdx.x;
    const int t0 = chunk * 128;
    int start = t0 - 256; if (start < 0) start = 0;
    const float* xp = x + (size_t)b * 1024 * 256 + d;
    float c = 0.0f;
    #pragma unroll 8
    for (int t = start; t < t0; t++)
        c = fmaf(0.9f, c, 0.1f * xp[(size_t)t * 256]);
    float* op = comb + (size_t)b * 1024 * 768 + 512 + d;
    #pragma unroll 8
    for (int t = t0; t < t0 + 128; t++) {
        c = fmaf(0.9f, c, 0.1f * xp[(size_t)t * 256]);
        op[(size_t)t * 768] = c;
    }
}

__global__ void __launch_bounds__(256) chunksum_kernel(
    const float* __restrict__ deltas, float* __restrict__ csum)
{
    const int b = blockIdx.x, chunk = blockIdx.y, d = threadIdx.x;
    const float* dp = deltas + ((size_t)b * 1024 + chunk * 128) * 256 + d;
    float s = 0.0f;
    #pragma unroll 8
    for (int t = 0; t < 128; t++) s += dp[(size_t)t * 256];
    csum[(b * 8 + chunk) * 256 + d] = s;
}

__global__ void __launch_bounds__(256) cumsum_kernel(
    const float* __restrict__ deltas, const float* __restrict__ seq,
    const float* __restrict__ csum, float* __restrict__ states)
{
    const int b = blockIdx.x, chunk = blockIdx.y, d = threadIdx.x;
    float c = seq[b * 256 + d];
    for (int cc = 0; cc < 8; cc++)
        if (cc < chunk) c = fmaf(0.5f, csum[(b * 8 + cc) * 256 + d], c);
    const float* dp = deltas + ((size_t)b * 1024 + chunk * 128) * 256 + d;
    float* sp = states + ((size_t)b * 1024 + chunk * 128) * 256 + d;
    #pragma unroll 8
    for (int t = 0; t < 128; t++) {
        c = fmaf(0.5f, dp[(size_t)t * 256], c);
        sp[(size_t)t * 256] = c;
    }
}

__global__ void traj_kernel(const float* __restrict__ comb, float* __restrict__ out)
{
    const int b = blockIdx.x, d = threadIdx.x;
    out[b * 256 + d] = comb[((size_t)b * 1024 + 1023) * 768 + 512 + d];
}

// ---------------------------------------------------------------------------
// Launch
// ---------------------------------------------------------------------------
extern "C" void kernel_launch(void* const* d_in, const int* in_sizes, int n_in,
                              void* d_out, int out_size)
{
    const float* x_in       = (const float*)d_in[0];
    const float* seq_state  = (const float*)d_in[1];
    const float* in_proj_w  = (const float*)d_in[3];
    const float* in_proj_b  = (const float*)d_in[4];
    const float* out_proj_w = (const float*)d_in[5];
    const float* out_proj_b = (const float*)d_in[6];
    const float* conv_w     = (const float*)d_in[7];
    const float* conv_b     = (const float*)d_in[8];
    const float* p2s_w      = (const float*)d_in[9];
    const float* p2s_b      = (const float*)d_in[10];
    const float* s2p_w      = (const float*)d_in[11];
    const float* s2p_b      = (const float*)d_in[12];
    const float* tw1        = (const float*)d_in[13];
    const float* tb1        = (const float*)d_in[14];
    const float* tw2        = (const float*)d_in[15];
    const float* tb2        = (const float*)d_in[16];
    const float* fw1        = (const float*)d_in[17];
    const float* fb1        = (const float*)d_in[18];
    const float* fw2        = (const float*)d_in[19];
    const float* fb2        = (const float*)d_in[20];
    const float* ln1s = (const float*)d_in[21];
    const float* ln1b = (const float*)d_in[22];
    const float* ln2s = (const float*)d_in[23];
    const float* ln2b = (const float*)d_in[24];
    const float* ln3s = (const float*)d_in[25];
    const float* ln3b = (const float*)d_in[26];
    const float* ln4s = (const float*)d_in[27];
    const float* ln4b = (const float*)d_in[28];
    float* out = (float*)d_out;

    float* scr = nullptr;
    cudaGetSymbolAddress((void**)&scr, d_scratch);
    float* qkv    = scr + OFF_QKV;
    float* attn   = scr + OFF_ATTN;
    float* tmp    = scr + OFF_TMP;
    float* xb     = scr + OFF_X;
    float* comb   = scr + OFF_COMB;
    float* hb     = scr + OFF_H;
    float* deltas = scr + OFF_DELTAS;
    float* states = scr + OFF_STATES;
    float* ffnin  = scr + OFF_FFNIN;
    float* fbuf   = scr + OFF_F;
    float* csum   = scr + OFF_CSUM;

    static bool attr_set = false;
    if (!attr_set) {
        cudaFuncSetAttribute(mma_gemm<0>, cudaFuncAttributeMaxDynamicSharedMemorySize, GEMM_SMEM);
        cudaFuncSetAttribute(mma_gemm<1>, cudaFuncAttributeMaxDynamicSharedMemorySize, GEMM_SMEM);
        cudaFuncSetAttribute(mma_gemm<2>, cudaFuncAttributeMaxDynamicSharedMemorySize, GEMM_SMEM);
        cudaFuncSetAttribute(mma_gemm<3>, cudaFuncAttributeMaxDynamicSharedMemorySize, GEMM_SMEM);
        cudaFuncSetAttribute(attn_mma_kernel, cudaFuncAttributeMaxDynamicSharedMemorySize, ATTN_SMEM);
        attr_set = true;
    }

    // 1. qkv = x @ in_proj_w^T + b
    mma_gemm<0><<<dim3(6, 64), 256, GEMM_SMEM>>>(x_in, 256, in_proj_w, in_proj_b,
                                                 nullptr, 0, qkv, 768, 256);
    // 2. causal attention (tf32 mma, cp.async double-buffered)
    attn_mma_kernel<<<dim3(8, 32), 256, ATTN_SMEM>>>(qkv, attn);
    // 3. out_proj + residual
    mma_gemm<1><<<dim3(2, 64), 256, GEMM_SMEM>>>(attn, 256, out_proj_w, out_proj_b,
                                                 x_in, 256, tmp, 256, 256);
    // 4. x = LN1(tmp)
    ln_warp_kernel<<<1024, 256>>>(tmp, 256, ln1s, ln1b, xb, 256, 8192);
    // 5. conv -> combined[:,256:512]
    conv_kernel<<<8192, 256>>>(xb, conv_w, conv_b, comb);
    // 6. EMA -> combined[:,512:768]  (chunk-parallel)
    ema_kernel<<<dim3(8, 8), 256>>>(xb, comb);
    // 7. combined[:,0:256] = x + 0.3*(x @ p2s^T + b)
    mma_gemm<3><<<dim3(2, 64), 256, GEMM_SMEM>>>(xb, 256, p2s_w, p2s_b,
                                                 xb, 256, comb, 768, 256);
    // 8. h = gelu(comb @ tw1^T + b1)
    mma_gemm<2><<<dim3(4, 64), 256, GEMM_SMEM>>>(comb, 768, tw1, tb1,
                                                 nullptr, 0, hb, 512, 768);
    // 9. deltas = h @ tw2^T + b2
    mma_gemm<0><<<dim3(2, 64), 256, GEMM_SMEM>>>(hb, 512, tw2, tb2,
                                                 nullptr, 0, deltas, 256, 512);
    // 10. states = seq + 0.5*cumsum(deltas)  (two-phase parallel)
    chunksum_kernel<<<dim3(8, 8), 256>>>(deltas, csum);
    cumsum_kernel<<<dim3(8, 8), 256>>>(deltas, seq_state, csum, states);
    // 11. states = LN3(states)
    ln_warp_kernel<<<1024, 256>>>(states, 256, ln3s, ln3b, states, 256, 8192);
    // 12. ffn_in = x + 0.3*(states @ s2p^T + b)
    mma_gemm<3><<<dim3(2, 64), 256, GEMM_SMEM>>>(states, 256, s2p_w, s2p_b,
                                                 xb, 256, ffnin, 256, 256);
    // 13. f = gelu(ffn_in @ fw1^T + b1)
    mma_gemm<2><<<dim3(8, 64), 256, GEMM_SMEM>>>(ffnin, 256, fw1, fb1,
                                                 nullptr, 0, fbuf, 1024, 256);
    // 14. tmp = x + f @ fw2^T + b2
    mma_gemm<1><<<dim3(2, 64), 256, GEMM_SMEM>>>(fbuf, 1024, fw2, fb2,
                                                 xb, 256, tmp, 256, 1024);
    // 15. LN2 -> out
    ln_warp_kernel<<<1024, 256>>>(tmp, 256, ln2s, ln2b, out, 256, 8192);
    // 16. LN4(states[:, -1, :])
    ln_warp_kernel<<<1, 256>>>(states + (size_t)1023 * 256, (long)1024 * 256,
                               ln4s, ln4b, out + (size_t)M_ROWS * 256, 256, 8);
    // 17. trajectory summary
    traj_kernel<<<8, 256>>>(comb, out + (size_t)M_ROWS * 256 + 2048);
}

// round 10
// speedup vs baseline: 1.2173x; 1.0098x over previous
#include <cuda_runtime.h>
#include <math.h>
#include <stdint.h>

#define B_SZ   8
#define T_SEQ  1024
#define D_MOD  256
#define M_ROWS (B_SZ * T_SEQ)   // 8192

// ---------------------------------------------------------------------------
// Scratch
// ---------------------------------------------------------------------------
#define OFF_QKV    0ul
#define OFF_ATTN   6291456ul
#define OFF_TMP    8388608ul
#define OFF_X      10485760ul
#define OFF_COMB   12582912ul
#define OFF_H      18874368ul
#define OFF_DELTAS 23068672ul
#define OFF_STATES 25165824ul
#define OFF_FFNIN  27262976ul
#define OFF_F      29360128ul
#define OFF_CSUM   37748736ul
#define SCRATCH_TOTAL 37765120ul

__device__ float d_scratch[SCRATCH_TOTAL];

__device__ __forceinline__ float gelu_f(float x) {
    return 0.5f * x * (1.0f + erff(x * 0.70710678118654752f));
}

__device__ __forceinline__ uint32_t f2tf32(float x) {
    uint32_t r;
    asm("cvt.rna.tf32.f32 %0, %1;" : "=r"(r) : "f"(x));
    return r;
}

#define MMA_TF32(d, a, b) \
    asm volatile("mma.sync.aligned.m16n8k8.row.col.f32.tf32.tf32.f32 " \
                 "{%0,%1,%2,%3}, {%4,%5,%6,%7}, {%8,%9}, {%0,%1,%2,%3};" \
                 : "+f"(d[0]), "+f"(d[1]), "+f"(d[2]), "+f"(d[3]) \
                 : "r"(a[0]), "r"(a[1]), "r"(a[2]), "r"(a[3]), \
                   "r"(b[0]), "r"(b[1]))

// Fast exp(s/8): FMA-pipe only, no MUFU.
__device__ __forceinline__ float fexp_s8(float s) {
    const float y = s * 0.1803368801111244f;
    const float rnd = y + 12582912.0f;
    const int   i   = __float_as_int(rnd);
    const float nf  = rnd - 12582912.0f;
    const float f   = y - nf;
    float p = 1.3333558146e-3f;
    p = fmaf(p, f, 9.6181291076e-3f);
    p = fmaf(p, f, 5.5504108665e-2f);
    p = fmaf(p, f, 2.4022650696e-1f);
    p = fmaf(p, f, 6.9314718056e-1f);
    p = fmaf(p, f, 1.0f);
    const float scale = __int_as_float((i << 23) + 0x3f800000);
    return p * scale;
}

// ---------------------------------------------------------------------------
// TF32 GEMM v4 (unchanged from R7/R9 best).
// ---------------------------------------------------------------------------
#define GEMM_TS (128 * 36)
#define GEMM_STAGE (2 * GEMM_TS)
#define GEMM_SMEM (3 * GEMM_STAGE * 4)  // 110592 bytes

#define ISSUE_TILE(k0, sidx)                                                   \
    {                                                                          \
        _Pragma("unroll")                                                      \
        for (int i = 0; i < 4; i++) {                                          \
            uint32_t da = smem_base + (uint32_t)(((sidx) * GEMM_STAGE + (mrow0 + 32 * i) * 36 + kq) * 4); \
            const float* ga = A + (size_t)(bm + mrow0 + 32 * i) * lda + (k0) + kq; \
            asm volatile("cp.async.cg.shared.global [%0], [%1], 16;" :: "r"(da), "l"(ga)); \
            uint32_t db = smem_base + (uint32_t)(((sidx) * GEMM_STAGE + GEMM_TS + (mrow0 + 32 * i) * 36 + kq) * 4); \
            const float* gw = W + (size_t)(bn + mrow0 + 32 * i) * (size_t)K + (k0) + kq; \
            asm volatile("cp.async.cg.shared.global [%0], [%1], 16;" :: "r"(db), "l"(gw)); \
        }                                                                      \
        asm volatile("cp.async.commit_group;");                                \
    }

template<int EPI>
__global__ void __launch_bounds__(256, 2) mma_gemm(
    const float* __restrict__ A, int lda,
    const float* __restrict__ W,
    const float* __restrict__ bias,
    const float* __restrict__ addend, int ld_add,
    float* __restrict__ C, int ldc,
    int K)
{
    extern __shared__ uint32_t sm[];
    const uint32_t smem_base = (uint32_t)__cvta_generic_to_shared(sm);

    const int tid  = threadIdx.x;
    const int bm   = blockIdx.y * 128;
    const int bn   = blockIdx.x * 128;
    const int wid  = tid >> 5;
    const int lane = tid & 31;
    const int wm64 = (wid & 1) * 64;
    const int wn32 = (wid >> 1) * 32;
    const int r    = lane >> 2;
    const int t    = lane & 3;

    const int kq    = (tid & 7) * 4;
    const int mrow0 = tid >> 3;

    float acc[4][4][4];
    #pragma unroll
    for (int mi = 0; mi < 4; mi++)
        #pragma unroll
        for (int ni = 0; ni < 4; ni++)
            #pragma unroll
            for (int c = 0; c < 4; c++) acc[mi][ni][c] = 0.0f;

    const int ntiles = K >> 5;

    ISSUE_TILE(0, 0);
    ISSUE_TILE(32, 1);

    int sidx = 0;
    for (int kt = 0; kt < ntiles; kt++) {
        if (kt == ntiles - 1) {
            asm volatile("cp.async.wait_group 0;");
        } else {
            asm volatile("cp.async.wait_group 1;");
        }
        __syncthreads();

        if (kt + 2 < ntiles) {
            int ws = sidx + 2; if (ws >= 3) ws -= 3;
            ISSUE_TILE((kt + 2) * 32, ws);
        }

        const uint32_t* Ab = sm + sidx * GEMM_STAGE;
        const uint32_t* Bb = Ab + GEMM_TS;

        #pragma unroll
        for (int ks = 0; ks < 4; ks++) {
            const int kb = ks * 8;
            uint32_t a[4][4], b[4][2];
            #pragma unroll
            for (int mi = 0; mi < 4; mi++) {
                int idx = (wm64 + mi * 16 + r) * 36 + kb + t;
                a[mi][0] = Ab[idx];
                a[mi][1] = Ab[idx + 8 * 36];
                a[mi][2] = Ab[idx + 4];
                a[mi][3] = Ab[idx + 8 * 36 + 4];
            }
            #pragma unroll
            for (int ni = 0; ni < 4; ni++) {
                int idx = (wn32 + ni * 8 + r) * 36 + kb + t;
                b[ni][0] = Bb[idx];
                b[ni][1] = Bb[idx + 4];
            }
            #pragma unroll
            for (int mi = 0; mi < 4; mi++)
                #pragma unroll
                for (int ni = 0; ni < 4; ni++)
                    MMA_TF32(acc[mi][ni], a[mi], b[ni]);
        }
        sidx++; if (sidx == 3) sidx = 0;
    }

    #pragma unroll
    for (int mi = 0; mi < 4; mi++) {
        const int row0 = bm + wm64 + mi * 16 + r;
        const int row1 = row0 + 8;
        #pragma unroll
        for (int ni = 0; ni < 4; ni++) {
            const int col = bn + wn32 + ni * 8 + 2 * t;
            const float2 bb = *(const float2*)(bias + col);
            float v00 = acc[mi][ni][0] + bb.x;
            float v01 = acc[mi][ni][1] + bb.y;
            float v10 = acc[mi][ni][2] + bb.x;
            float v11 = acc[mi][ni][3] + bb.y;
            if (EPI == 1) {
                const float2 r0 = *(const float2*)(addend + (size_t)row0 * ld_add + col);
                const float2 r1 = *(const float2*)(addend + (size_t)row1 * ld_add + col);
                v00 += r0.x; v01 += r0.y; v10 += r1.x; v11 += r1.y;
            }
            if (EPI == 2) {
                v00 = gelu_f(v00); v01 = gelu_f(v01);
                v10 = gelu_f(v10); v11 = gelu_f(v11);
            }
            if (EPI == 3) {
                const float2 r0 = *(const float2*)(addend + (size_t)row0 * ld_add + col);
                const float2 r1 = *(const float2*)(addend + (size_t)row1 * ld_add + col);
                v00 = r0.x + 0.3f * v00; v01 = r0.y + 0.3f * v01;
                v10 = r1.x + 0.3f * v10; v11 = r1.y + 0.3f * v11;
            }
            *(float2*)(C + (size_t)row0 * ldc + col) = make_float2(v00, v01);
            *(float2*)(C + (size_t)row1 * ldc + col) = make_float2(v10, v11);
        }
    }
}

// ---------------------------------------------------------------------------
// TF32 mma causal flash-attention v3: cp.async double-buffered (R9) +
// heavy-first block remap (qx = gridDim.x-1-blockIdx.x) so long CTAs
// dispatch first and light CTAs backfill.
// ---------------------------------------------------------------------------
#define KV_K     (64 * 68)
#define KV_STAGE (64 * 68 + 64 * 72)
#define ATTN_SMEM (2 * KV_STAGE * 4)   // 71680 bytes

#define AT_ISSUE(jt, s)                                                        \
    {                                                                          \
        const int _j0 = (jt) * 64;                                             \
        _Pragma("unroll")                                                      \
        for (int _i = 0; _i < 4; _i++) {                                       \
            int _idx = tid + _i * 256;                                         \
            int _row = _idx >> 4;                                              \
            int _c4  = (_idx & 15) * 4;                                        \
            const float* _kp = base + (size_t)(_j0 + _row) * 768 + 256 + h * 64 + _c4; \
            uint32_t _dk = smem_base + (uint32_t)(((s) * KV_STAGE + _row * 68 + _c4) * 4); \
            asm volatile("cp.async.cg.shared.global [%0], [%1], 16;" :: "r"(_dk), "l"(_kp)); \
            uint32_t _dv = smem_base + (uint32_t)(((s) * KV_STAGE + KV_K + _row * 72 + _c4) * 4); \
            asm volatile("cp.async.cg.shared.global [%0], [%1], 16;" :: "r"(_dv), "l"(_kp + 256)); \
        }                                                                      \
        asm volatile("cp.async.commit_group;");                                \
    }

__global__ void __launch_bounds__(256) attn_mma_kernel(
    const float* __restrict__ qkv, float* __restrict__ attn_out)
{
    extern __shared__ uint32_t dsm[];
    const uint32_t smem_base = (uint32_t)__cvta_generic_to_shared(dsm);

    const int bh = blockIdx.y;
    const int b  = bh >> 2;
    const int h  = bh & 3;
    const int qx = gridDim.x - 1 - blockIdx.x;   // heavy-first
    const int qbase = qx * 128;
    const int tid  = threadIdx.x;
    const int wid  = tid >> 5;
    const int lane = tid & 31;
    const int r    = lane >> 2;
    const int t    = lane & 3;
    const float* base = qkv + (size_t)b * T_SEQ * 768;

    const int qrow0 = qbase + wid * 16 + r;
    const int qrow1 = qrow0 + 8;

    uint32_t aq[8][4];
    {
        const float* q0 = base + (size_t)qrow0 * 768 + h * 64;
        const float* q1 = base + (size_t)qrow1 * 768 + h * 64;
        #pragma unroll
        for (int ks = 0; ks < 8; ks++) {
            aq[ks][0] = f2tf32(q0[ks * 8 + t]);
            aq[ks][1] = f2tf32(q1[ks * 8 + t]);
            aq[ks][2] = f2tf32(q0[ks * 8 + t + 4]);
            aq[ks][3] = f2tf32(q1[ks * 8 + t + 4]);
        }
    }

    float oacc[8][4];
    #pragma unroll
    for (int ni = 0; ni < 8; ni++)
        #pragma unroll
        for (int c = 0; c < 4; c++) oacc[ni][c] = 0.0f;
    float lsum0 = 0.0f, lsum1 = 0.0f;

    const int ntiles   = 2 * qx + 2;
    const int wrow_max = qbase + wid * 16 + 15;
    const unsigned FULL = 0xffffffffu;
    const int s0 = (lane & ~3) | (t >> 1);
    const int s1 = s0 + 2;

    AT_ISSUE(0, 0);

    for (int jt = 0; jt < ntiles; jt++) {
        const int j0 = jt * 64;
        asm volatile("cp.async.wait_group 0;");
        __syncthreads();

        if (jt + 1 < ntiles) AT_ISSUE(jt + 1, (jt + 1) & 1);

        if (j0 > wrow_max) continue;

        const uint32_t* Ks = dsm + (jt & 1) * KV_STAGE;
        const uint32_t* Vs = Ks + KV_K;

        float sc[8][4];
        #pragma unroll
        for (int ni = 0; ni < 8; ni++)
            #pragma unroll
            for (int c = 0; c < 4; c++) sc[ni][c] = 0.0f;
        #pragma unroll
        for (int ks = 0; ks < 8; ks++) {
            #pragma unroll
            for (int ni = 0; ni < 8; ni++) {
                uint32_t bfr[2];
                const int key = ni * 8 + r;
                bfr[0] = Ks[key * 68 + ks * 8 + t];
                bfr[1] = Ks[key * 68 + ks * 8 + t + 4];
                MMA_TF32(sc[ni], aq[ks], bfr);
            }
        }

        #pragma unroll
        for (int ni = 0; ni < 8; ni++) {
            const int col0 = j0 + ni * 8 + 2 * t;
            float p0 = (col0     <= qrow0) ? fexp_s8(sc[ni][0]) : 0.0f;
            float p1 = (col0 + 1 <= qrow0) ? fexp_s8(sc[ni][1]) : 0.0f;
            float p2 = (col0     <= qrow1) ? fexp_s8(sc[ni][2]) : 0.0f;
            float p3 = (col0 + 1 <= qrow1) ? fexp_s8(sc[ni][3]) : 0.0f;
            lsum0 += p0 + p1;
            lsum1 += p2 + p3;
            sc[ni][0] = p0; sc[ni][1] = p1; sc[ni][2] = p2; sc[ni][3] = p3;
        }

        #pragma unroll
        for (int ks = 0; ks < 8; ks++) {
            uint32_t ap[4];
            float e, o;
            e = __shfl_sync(FULL, sc[ks][0], s0);
            o = __shfl_sync(FULL, sc[ks][1], s0);
            ap[0] = f2tf32((t & 1) ? o : e);
            e = __shfl_sync(FULL, sc[ks][2], s0);
            o = __shfl_sync(FULL, sc[ks][3], s0);
            ap[1] = f2tf32((t & 1) ? o : e);
            e = __shfl_sync(FULL, sc[ks][0], s1);
            o = __shfl_sync(FULL, sc[ks][1], s1);
            ap[2] = f2tf32((t & 1) ? o : e);
            e = __shfl_sync(FULL, sc[ks][2], s1);
            o = __shfl_sync(FULL, sc[ks][3], s1);
            ap[3] = f2tf32((t & 1) ? o : e);
            #pragma unroll
            for (int ni = 0; ni < 8; ni++) {
                uint32_t bfr[2];
                bfr[0] = Vs[(ks * 8 + t)     * 72 + ni * 8 + r];
                bfr[1] = Vs[(ks * 8 + t + 4) * 72 + ni * 8 + r];
                MMA_TF32(oacc[ni], ap, bfr);
            }
        }
    }

    lsum0 += __shfl_xor_sync(FULL, lsum0, 1);
    lsum0 += __shfl_xor_sync(FULL, lsum0, 2);
    lsum1 += __shfl_xor_sync(FULL, lsum1, 1);
    lsum1 += __shfl_xor_sync(FULL, lsum1, 2);
    const float inv0 = 1.0f / lsum0;
    const float inv1 = 1.0f / lsum1;

    float* op0 = attn_out + ((size_t)b * T_SEQ + qrow0) * 256 + h * 64;
    float* op1 = attn_out + ((size_t)b * T_SEQ + qrow1) * 256 + h * 64;
    #pragma unroll
    for (int ni = 0; ni < 8; ni++) {
        *(float2*)(op0 + ni * 8 + 2 * t) = make_float2(oacc[ni][0] * inv0, oacc[ni][1] * inv0);
        *(float2*)(op1 + ni * 8 + 2 * t) = make_float2(oacc[ni][2] * inv1, oacc[ni][3] * inv1);
    }
}

// ---------------------------------------------------------------------------
// LayerNorm v2: 2 rows per warp (independent reduction chains -> 2x ILP).
// ---------------------------------------------------------------------------
__global__ void __launch_bounds__(256) ln_warp_kernel(
    const float* __restrict__ in, long ld_in,
    const float* __restrict__ gamma, const float* __restrict__ beta,
    float* __restrict__ out, long ld_out, int nrows)
{
    const int wid = threadIdx.x >> 5, lane = threadIdx.x & 31;
    const int rowA = blockIdx.x * 16 + wid * 2;
    const int rowB = rowA + 1;
    if (rowA >= nrows) return;
    const bool hasB = (rowB < nrows);

    const float* ipA = in + (size_t)rowA * ld_in + lane * 8;
    const float* ipB = in + (size_t)(hasB ? rowB : rowA) * ld_in + lane * 8;
    float4 a0 = ((const float4*)ipA)[0];
    float4 a1 = ((const float4*)ipA)[1];
    float4 b0 = ((const float4*)ipB)[0];
    float4 b1 = ((const float4*)ipB)[1];

    float sA  = a0.x + a0.y + a0.z + a0.w + a1.x + a1.y + a1.z + a1.w;
    float qA  = a0.x*a0.x + a0.y*a0.y + a0.z*a0.z + a0.w*a0.w
              + a1.x*a1.x + a1.y*a1.y + a1.z*a1.z + a1.w*a1.w;
    float sB  = b0.x + b0.y + b0.z + b0.w + b1.x + b1.y + b1.z + b1.w;
    float qB  = b0.x*b0.x + b0.y*b0.y + b0.z*b0.z + b0.w*b0.w
              + b1.x*b1.x + b1.y*b1.y + b1.z*b1.z + b1.w*b1.w;
    #pragma unroll
    for (int o = 16; o > 0; o >>= 1) {
        sA += __shfl_xor_sync(0xffffffffu, sA, o);
        sB += __shfl_xor_sync(0xffffffffu, sB, o);
        qA += __shfl_xor_sync(0xffffffffu, qA, o);
        qB += __shfl_xor_sync(0xffffffffu, qB, o);
    }
    const float mA = sA * (1.0f / 256.0f);
    const float vA = qA * (1.0f / 256.0f) - mA * mA;
    const float rA = rsqrtf(vA + 1e-5f);
    const float mB = sB * (1.0f / 256.0f);
    const float vB = qB * (1.0f / 256.0f) - mB * mB;
    const float rB = rsqrtf(vB + 1e-5f);

    const float4 g0 = ((const float4*)(gamma + lane * 8))[0];
    const float4 g1 = ((const float4*)(gamma + lane * 8))[1];
    const float4 be0 = ((const float4*)(beta  + lane * 8))[0];
    const float4 be1 = ((const float4*)(beta  + lane * 8))[1];

    float4 o0, o1;
    o0.x = (a0.x - mA) * rA * g0.x + be0.x;
    o0.y = (a0.y - mA) * rA * g0.y + be0.y;
    o0.z = (a0.z - mA) * rA * g0.z + be0.z;
    o0.w = (a0.w - mA) * rA * g0.w + be0.w;
    o1.x = (a1.x - mA) * rA * g1.x + be1.x;
    o1.y = (a1.y - mA) * rA * g1.y + be1.y;
    o1.z = (a1.z - mA) * rA * g1.z + be1.z;
    o1.w = (a1.w - mA) * rA * g1.w + be1.w;
    float* opA = out + (size_t)rowA * ld_out + lane * 8;
    ((float4*)opA)[0] = o0;
    ((float4*)opA)[1] = o1;

    if (hasB) {
        float4 p0, p1;
        p0.x = (b0.x - mB) * rB * g0.x + be0.x;
        p0.y = (b0.y - mB) * rB * g0.y + be0.y;
        p0.z = (b0.z - mB) * rB * g0.z + be0.z;
        p0.w = (b0.w - mB) * rB * g0.w + be0.w;
        p1.x = (b1.x - mB) * rB * g1.x + be1.x;
        p1.y = (b1.y - mB) * rB * g1.y + be1.y;
        p1.z = (b1.z - mB) * rB * g1.z + be1.z;
        p1.w = (b1.w - mB) * rB * g1.w + be1.w;
        float* opB = out + (size_t)rowB * ld_out + lane * 8;
        ((float4*)opB)[0] = p0;
        ((float4*)opB)[1] = p1;
    }
}

__global__ void __launch_bounds__(256) conv_kernel(
    const float* __restrict__ x, const float* __restrict__ cw,
    const float* __restrict__ cb, float* __restrict__ comb)
{
    const int idx = blockIdx.x * 256 + threadIdx.x;
    const int d = idx & 255;
    const int t = (idx >> 8) & 1023;
    const int b = idx >> 18;
    float r = cb[d];
    #pragma unroll
    for (int w = 0; w < 8; w++) {
        int tt = t - 7 + w;
        if (tt >= 0) r = fmaf(cw[d * 8 + w], x[((size_t)b * 1024 + tt) * 256 + d], r);
    }
    comb[((size_t)b * 1024 + t) * 768 + 256 + d] = r;
}

// ---------------------------------------------------------------------------
// EMA, chunk-parallel; last chunk also emits trajectory summary (fused traj).
// ---------------------------------------------------------------------------
__global__ void __launch_bounds__(256) ema_kernel(
    const float* __restrict__ x, float* __restrict__ comb,
    float* __restrict__ traj_out)
{
    const int b = blockIdx.x, chunk = blockIdx.y, d = threadIdx.x;
    const int t0 = chunk * 128;
    int start = t0 - 256; if (start < 0) start = 0;
    const float* xp = x + (size_t)b * 1024 * 256 + d;
    float c = 0.0f;
    #pragma unroll 8
    for (int t = start; t < t0; t++)
        c = fmaf(0.9f, c, 0.1f * xp[(size_t)t * 256]);
    float* op = comb + (size_t)b * 1024 * 768 + 512 + d;
    #pragma unroll 8
    for (int t = t0; t < t0 + 128; t++) {
        c = fmaf(0.9f, c, 0.1f * xp[(size_t)t * 256]);
        op[(size_t)t * 768] = c;
    }
    if (chunk == 7) traj_out[b * 256 + d] = c;
}

__global__ void __launch_bounds__(256) chunksum_kernel(
    const float* __restrict__ deltas, float* __restrict__ csum)
{
    const int b = blockIdx.x, chunk = blockIdx.y, d = threadIdx.x;
    const float* dp = deltas + ((size_t)b * 1024 + chunk * 128) * 256 + d;
    float s = 0.0f;
    #pragma unroll 8
    for (int t = 0; t < 128; t++) s += dp[(size_t)t * 256];
    csum[(b * 8 + chunk) * 256 + d] = s;
}

__global__ void __launch_bounds__(256) cumsum_kernel(
    const float* __restrict__ deltas, const float* __restrict__ seq,
    const float* __restrict__ csum, float* __restrict__ states)
{
    const int b = blockIdx.x, chunk = blockIdx.y, d = threadIdx.x;
    float c = seq[b * 256 + d];
    for (int cc = 0; cc < 8; cc++)
        if (cc < chunk) c = fmaf(0.5f, csum[(b * 8 + cc) * 256 + d], c);
    const float* dp = deltas + ((size_t)b * 1024 + chunk * 128) * 256 + d;
    float* sp = states + ((size_t)b * 1024 + chunk * 128) * 256 + d;
    #pragma unroll 8
    for (int t = 0; t < 128; t++) {
        c = fmaf(0.5f, dp[(size_t)t * 256], c);
        sp[(size_t)t * 256] = c;
    }
}

// ---------------------------------------------------------------------------
// Launch
// ---------------------------------------------------------------------------
extern "C" void kernel_launch(void* const* d_in, const int* in_sizes, int n_in,
                              void* d_out, int out_size)
{
    const float* x_in       = (const float*)d_in[0];
    const float* seq_state  = (const float*)d_in[1];
    const float* in_proj_w  = (const float*)d_in[3];
    const float* in_proj_b  = (const float*)d_in[4];
    const float* out_proj_w = (const float*)d_in[5];
    const float* out_proj_b = (const float*)d_in[6];
    const float* conv_w     = (const float*)d_in[7];
    const float* conv_b     = (const float*)d_in[8];
    const float* p2s_w      = (const float*)d_in[9];
    const float* p2s_b      = (const float*)d_in[10];
    const float* s2p_w      = (const float*)d_in[11];
    const float* s2p_b      = (const float*)d_in[12];
    const float* tw1        = (const float*)d_in[13];
    const float* tb1        = (const float*)d_in[14];
    const float* tw2        = (const float*)d_in[15];
    const float* tb2        = (const float*)d_in[16];
    const float* fw1        = (const float*)d_in[17];
    const float* fb1        = (const float*)d_in[18];
    const float* fw2        = (const float*)d_in[19];
    const float* fb2        = (const float*)d_in[20];
    const float* ln1s = (const float*)d_in[21];
    const float* ln1b = (const float*)d_in[22];
    const float* ln2s = (const float*)d_in[23];
    const float* ln2b = (const float*)d_in[24];
    const float* ln3s = (const float*)d_in[25];
    const float* ln3b = (const float*)d_in[26];
    const float* ln4s = (const float*)d_in[27];
    const float* ln4b = (const float*)d_in[28];
    float* out = (float*)d_out;

    float* scr = nullptr;
    cudaGetSymbolAddress((void**)&scr, d_scratch);
    float* qkv    = scr + OFF_QKV;
    float* attn   = scr + OFF_ATTN;
    float* tmp    = scr + OFF_TMP;
    float* xb     = scr + OFF_X;
    float* comb   = scr + OFF_COMB;
    float* hb     = scr + OFF_H;
    float* deltas = scr + OFF_DELTAS;
    float* states = scr + OFF_STATES;
    float* ffnin  = scr + OFF_FFNIN;
    float* fbuf   = scr + OFF_F;
    float* csum   = scr + OFF_CSUM;

    static bool attr_set = false;
    if (!attr_set) {
        cudaFuncSetAttribute(mma_gemm<0>, cudaFuncAttributeMaxDynamicSharedMemorySize, GEMM_SMEM);
        cudaFuncSetAttribute(mma_gemm<1>, cudaFuncAttributeMaxDynamicSharedMemorySize, GEMM_SMEM);
        cudaFuncSetAttribute(mma_gemm<2>, cudaFuncAttributeMaxDynamicSharedMemorySize, GEMM_SMEM);
        cudaFuncSetAttribute(mma_gemm<3>, cudaFuncAttributeMaxDynamicSharedMemorySize, GEMM_SMEM);
        cudaFuncSetAttribute(attn_mma_kernel, cudaFuncAttributeMaxDynamicSharedMemorySize, ATTN_SMEM);
        attr_set = true;
    }

    // 1. qkv = x @ in_proj_w^T + b
    mma_gemm<0><<<dim3(6, 64), 256, GEMM_SMEM>>>(x_in, 256, in_proj_w, in_proj_b,
                                                 nullptr, 0, qkv, 768, 256);
    // 2. causal attention (tf32 mma, double-buffered, heavy-first)
    attn_mma_kernel<<<dim3(8, 32), 256, ATTN_SMEM>>>(qkv, attn);
    // 3. out_proj + residual
    mma_gemm<1><<<dim3(2, 64), 256, GEMM_SMEM>>>(attn, 256, out_proj_w, out_proj_b,
                                                 x_in, 256, tmp, 256, 256);
    // 4. x = LN1(tmp)
    ln_warp_kernel<<<512, 256>>>(tmp, 256, ln1s, ln1b, xb, 256, 8192);
    // 5. conv -> combined[:,256:512]
    conv_kernel<<<8192, 256>>>(xb, conv_w, conv_b, comb);
    // 6. EMA -> combined[:,512:768] (+ trajectory summary, fused)
    ema_kernel<<<dim3(8, 8), 256>>>(xb, comb, out + (size_t)M_ROWS * 256 + 2048);
    // 7. combined[:,0:256] = x + 0.3*(x @ p2s^T + b)
    mma_gemm<3><<<dim3(2, 64), 256, GEMM_SMEM>>>(xb, 256, p2s_w, p2s_b,
                                                 xb, 256, comb, 768, 256);
    // 8. h = gelu(comb @ tw1^T + b1)
    mma_gemm<2><<<dim3(4, 64), 256, GEMM_SMEM>>>(comb, 768, tw1, tb1,
                                                 nullptr, 0, hb, 512, 768);
    // 9. deltas = h @ tw2^T + b2
    mma_gemm<0><<<dim3(2, 64), 256, GEMM_SMEM>>>(hb, 512, tw2, tb2,
                                                 nullptr, 0, deltas, 256, 512);
    // 10. states = seq + 0.5*cumsum(deltas)  (two-phase parallel)
    chunksum_kernel<<<dim3(8, 8), 256>>>(deltas, csum);
    cumsum_kernel<<<dim3(8, 8), 256>>>(deltas, seq_state, csum, states);
    // 11. states = LN3(states)
    ln_warp_kernel<<<512, 256>>>(states, 256, ln3s, ln3b, states, 256, 8192);
    // 12. ffn_in = x + 0.3*(states @ s2p^T + b)
    mma_gemm<3><<<dim3(2, 64), 256, GEMM_SMEM>>>(states, 256, s2p_w, s2p_b,
                                                 xb, 256, ffnin, 256, 256);
    // 13. f = gelu(ffn_in @ fw1^T + b1)
    mma_gemm<2><<<dim3(8, 64), 256, GEMM_SMEM>>>(ffnin, 256, fw1, fb1,
                                                 nullptr, 0, fbuf, 1024, 256);
    // 14. tmp = x + f @ fw2^T + b2
    mma_gemm<1><<<dim3(2, 64), 256, GEMM_SMEM>>>(fbuf, 1024, fw2, fb2,
                                                 xb, 256, tmp, 256, 1024);
    // 15. LN2 -> out
    ln_warp_kernel<<<512, 256>>>(tmp, 256, ln2s, ln2b, out, 256, 8192);
    // 16. LN4(states[:, -1, :])
    ln_warp_kernel<<<1, 256>>>(states + (size_t)1023 * 256, (long)1024 * 256,
                               ln4s, ln4b, out + (size_t)M_ROWS * 256, 256, 8);
}

// round 11
// speedup vs baseline: 1.4526x; 1.1933x over previous
#include <cuda_runtime.h>
#include <cuda_fp16.h>
#include <math.h>
#include <stdint.h>

#define B_SZ   8
#define T_SEQ  1024
#define D_MOD  256
#define M_ROWS (B_SZ * T_SEQ)   // 8192

// ---------------------------------------------------------------------------
// Scratch layout (float units)
// ---------------------------------------------------------------------------
#define OFF_QKV      0ul          // [8192,768] fp32
#define OFF_TMP      6291456ul    // [8192,256] fp32
#define OFF_X        8388608ul    // [8192,256] fp32
#define OFF_STATES   10485760ul   // [8192,256] fp32
#define OFF_DELTAS   12582912ul   // [8192,256] fp32
#define OFF_CSUM     14680064ul   // [64,256]   fp32
#define OFF_XIN_H    14696448ul   // [8192,256] half
#define OFF_ATTN_H   15745024ul   // [8192,256] half
#define OFF_XB_H     16793600ul   // [8192,256] half
#define OFF_COMB_H   17842176ul   // [8192,768] half
#define OFF_HB_H     20987904ul   // [8192,512] half
#define OFF_STATES_H 23085056ul   // [8192,256] half
#define OFF_FFNIN_H  24133632ul   // [8192,256] half
#define OFF_FBUF_H   25182208ul   // [8192,1024] half
#define OFF_WH       29376512ul   // all weights, half
#define SCRATCH_TOTAL 30097408ul

// weight offsets within W_H (half units)
#define WH_IP   0
#define WH_OP   196608
#define WH_P2S  262144
#define WH_S2P  327680
#define WH_TW1  393216
#define WH_TW2  786432
#define WH_FW1  917504
#define WH_FW2  1179648

__device__ float d_scratch[SCRATCH_TOTAL];

__device__ __forceinline__ float gelu_f(float x) {
    return 0.5f * x * (1.0f + erff(x * 0.70710678118654752f));
}

__device__ __forceinline__ uint32_t f2tf32(float x) {
    uint32_t r;
    asm("cvt.rna.tf32.f32 %0, %1;" : "=r"(r) : "f"(x));
    return r;
}

#define MMA_TF32(d, a, b) \
    asm volatile("mma.sync.aligned.m16n8k8.row.col.f32.tf32.tf32.f32 " \
                 "{%0,%1,%2,%3}, {%4,%5,%6,%7}, {%8,%9}, {%0,%1,%2,%3};" \
                 : "+f"(d[0]), "+f"(d[1]), "+f"(d[2]), "+f"(d[3]) \
                 : "r"(a[0]), "r"(a[1]), "r"(a[2]), "r"(a[3]), \
                   "r"(b[0]), "r"(b[1]))

#define MMA_F16(d, a, b) \
    asm volatile("mma.sync.aligned.m16n8k16.row.col.f32.f16.f16.f32 " \
                 "{%0,%1,%2,%3}, {%4,%5,%6,%7}, {%8,%9}, {%0,%1,%2,%3};" \
                 : "+f"(d[0]), "+f"(d[1]), "+f"(d[2]), "+f"(d[3]) \
                 : "r"(a[0]), "r"(a[1]), "r"(a[2]), "r"(a[3]), \
                   "r"(b[0]), "r"(b[1]))

// Fast exp(s/8): FMA-pipe only, no MUFU.
__device__ __forceinline__ float fexp_s8(float s) {
    const float y = s * 0.1803368801111244f;
    const float rnd = y + 12582912.0f;
    const int   i   = __float_as_int(rnd);
    const float nf  = rnd - 12582912.0f;
    const float f   = y - nf;
    float p = 1.3333558146e-3f;
    p = fmaf(p, f, 9.6181291076e-3f);
    p = fmaf(p, f, 5.5504108665e-2f);
    p = fmaf(p, f, 2.4022650696e-1f);
    p = fmaf(p, f, 6.9314718056e-1f);
    p = fmaf(p, f, 1.0f);
    const float scale = __int_as_float((i << 23) + 0x3f800000);
    return p * scale;
}

// ---------------------------------------------------------------------------
// fp32 -> fp16 bulk conversion: x_in + all 8 weight matrices, one kernel.
// Work item = 8 elements (two float4 -> one uint4 of 8 halves).
// ---------------------------------------------------------------------------
__global__ void __launch_bounds__(256) cvt_all_kernel(
    const float* __restrict__ xin,
    const float* __restrict__ w_ip, const float* __restrict__ w_op,
    const float* __restrict__ w_p2s, const float* __restrict__ w_s2p,
    const float* __restrict__ w_tw1, const float* __restrict__ w_tw2,
    const float* __restrict__ w_fw1, const float* __restrict__ w_fw2,
    __half* __restrict__ xin_h, __half* __restrict__ w_h)
{
    const size_t e = ((size_t)blockIdx.x * 256 + threadIdx.x) * 8;
    const float* src; __half* dst;
    if      (e < 2097152ul) { src = xin   + e;             dst = xin_h + e; }
    else if (e < 2293760ul) { src = w_ip  + (e - 2097152); dst = w_h + WH_IP  + (e - 2097152); }
    else if (e < 2359296ul) { src = w_op  + (e - 2293760); dst = w_h + WH_OP  + (e - 2293760); }
    else if (e < 2424832ul) { src = w_p2s + (e - 2359296); dst = w_h + WH_P2S + (e - 2359296); }
    else if (e < 2490368ul) { src = w_s2p + (e - 2424832); dst = w_h + WH_S2P + (e - 2424832); }
    else if (e < 2883584ul) { src = w_tw1 + (e - 2490368); dst = w_h + WH_TW1 + (e - 2490368); }
    else if (e < 3014656ul) { src = w_tw2 + (e - 2883584); dst = w_h + WH_TW2 + (e - 2883584); }
    else if (e < 3276800ul) { src = w_fw1 + (e - 3014656); dst = w_h + WH_FW1 + (e - 3014656); }
    else                    { src = w_fw2 + (e - 3276800); dst = w_h + WH_FW2 + (e - 3276800); }
    float4 f0 = ((const float4*)src)[0];
    float4 f1 = ((const float4*)src)[1];
    __half2 h[4];
    h[0] = __floats2half2_rn(f0.x, f0.y);
    h[1] = __floats2half2_rn(f0.z, f0.w);
    h[2] = __floats2half2_rn(f1.x, f1.y);
    h[3] = __floats2half2_rn(f1.z, f1.w);
    *(uint4*)dst = *(uint4*)h;
}

// ---------------------------------------------------------------------------
// FP16 GEMM: C[M,N] = epi( A[M,K] @ W[N,K]^T + bias[N] ), fp32 accumulate.
// 3-stage cp.async, one syncthreads per k-tile, BM=BN=128, BK=32 halves,
// warp tile 64x32 via m16n8k16, __launch_bounds__(256,2).
// Smem tiles in half2 units, row stride 36 (conflict-free fragment LDS).
// EPI: 0 bias | 1 bias+addend | 2 gelu | 3 addend + 0.3*(acc+bias)
// OUTH: write C as half (ldc in halves) else float.
// ---------------------------------------------------------------------------
#define GEMM_TS (128 * 36)              // half2 units per tile
#define GEMM_STAGE (2 * GEMM_TS)
#define GEMM_SMEM (3 * GEMM_STAGE * 4)  // 110592 bytes

#define ISSUE_TILE(k0, sidx)                                                   \
    {                                                                          \
        _Pragma("unroll")                                                      \
        for (int i = 0; i < 2; i++) {                                          \
            int idx = tid + i * 256;                                           \
            int row = idx >> 2;                                                \
            int ch  = idx & 3;                                                 \
            uint32_t da = smem_base + (uint32_t)(((sidx) * GEMM_STAGE + row * 36 + ch * 4) * 4); \
            const __half* ga = A + (size_t)(bm + row) * lda + (k0) + ch * 8;   \
            asm volatile("cp.async.cg.shared.global [%0], [%1], 16;" :: "r"(da), "l"(ga)); \
            uint32_t db = smem_base + (uint32_t)(((sidx) * GEMM_STAGE + GEMM_TS + row * 36 + ch * 4) * 4); \
            const __half* gw = W + (size_t)(bn + row) * (size_t)K + (k0) + ch * 8; \
            asm volatile("cp.async.cg.shared.global [%0], [%1], 16;" :: "r"(db), "l"(gw)); \
        }                                                                      \
        asm volatile("cp.async.commit_group;");                                \
    }

template<int EPI, bool OUTH>
__global__ void __launch_bounds__(256, 2) mma_gemm(
    const __half* __restrict__ A, int lda,
    const __half* __restrict__ W,
    const float* __restrict__ bias,
    const float* __restrict__ addend, int ld_add,
    void* __restrict__ Cv, int ldc,
    int K)
{
    extern __shared__ uint32_t sm[];
    const uint32_t smem_base = (uint32_t)__cvta_generic_to_shared(sm);

    const int tid  = threadIdx.x;
    const int bm   = blockIdx.y * 128;
    const int bn   = blockIdx.x * 128;
    const int wid  = tid >> 5;
    const int lane = tid & 31;
    const int wm64 = (wid & 1) * 64;
    const int wn32 = (wid >> 1) * 32;
    const int r    = lane >> 2;
    const int t    = lane & 3;

    float acc[4][4][4];
    #pragma unroll
    for (int mi = 0; mi < 4; mi++)
        #pragma unroll
        for (int ni = 0; ni < 4; ni++)
            #pragma unroll
            for (int c = 0; c < 4; c++) acc[mi][ni][c] = 0.0f;

    const int ntiles = K >> 5;

    ISSUE_TILE(0, 0);
    ISSUE_TILE(32, 1);

    int sidx = 0;
    for (int kt = 0; kt < ntiles; kt++) {
        if (kt == ntiles - 1) {
            asm volatile("cp.async.wait_group 0;");
        } else {
            asm volatile("cp.async.wait_group 1;");
        }
        __syncthreads();

        if (kt + 2 < ntiles) {
            int ws = sidx + 2; if (ws >= 3) ws -= 3;
            ISSUE_TILE((kt + 2) * 32, ws);
        }

        const uint32_t* Ab = sm + sidx * GEMM_STAGE;
        const uint32_t* Bb = Ab + GEMM_TS;

        #pragma unroll
        for (int ks = 0; ks < 2; ks++) {          // two k16 steps per 32-k tile
            const int kb = ks * 8;                // half2 offset
            uint32_t a[4][4], b[4][2];
            #pragma unroll
            for (int mi = 0; mi < 4; mi++) {
                int idx = (wm64 + mi * 16 + r) * 36 + kb + t;
                a[mi][0] = Ab[idx];
                a[mi][1] = Ab[idx + 8 * 36];
                a[mi][2] = Ab[idx + 4];
                a[mi][3] = Ab[idx + 8 * 36 + 4];
            }
            #pragma unroll
            for (int ni = 0; ni < 4; ni++) {
                int idx = (wn32 + ni * 8 + r) * 36 + kb + t;
                b[ni][0] = Bb[idx];
                b[ni][1] = Bb[idx + 4];
            }
            #pragma unroll
            for (int mi = 0; mi < 4; mi++)
                #pragma unroll
                for (int ni = 0; ni < 4; ni++)
                    MMA_F16(acc[mi][ni], a[mi], b[ni]);
        }
        sidx++; if (sidx == 3) sidx = 0;
    }

    float* Cf = (float*)Cv;
    __half* Ch = (__half*)Cv;

    #pragma unroll
    for (int mi = 0; mi < 4; mi++) {
        const int row0 = bm + wm64 + mi * 16 + r;
        const int row1 = row0 + 8;
        #pragma unroll
        for (int ni = 0; ni < 4; ni++) {
            const int col = bn + wn32 + ni * 8 + 2 * t;
            const float2 bb = *(const float2*)(bias + col);
            float v00 = acc[mi][ni][0] + bb.x;
            float v01 = acc[mi][ni][1] + bb.y;
            float v10 = acc[mi][ni][2] + bb.x;
            float v11 = acc[mi][ni][3] + bb.y;
            if (EPI == 1) {
                const float2 r0 = *(const float2*)(addend + (size_t)row0 * ld_add + col);
                const float2 r1 = *(const float2*)(addend + (size_t)row1 * ld_add + col);
                v00 += r0.x; v01 += r0.y; v10 += r1.x; v11 += r1.y;
            }
            if (EPI == 2) {
                v00 = gelu_f(v00); v01 = gelu_f(v01);
                v10 = gelu_f(v10); v11 = gelu_f(v11);
            }
            if (EPI == 3) {
                const float2 r0 = *(const float2*)(addend + (size_t)row0 * ld_add + col);
                const float2 r1 = *(const float2*)(addend + (size_t)row1 * ld_add + col);
                v00 = r0.x + 0.3f * v00; v01 = r0.y + 0.3f * v01;
                v10 = r1.x + 0.3f * v10; v11 = r1.y + 0.3f * v11;
            }
            if (OUTH) {
                *(__half2*)(Ch + (size_t)row0 * ldc + col) = __floats2half2_rn(v00, v01);
                *(__half2*)(Ch + (size_t)row1 * ldc + col) = __floats2half2_rn(v10, v11);
            } else {
                *(float2*)(Cf + (size_t)row0 * ldc + col) = make_float2(v00, v01);
                *(float2*)(Cf + (size_t)row1 * ldc + col) = make_float2(v10, v11);
            }
        }
    }
}

// ---------------------------------------------------------------------------
// TF32 mma causal flash-attention (R10): cp.async double-buffered, heavy-first
// remap; epilogue now writes fp16 (consumed only by out_proj GEMM).
// ---------------------------------------------------------------------------
#define KV_K     (64 * 68)
#define KV_STAGE (64 * 68 + 64 * 72)
#define ATTN_SMEM (2 * KV_STAGE * 4)   // 71680 bytes

#define AT_ISSUE(jt, s)                                                        \
    {                                                                          \
        const int _j0 = (jt) * 64;                                             \
        _Pragma("unroll")                                                      \
        for (int _i = 0; _i < 4; _i++) {                                       \
            int _idx = tid + _i * 256;                                         \
            int _row = _idx >> 4;                                              \
            int _c4  = (_idx & 15) * 4;                                        \
            const float* _kp = base + (size_t)(_j0 + _row) * 768 + 256 + h * 64 + _c4; \
            uint32_t _dk = smem_base + (uint32_t)(((s) * KV_STAGE + _row * 68 + _c4) * 4); \
            asm volatile("cp.async.cg.shared.global [%0], [%1], 16;" :: "r"(_dk), "l"(_kp)); \
            uint32_t _dv = smem_base + (uint32_t)(((s) * KV_STAGE + KV_K + _row * 72 + _c4) * 4); \
            asm volatile("cp.async.cg.shared.global [%0], [%1], 16;" :: "r"(_dv), "l"(_kp + 256)); \
        }                                                                      \
        asm volatile("cp.async.commit_group;");                                \
    }

__global__ void __launch_bounds__(256) attn_mma_kernel(
    const float* __restrict__ qkv, __half* __restrict__ attn_out)
{
    extern __shared__ uint32_t dsm[];
    const uint32_t smem_base = (uint32_t)__cvta_generic_to_shared(dsm);

    const int bh = blockIdx.y;
    const int b  = bh >> 2;
    const int h  = bh & 3;
    const int qx = gridDim.x - 1 - blockIdx.x;   // heavy-first
    const int qbase = qx * 128;
    const int tid  = threadIdx.x;
    const int wid  = tid >> 5;
    const int lane = tid & 31;
    const int r    = lane >> 2;
    const int t    = lane & 3;
    const float* base = qkv + (size_t)b * T_SEQ * 768;

    const int qrow0 = qbase + wid * 16 + r;
    const int qrow1 = qrow0 + 8;

    uint32_t aq[8][4];
    {
        const float* q0 = base + (size_t)qrow0 * 768 + h * 64;
        const float* q1 = base + (size_t)qrow1 * 768 + h * 64;
        #pragma unroll
        for (int ks = 0; ks < 8; ks++) {
            aq[ks][0] = f2tf32(q0[ks * 8 + t]);
            aq[ks][1] = f2tf32(q1[ks * 8 + t]);
            aq[ks][2] = f2tf32(q0[ks * 8 + t + 4]);
            aq[ks][3] = f2tf32(q1[ks * 8 + t + 4]);
        }
    }

    float oacc[8][4];
    #pragma unroll
    for (int ni = 0; ni < 8; ni++)
        #pragma unroll
        for (int c = 0; c < 4; c++) oacc[ni][c] = 0.0f;
    float lsum0 = 0.0f, lsum1 = 0.0f;

    const int ntiles   = 2 * qx + 2;
    const int wrow_max = qbase + wid * 16 + 15;
    const unsigned FULL = 0xffffffffu;
    const int s0 = (lane & ~3) | (t >> 1);
    const int s1 = s0 + 2;

    AT_ISSUE(0, 0);

    for (int jt = 0; jt < ntiles; jt++) {
        const int j0 = jt * 64;
        asm volatile("cp.async.wait_group 0;");
        __syncthreads();

        if (jt + 1 < ntiles) AT_ISSUE(jt + 1, (jt + 1) & 1);

        if (j0 > wrow_max) continue;

        const uint32_t* Ks = dsm + (jt & 1) * KV_STAGE;
        const uint32_t* Vs = Ks + KV_K;

        float sc[8][4];
        #pragma unroll
        for (int ni = 0; ni < 8; ni++)
            #pragma unroll
            for (int c = 0; c < 4; c++) sc[ni][c] = 0.0f;
        #pragma unroll
        for (int ks = 0; ks < 8; ks++) {
            #pragma unroll
            for (int ni = 0; ni < 8; ni++) {
                uint32_t bfr[2];
                const int key = ni * 8 + r;
                bfr[0] = Ks[key * 68 + ks * 8 + t];
                bfr[1] = Ks[key * 68 + ks * 8 + t + 4];
                MMA_TF32(sc[ni], aq[ks], bfr);
            }
        }

        #pragma unroll
        for (int ni = 0; ni < 8; ni++) {
            const int col0 = j0 + ni * 8 + 2 * t;
            float p0 = (col0     <= qrow0) ? fexp_s8(sc[ni][0]) : 0.0f;
            float p1 = (col0 + 1 <= qrow0) ? fexp_s8(sc[ni][1]) : 0.0f;
            float p2 = (col0     <= qrow1) ? fexp_s8(sc[ni][2]) : 0.0f;
            float p3 = (col0 + 1 <= qrow1) ? fexp_s8(sc[ni][3]) : 0.0f;
            lsum0 += p0 + p1;
            lsum1 += p2 + p3;
            sc[ni][0] = p0; sc[ni][1] = p1; sc[ni][2] = p2; sc[ni][3] = p3;
        }

        #pragma unroll
        for (int ks = 0; ks < 8; ks++) {
            uint32_t ap[4];
            float e, o;
            e = __shfl_sync(FULL, sc[ks][0], s0);
            o = __shfl_sync(FULL, sc[ks][1], s0);
            ap[0] = f2tf32((t & 1) ? o : e);
            e = __shfl_sync(FULL, sc[ks][2], s0);
            o = __shfl_sync(FULL, sc[ks][3], s0);
            ap[1] = f2tf32((t & 1) ? o : e);
            e = __shfl_sync(FULL, sc[ks][0], s1);
            o = __shfl_sync(FULL, sc[ks][1], s1);
            ap[2] = f2tf32((t & 1) ? o : e);
            e = __shfl_sync(FULL, sc[ks][2], s1);
            o = __shfl_sync(FULL, sc[ks][3], s1);
            ap[3] = f2tf32((t & 1) ? o : e);
            #pragma unroll
            for (int ni = 0; ni < 8; ni++) {
                uint32_t bfr[2];
                bfr[0] = Vs[(ks * 8 + t)     * 72 + ni * 8 + r];
                bfr[1] = Vs[(ks * 8 + t + 4) * 72 + ni * 8 + r];
                MMA_TF32(oacc[ni], ap, bfr);
            }
        }
    }

    lsum0 += __shfl_xor_sync(FULL, lsum0, 1);
    lsum0 += __shfl_xor_sync(FULL, lsum0, 2);
    lsum1 += __shfl_xor_sync(FULL, lsum1, 1);
    lsum1 += __shfl_xor_sync(FULL, lsum1, 2);
    const float inv0 = 1.0f / lsum0;
    const float inv1 = 1.0f / lsum1;

    __half* op0 = attn_out + ((size_t)b * T_SEQ + qrow0) * 256 + h * 64;
    __half* op1 = attn_out + ((size_t)b * T_SEQ + qrow1) * 256 + h * 64;
    #pragma unroll
    for (int ni = 0; ni < 8; ni++) {
        *(__half2*)(op0 + ni * 8 + 2 * t) = __floats2half2_rn(oacc[ni][0] * inv0, oacc[ni][1] * inv0);
        *(__half2*)(op1 + ni * 8 + 2 * t) = __floats2half2_rn(oacc[ni][2] * inv1, oacc[ni][3] * inv1);
    }
}

// ---------------------------------------------------------------------------
// LayerNorm, 2 rows/warp; optional fp16 shadow output.
// ---------------------------------------------------------------------------
__global__ void __launch_bounds__(256) ln_warp_kernel(
    const float* __restrict__ in, long ld_in,
    const float* __restrict__ gamma, const float* __restrict__ beta,
    float* __restrict__ out, long ld_out, int nrows,
    __half* __restrict__ out_h)
{
    const int wid = threadIdx.x >> 5, lane = threadIdx.x & 31;
    const int rowA = blockIdx.x * 16 + wid * 2;
    const int rowB = rowA + 1;
    if (rowA >= nrows) return;
    const bool hasB = (rowB < nrows);

    const float* ipA = in + (size_t)rowA * ld_in + lane * 8;
    const float* ipB = in + (size_t)(hasB ? rowB : rowA) * ld_in + lane * 8;
    float4 a0 = ((const float4*)ipA)[0];
    float4 a1 = ((const float4*)ipA)[1];
    float4 b0 = ((const float4*)ipB)[0];
    float4 b1 = ((const float4*)ipB)[1];

    float sA  = a0.x + a0.y + a0.z + a0.w + a1.x + a1.y + a1.z + a1.w;
    float qA  = a0.x*a0.x + a0.y*a0.y + a0.z*a0.z + a0.w*a0.w
              + a1.x*a1.x + a1.y*a1.y + a1.z*a1.z + a1.w*a1.w;
    float sB  = b0.x + b0.y + b0.z + b0.w + b1.x + b1.y + b1.z + b1.w;
    float qB  = b0.x*b0.x + b0.y*b0.y + b0.z*b0.z + b0.w*b0.w
              + b1.x*b1.x + b1.y*b1.y + b1.z*b1.z + b1.w*b1.w;
    #pragma unroll
    for (int o = 16; o > 0; o >>= 1) {
        sA += __shfl_xor_sync(0xffffffffu, sA, o);
        sB += __shfl_xor_sync(0xffffffffu, sB, o);
        qA += __shfl_xor_sync(0xffffffffu, qA, o);
        qB += __shfl_xor_sync(0xffffffffu, qB, o);
    }
    const float mA = sA * (1.0f / 256.0f);
    const float vA = qA * (1.0f / 256.0f) - mA * mA;
    const float rA = rsqrtf(vA + 1e-5f);
    const float mB = sB * (1.0f / 256.0f);
    const float vB = qB * (1.0f / 256.0f) - mB * mB;
    const float rB = rsqrtf(vB + 1e-5f);

    const float4 g0 = ((const float4*)(gamma + lane * 8))[0];
    const float4 g1 = ((const float4*)(gamma + lane * 8))[1];
    const float4 be0 = ((const float4*)(beta  + lane * 8))[0];
    const float4 be1 = ((const float4*)(beta  + lane * 8))[1];

    float4 o0, o1;
    o0.x = (a0.x - mA) * rA * g0.x + be0.x;
    o0.y = (a0.y - mA) * rA * g0.y + be0.y;
    o0.z = (a0.z - mA) * rA * g0.z + be0.z;
    o0.w = (a0.w - mA) * rA * g0.w + be0.w;
    o1.x = (a1.x - mA) * rA * g1.x + be1.x;
    o1.y = (a1.y - mA) * rA * g1.y + be1.y;
    o1.z = (a1.z - mA) * rA * g1.z + be1.z;
    o1.w = (a1.w - mA) * rA * g1.w + be1.w;
    float* opA = out + (size_t)rowA * ld_out + lane * 8;
    ((float4*)opA)[0] = o0;
    ((float4*)opA)[1] = o1;
    if (out_h) {
        __half2 hh[4];
        hh[0] = __floats2half2_rn(o0.x, o0.y);
        hh[1] = __floats2half2_rn(o0.z, o0.w);
        hh[2] = __floats2half2_rn(o1.x, o1.y);
        hh[3] = __floats2half2_rn(o1.z, o1.w);
        *(uint4*)(out_h + (size_t)rowA * ld_out + lane * 8) = *(uint4*)hh;
    }

    if (hasB) {
        float4 p0, p1;
        p0.x = (b0.x - mB) * rB * g0.x + be0.x;
        p0.y = (b0.y - mB) * rB * g0.y + be0.y;
        p0.z = (b0.z - mB) * rB * g0.z + be0.z;
        p0.w = (b0.w - mB) * rB * g0.w + be0.w;
        p1.x = (b1.x - mB) * rB * g1.x + be1.x;
        p1.y = (b1.y - mB) * rB * g1.y + be1.y;
        p1.z = (b1.z - mB) * rB * g1.z + be1.z;
        p1.w = (b1.w - mB) * rB * g1.w + be1.w;
        float* opB = out + (size_t)rowB * ld_out + lane * 8;
        ((float4*)opB)[0] = p0;
        ((float4*)opB)[1] = p1;
        if (out_h) {
            __half2 hh[4];
            hh[0] = __floats2half2_rn(p0.x, p0.y);
            hh[1] = __floats2half2_rn(p0.z, p0.w);
            hh[2] = __floats2half2_rn(p1.x, p1.y);
            hh[3] = __floats2half2_rn(p1.z, p1.w);
            *(uint4*)(out_h + (size_t)rowB * ld_out + lane * 8) = *(uint4*)hh;
        }
    }
}

// Depthwise causal conv -> comb_h[:, 256:512] (half)
__global__ void __launch_bounds__(256) conv_kernel(
    const float* __restrict__ x, const float* __restrict__ cw,
    const float* __restrict__ cb, __half* __restrict__ comb_h)
{
    const int idx = blockIdx.x * 256 + threadIdx.x;
    const int d = idx & 255;
    const int t = (idx >> 8) & 1023;
    const int b = idx >> 18;
    float r = cb[d];
    #pragma unroll
    for (int w = 0; w < 8; w++) {
        int tt = t - 7 + w;
        if (tt >= 0) r = fmaf(cw[d * 8 + w], x[((size_t)b * 1024 + tt) * 256 + d], r);
    }
    comb_h[((size_t)b * 1024 + t) * 768 + 256 + d] = __float2half_rn(r);
}

// EMA chunk-parallel -> comb_h[:, 512:768] (half) + trajectory (fp32)
__global__ void __launch_bounds__(256) ema_kernel(
    const float* __restrict__ x, __half* __restrict__ comb_h,
    float* __restrict__ traj_out)
{
    const int b = blockIdx.x, chunk = blockIdx.y, d = threadIdx.x;
    const int t0 = chunk * 128;
    int start = t0 - 256; if (start < 0) start = 0;
    const float* xp = x + (size_t)b * 1024 * 256 + d;
    float c = 0.0f;
    #pragma unroll 8
    for (int t = start; t < t0; t++)
        c = fmaf(0.9f, c, 0.1f * xp[(size_t)t * 256]);
    __half* op = comb_h + (size_t)b * 1024 * 768 + 512 + d;
    #pragma unroll 8
    for (int t = t0; t < t0 + 128; t++) {
        c = fmaf(0.9f, c, 0.1f * xp[(size_t)t * 256]);
        op[(size_t)t * 768] = __float2half_rn(c);
    }
    if (chunk == 7) traj_out[b * 256 + d] = c;
}

__global__ void __launch_bounds__(256) chunksum_kernel(
    const float* __restrict__ deltas, float* __restrict__ csum)
{
    const int b = blockIdx.x, chunk = blockIdx.y, d = threadIdx.x;
    const float* dp = deltas + ((size_t)b * 1024 + chunk * 128) * 256 + d;
    float s = 0.0f;
    #pragma unroll 8
    for (int t = 0; t < 128; t++) s += dp[(size_t)t * 256];
    csum[(b * 8 + chunk) * 256 + d] = s;
}

__global__ void __launch_bounds__(256) cumsum_kernel(
    const float* __restrict__ deltas, const float* __restrict__ seq,
    const float* __restrict__ csum, float* __restrict__ states)
{
    const int b = blockIdx.x, chunk = blockIdx.y, d = threadIdx.x;
    float c = seq[b * 256 + d];
    for (int cc = 0; cc < 8; cc++)
        if (cc < chunk) c = fmaf(0.5f, csum[(b * 8 + cc) * 256 + d], c);
    const float* dp = deltas + ((size_t)b * 1024 + chunk * 128) * 256 + d;
    float* sp = states + ((size_t)b * 1024 + chunk * 128) * 256 + d;
    #pragma unroll 8
    for (int t = 0; t < 128; t++) {
        c = fmaf(0.5f, dp[(size_t)t * 256], c);
        sp[(size_t)t * 256] = c;
    }
}

// ---------------------------------------------------------------------------
// Launch
// ---------------------------------------------------------------------------
extern "C" void kernel_launch(void* const* d_in, const int* in_sizes, int n_in,
                              void* d_out, int out_size)
{
    const float* x_in       = (const float*)d_in[0];
    const float* seq_state  = (const float*)d_in[1];
    const float* in_proj_w  = (const float*)d_in[3];
    const float* in_proj_b  = (const float*)d_in[4];
    const float* out_proj_w = (const float*)d_in[5];
    const float* out_proj_b = (const float*)d_in[6];
    const float* conv_w     = (const float*)d_in[7];
    const float* conv_b     = (const float*)d_in[8];
    const float* p2s_w      = (const float*)d_in[9];
    const float* p2s_b      = (const float*)d_in[10];
    const float* s2p_w      = (const float*)d_in[11];
    const float* s2p_b      = (const float*)d_in[12];
    const float* tw1        = (const float*)d_in[13];
    const float* tb1        = (const float*)d_in[14];
    const float* tw2        = (const float*)d_in[15];
    const float* tb2        = (const float*)d_in[16];
    const float* fw1        = (const float*)d_in[17];
    const float* fb1        = (const float*)d_in[18];
    const float* fw2        = (const float*)d_in[19];
    const float* fb2        = (const float*)d_in[20];
    const float* ln1s = (const float*)d_in[21];
    const float* ln1b = (const float*)d_in[22];
    const float* ln2s = (const float*)d_in[23];
    const float* ln2b = (const float*)d_in[24];
    const float* ln3s = (const float*)d_in[25];
    const float* ln3b = (const float*)d_in[26];
    const float* ln4s = (const float*)d_in[27];
    const float* ln4b = (const float*)d_in[28];
    float* out = (float*)d_out;

    float* scr = nullptr;
    cudaGetSymbolAddress((void**)&scr, d_scratch);
    float*  qkv      = scr + OFF_QKV;
    float*  tmp      = scr + OFF_TMP;
    float*  xb       = scr + OFF_X;
    float*  states   = scr + OFF_STATES;
    float*  deltas   = scr + OFF_DELTAS;
    float*  csum     = scr + OFF_CSUM;
    __half* xin_h    = (__half*)(scr + OFF_XIN_H);
    __half* attn_h   = (__half*)(scr + OFF_ATTN_H);
    __half* xb_h     = (__half*)(scr + OFF_XB_H);
    __half* comb_h   = (__half*)(scr + OFF_COMB_H);
    __half* hb_h     = (__half*)(scr + OFF_HB_H);
    __half* states_h = (__half*)(scr + OFF_STATES_H);
    __half* ffnin_h  = (__half*)(scr + OFF_FFNIN_H);
    __half* fbuf_h   = (__half*)(scr + OFF_FBUF_H);
    __half* w_h      = (__half*)(scr + OFF_WH);

    static bool attr_set = false;
    if (!attr_set) {
        cudaFuncSetAttribute(mma_gemm<0,false>, cudaFuncAttributeMaxDynamicSharedMemorySize, GEMM_SMEM);
        cudaFuncSetAttribute(mma_gemm<1,false>, cudaFuncAttributeMaxDynamicSharedMemorySize, GEMM_SMEM);
        cudaFuncSetAttribute(mma_gemm<2,true>,  cudaFuncAttributeMaxDynamicSharedMemorySize, GEMM_SMEM);
        cudaFuncSetAttribute(mma_gemm<3,true>,  cudaFuncAttributeMaxDynamicSharedMemorySize, GEMM_SMEM);
        cudaFuncSetAttribute(mma_gemm<0,true>,  cudaFuncAttributeMaxDynamicSharedMemorySize, GEMM_SMEM);
        cudaFuncSetAttribute(attn_mma_kernel, cudaFuncAttributeMaxDynamicSharedMemorySize, ATTN_SMEM);
        attr_set = true;
    }

    // 0. convert x_in + all weights to fp16
    cvt_all_kernel<<<1728, 256>>>(x_in, in_proj_w, out_proj_w, p2s_w, s2p_w,
                                  tw1, tw2, fw1, fw2, xin_h, w_h);

    // 1. qkv = x @ in_proj_w^T + b   (fp32 out, attention consumes)
    mma_gemm<0,false><<<dim3(6, 64), 256, GEMM_SMEM>>>(xin_h, 256, w_h + WH_IP, in_proj_b,
                                                       nullptr, 0, qkv, 768, 256);
    // 2. causal attention -> attn_h (fp16)
    attn_mma_kernel<<<dim3(8, 32), 256, ATTN_SMEM>>>(qkv, attn_h);
    // 3. out_proj + residual(x_in) -> tmp fp32
    mma_gemm<1,false><<<dim3(2, 64), 256, GEMM_SMEM>>>(attn_h, 256, w_h + WH_OP, out_proj_b,
                                                       x_in, 256, tmp, 256, 256);
    // 4. x = LN1(tmp) -> xb fp32 + xb_h
    ln_warp_kernel<<<512, 256>>>(tmp, 256, ln1s, ln1b, xb, 256, 8192, xb_h);
    // 5. conv -> comb_h[:,256:512]
    conv_kernel<<<8192, 256>>>(xb, conv_w, conv_b, comb_h);
    // 6. EMA -> comb_h[:,512:768] + trajectory
    ema_kernel<<<dim3(8, 8), 256>>>(xb, comb_h, out + (size_t)M_ROWS * 256 + 2048);
    // 7. comb_h[:,0:256] = x + 0.3*(x @ p2s^T + b)
    mma_gemm<3,true><<<dim3(2, 64), 256, GEMM_SMEM>>>(xb_h, 256, w_h + WH_P2S, p2s_b,
                                                      xb, 256, comb_h, 768, 256);
    // 8. h = gelu(comb @ tw1^T + b1) -> hb_h
    mma_gemm<2,true><<<dim3(4, 64), 256, GEMM_SMEM>>>(comb_h, 768, w_h + WH_TW1, tb1,
                                                      nullptr, 0, hb_h, 512, 768);
    // 9. deltas = h @ tw2^T + b2  (fp32, feeds cumsum)
    mma_gemm<0,false><<<dim3(2, 64), 256, GEMM_SMEM>>>(hb_h, 512, w_h + WH_TW2, tb2,
                                                       nullptr, 0, deltas, 256, 512);
    // 10. states = seq + 0.5*cumsum(deltas)
    chunksum_kernel<<<dim3(8, 8), 256>>>(deltas, csum);
    cumsum_kernel<<<dim3(8, 8), 256>>>(deltas, seq_state, csum, states);
    // 11. states = LN3(states) -> fp32 (for LN4) + states_h
    ln_warp_kernel<<<512, 256>>>(states, 256, ln3s, ln3b, states, 256, 8192, states_h);
    // 12. ffn_in = x + 0.3*(states @ s2p^T + b) -> ffnin_h
    mma_gemm<3,true><<<dim3(2, 64), 256, GEMM_SMEM>>>(states_h, 256, w_h + WH_S2P, s2p_b,
                                                      xb, 256, ffnin_h, 256, 256);
    // 13. f = gelu(ffn_in @ fw1^T + b1) -> fbuf_h
    mma_gemm<2,true><<<dim3(8, 64), 256, GEMM_SMEM>>>(ffnin_h, 256, w_h + WH_FW1, fb1,
                                                      nullptr, 0, fbuf_h, 1024, 256);
    // 14. tmp = x + f @ fw2^T + b2  (fp32)
    mma_gemm<1,false><<<dim3(2, 64), 256, GEMM_SMEM>>>(fbuf_h, 1024, w_h + WH_FW2, fb2,
                                                       xb, 256, tmp, 256, 1024);
    // 15. LN2 -> out (fp32)
    ln_warp_kernel<<<512, 256>>>(tmp, 256, ln2s, ln2b, out, 256, 8192, nullptr);
    // 16. LN4(states[:, -1, :])
    ln_warp_kernel<<<1, 256>>>(states + (size_t)1023 * 256, (long)1024 * 256,
                               ln4s, ln4b, out + (size_t)M_ROWS * 256, 256, 8, nullptr);
}

// round 12
// speedup vs baseline: 1.5269x; 1.0512x over previous
#include <cuda_runtime.h>
#include <cuda_fp16.h>
#include <math.h>
#include <stdint.h>

#define B_SZ   8
#define T_SEQ  1024
#define D_MOD  256
#define M_ROWS (B_SZ * T_SEQ)   // 8192

// ---------------------------------------------------------------------------
// Scratch layout (float units)
// ---------------------------------------------------------------------------
#define OFF_TMP      0ul          // [8192,256] fp32
#define OFF_X        2097152ul    // [8192,256] fp32
#define OFF_STATES   4194304ul    // [8192,256] fp32
#define OFF_DELTAS   6291456ul    // [8192,256] fp32
#define OFF_CSUM     8388608ul    // [64,256]   fp32
#define OFF_QKV_H    8404992ul    // [8192,768] half
#define OFF_XIN_H    11550720ul   // [8192,256] half
#define OFF_ATTN_H   12599296ul   // [8192,256] half
#define OFF_XB_H     13647872ul   // [8192,256] half
#define OFF_COMB_H   14696448ul   // [8192,768] half
#define OFF_HB_H     17842176ul   // [8192,512] half
#define OFF_STATES_H 19939328ul   // [8192,256] half
#define OFF_FFNIN_H  20987904ul   // [8192,256] half
#define OFF_FBUF_H   22036480ul   // [8192,1024] half
#define OFF_WH       26230784ul   // all weights, half
#define SCRATCH_TOTAL 26853376ul

// weight offsets within W_H (half units)
#define WH_IP   0
#define WH_OP   196608
#define WH_P2S  262144
#define WH_S2P  327680
#define WH_TW1  393216
#define WH_TW2  786432
#define WH_FW1  917504
#define WH_FW2  1179648

__device__ float d_scratch[SCRATCH_TOTAL];

__device__ __forceinline__ float gelu_f(float x) {
    return 0.5f * x * (1.0f + erff(x * 0.70710678118654752f));
}

#define MMA_F16(d, a, b) \
    asm volatile("mma.sync.aligned.m16n8k16.row.col.f32.f16.f16.f32 " \
                 "{%0,%1,%2,%3}, {%4,%5,%6,%7}, {%8,%9}, {%0,%1,%2,%3};" \
                 : "+f"(d[0]), "+f"(d[1]), "+f"(d[2]), "+f"(d[3]) \
                 : "r"(a[0]), "r"(a[1]), "r"(a[2]), "r"(a[3]), \
                   "r"(b[0]), "r"(b[1]))

// Fast exp(s/8): FMA-pipe only, no MUFU.
__device__ __forceinline__ float fexp_s8(float s) {
    const float y = s * 0.1803368801111244f;
    const float rnd = y + 12582912.0f;
    const int   i   = __float_as_int(rnd);
    const float nf  = rnd - 12582912.0f;
    const float f   = y - nf;
    float p = 1.3333558146e-3f;
    p = fmaf(p, f, 9.6181291076e-3f);
    p = fmaf(p, f, 5.5504108665e-2f);
    p = fmaf(p, f, 2.4022650696e-1f);
    p = fmaf(p, f, 6.9314718056e-1f);
    p = fmaf(p, f, 1.0f);
    const float scale = __int_as_float((i << 23) + 0x3f800000);
    return p * scale;
}

__device__ __forceinline__ uint32_t h2u(__half2 v) {
    return *(uint32_t*)&v;
}

// ---------------------------------------------------------------------------
// fp32 -> fp16 bulk conversion (unchanged from R11).
// ---------------------------------------------------------------------------
__global__ void __launch_bounds__(256) cvt_all_kernel(
    const float* __restrict__ xin,
    const float* __restrict__ w_ip, const float* __restrict__ w_op,
    const float* __restrict__ w_p2s, const float* __restrict__ w_s2p,
    const float* __restrict__ w_tw1, const float* __restrict__ w_tw2,
    const float* __restrict__ w_fw1, const float* __restrict__ w_fw2,
    __half* __restrict__ xin_h, __half* __restrict__ w_h)
{
    const size_t e = ((size_t)blockIdx.x * 256 + threadIdx.x) * 8;
    const float* src; __half* dst;
    if      (e < 2097152ul) { src = xin   + e;             dst = xin_h + e; }
    else if (e < 2293760ul) { src = w_ip  + (e - 2097152); dst = w_h + WH_IP  + (e - 2097152); }
    else if (e < 2359296ul) { src = w_op  + (e - 2293760); dst = w_h + WH_OP  + (e - 2293760); }
    else if (e < 2424832ul) { src = w_p2s + (e - 2359296); dst = w_h + WH_P2S + (e - 2359296); }
    else if (e < 2490368ul) { src = w_s2p + (e - 2424832); dst = w_h + WH_S2P + (e - 2424832); }
    else if (e < 2883584ul) { src = w_tw1 + (e - 2490368); dst = w_h + WH_TW1 + (e - 2490368); }
    else if (e < 3014656ul) { src = w_tw2 + (e - 2883584); dst = w_h + WH_TW2 + (e - 2883584); }
    else if (e < 3276800ul) { src = w_fw1 + (e - 3014656); dst = w_h + WH_FW1 + (e - 3014656); }
    else                    { src = w_fw2 + (e - 3276800); dst = w_h + WH_FW2 + (e - 3276800); }
    float4 f0 = ((const float4*)src)[0];
    float4 f1 = ((const float4*)src)[1];
    __half2 h[4];
    h[0] = __floats2half2_rn(f0.x, f0.y);
    h[1] = __floats2half2_rn(f0.z, f0.w);
    h[2] = __floats2half2_rn(f1.x, f1.y);
    h[3] = __floats2half2_rn(f1.z, f1.w);
    *(uint4*)dst = *(uint4*)h;
}

// ---------------------------------------------------------------------------
// FP16 GEMM, templated BM in {128, 64}. BM=64 -> grid 256 for N=256 layers.
// C[M,N] = epi( A[M,K] @ W[N,K]^T + bias[N] ), fp32 accumulate.
// 3-stage cp.async, one syncthreads per k-tile, BN=128, BK=32 halves.
// ---------------------------------------------------------------------------
#define ISSUE_TILE(k0, sidx)                                                   \
    {                                                                          \
        _Pragma("unroll")                                                      \
        for (int i = 0; i < BM / 64; i++) {                                    \
            int idx = tid + i * 256;                                           \
            int row = idx >> 2;                                                \
            int ch  = idx & 3;                                                 \
            uint32_t da = smem_base + (uint32_t)(((sidx) * STAGE + row * 36 + ch * 4) * 4); \
            const __half* ga = A + (size_t)(bm + row) * lda + (k0) + ch * 8;   \
            asm volatile("cp.async.cg.shared.global [%0], [%1], 16;" :: "r"(da), "l"(ga)); \
        }                                                                      \
        _Pragma("unroll")                                                      \
        for (int i = 0; i < 2; i++) {                                          \
            int idx = tid + i * 256;                                           \
            int row = idx >> 2;                                                \
            int ch  = idx & 3;                                                 \
            uint32_t db = smem_base + (uint32_t)(((sidx) * STAGE + A_TS + row * 36 + ch * 4) * 4); \
            const __half* gw = W + (size_t)(bn + row) * (size_t)K + (k0) + ch * 8; \
            asm volatile("cp.async.cg.shared.global [%0], [%1], 16;" :: "r"(db), "l"(gw)); \
        }                                                                      \
        asm volatile("cp.async.commit_group;");                                \
    }

template<int EPI, bool OUTH, int BM>
__global__ void __launch_bounds__(256, 2) mma_gemm(
    const __half* __restrict__ A, int lda,
    const __half* __restrict__ W,
    const float* __restrict__ bias,
    const float* __restrict__ addend, int ld_add,
    void* __restrict__ Cv, int ldc,
    int K)
{
    constexpr int MI    = BM / 32;       // m16 tiles per warp
    constexpr int A_TS  = BM * 36;       // half2 units
    constexpr int STAGE = A_TS + 128 * 36;

    extern __shared__ uint32_t sm[];
    const uint32_t smem_base = (uint32_t)__cvta_generic_to_shared(sm);

    const int tid  = threadIdx.x;
    const int bm   = blockIdx.y * BM;
    const int bn   = blockIdx.x * 128;
    const int wid  = tid >> 5;
    const int lane = tid & 31;
    const int wm   = (wid & 1) * (BM / 2);
    const int wn32 = (wid >> 1) * 32;
    const int r    = lane >> 2;
    const int t    = lane & 3;

    float acc[MI][4][4];
    #pragma unroll
    for (int mi = 0; mi < MI; mi++)
        #pragma unroll
        for (int ni = 0; ni < 4; ni++)
            #pragma unroll
            for (int c = 0; c < 4; c++) acc[mi][ni][c] = 0.0f;

    const int ntiles = K >> 5;

    ISSUE_TILE(0, 0);
    ISSUE_TILE(32, 1);

    int sidx = 0;
    for (int kt = 0; kt < ntiles; kt++) {
        if (kt == ntiles - 1) {
            asm volatile("cp.async.wait_group 0;");
        } else {
            asm volatile("cp.async.wait_group 1;");
        }
        __syncthreads();

        if (kt + 2 < ntiles) {
            int ws = sidx + 2; if (ws >= 3) ws -= 3;
            ISSUE_TILE((kt + 2) * 32, ws);
        }

        const uint32_t* Ab = sm + sidx * STAGE;
        const uint32_t* Bb = Ab + A_TS;

        #pragma unroll
        for (int ks = 0; ks < 2; ks++) {
            const int kb = ks * 8;
            uint32_t a[MI][4], b[4][2];
            #pragma unroll
            for (int mi = 0; mi < MI; mi++) {
                int idx = (wm + mi * 16 + r) * 36 + kb + t;
                a[mi][0] = Ab[idx];
                a[mi][1] = Ab[idx + 8 * 36];
                a[mi][2] = Ab[idx + 4];
                a[mi][3] = Ab[idx + 8 * 36 + 4];
            }
            #pragma unroll
            for (int ni = 0; ni < 4; ni++) {
                int idx = (wn32 + ni * 8 + r) * 36 + kb + t;
                b[ni][0] = Bb[idx];
                b[ni][1] = Bb[idx + 4];
            }
            #pragma unroll
            for (int mi = 0; mi < MI; mi++)
                #pragma unroll
                for (int ni = 0; ni < 4; ni++)
                    MMA_F16(acc[mi][ni], a[mi], b[ni]);
        }
        sidx++; if (sidx == 3) sidx = 0;
    }

    float* Cf = (float*)Cv;
    __half* Ch = (__half*)Cv;

    #pragma unroll
    for (int mi = 0; mi < MI; mi++) {
        const int row0 = bm + wm + mi * 16 + r;
        const int row1 = row0 + 8;
        #pragma unroll
        for (int ni = 0; ni < 4; ni++) {
            const int col = bn + wn32 + ni * 8 + 2 * t;
            const float2 bb = *(const float2*)(bias + col);
            float v00 = acc[mi][ni][0] + bb.x;
            float v01 = acc[mi][ni][1] + bb.y;
            float v10 = acc[mi][ni][2] + bb.x;
            float v11 = acc[mi][ni][3] + bb.y;
            if (EPI == 1) {
                const float2 r0 = *(const float2*)(addend + (size_t)row0 * ld_add + col);
                const float2 r1 = *(const float2*)(addend + (size_t)row1 * ld_add + col);
                v00 += r0.x; v01 += r0.y; v10 += r1.x; v11 += r1.y;
            }
            if (EPI == 2) {
                v00 = gelu_f(v00); v01 = gelu_f(v01);
                v10 = gelu_f(v10); v11 = gelu_f(v11);
            }
            if (EPI == 3) {
                const float2 r0 = *(const float2*)(addend + (size_t)row0 * ld_add + col);
                const float2 r1 = *(const float2*)(addend + (size_t)row1 * ld_add + col);
                v00 = r0.x + 0.3f * v00; v01 = r0.y + 0.3f * v01;
                v10 = r1.x + 0.3f * v10; v11 = r1.y + 0.3f * v11;
            }
            if (OUTH) {
                *(__half2*)(Ch + (size_t)row0 * ldc + col) = __floats2half2_rn(v00, v01);
                *(__half2*)(Ch + (size_t)row1 * ldc + col) = __floats2half2_rn(v10, v11);
            } else {
                *(float2*)(Cf + (size_t)row0 * ldc + col) = make_float2(v00, v01);
                *(float2*)(Cf + (size_t)row1 * ldc + col) = make_float2(v10, v11);
            }
        }
    }
}

#define GEMM_SMEM_128 (3 * (128 + 128) * 36 * 4)   // 110592 B
#define GEMM_SMEM_64  (3 * (64 + 128) * 36 * 4)    // 82944 B

// ---------------------------------------------------------------------------
// FP16 mma causal flash-attention: qkv in half; K/V staged raw (stride 72
// halves, conflict-free), S via m16n8k16, P fragments ARE the S accumulator
// layout (no shuffles), PV B-frags via paired LDS.U16. cp.async double-
// buffered, heavy-first remap. Output half.
// ---------------------------------------------------------------------------
#define KV_STG_U32 4608                    // per stage: K 2304 + V 2304 u32
#define ATTN_SMEM (2 * KV_STG_U32 * 4)     // 36864 B

#define AT_ISSUE(jt, s)                                                        \
    {                                                                          \
        const int _j0 = (jt) * 64;                                             \
        _Pragma("unroll")                                                      \
        for (int _i = 0; _i < 2; _i++) {                                       \
            int _idx = tid + _i * 256;                                         \
            int _row = _idx >> 3;                                              \
            int _ch  = _idx & 7;                                               \
            const __half* _kp = baseh + (size_t)(_j0 + _row) * 768 + 256 + h * 64 + _ch * 8; \
            uint32_t _dk = smem_base + (uint32_t)(((s) * KV_STG_U32 + _row * 36 + _ch * 4) * 4); \
            asm volatile("cp.async.cg.shared.global [%0], [%1], 16;" :: "r"(_dk), "l"(_kp)); \
            uint32_t _dv = smem_base + (uint32_t)(((s) * KV_STG_U32 + 2304 + _row * 36 + _ch * 4) * 4); \
            asm volatile("cp.async.cg.shared.global [%0], [%1], 16;" :: "r"(_dv), "l"(_kp + 256)); \
        }                                                                      \
        asm volatile("cp.async.commit_group;");                                \
    }

__global__ void __launch_bounds__(256) attn_mma_kernel(
    const __half* __restrict__ qkvh, __half* __restrict__ attn_out)
{
    extern __shared__ uint32_t dsm[];
    const uint32_t smem_base = (uint32_t)__cvta_generic_to_shared(dsm);

    const int bh = blockIdx.y;
    const int b  = bh >> 2;
    const int h  = bh & 3;
    const int qx = gridDim.x - 1 - blockIdx.x;   // heavy-first
    const int qbase = qx * 128;
    const int tid  = threadIdx.x;
    const int wid  = tid >> 5;
    const int lane = tid & 31;
    const int r    = lane >> 2;
    const int t    = lane & 3;
    const __half* baseh = qkvh + (size_t)b * T_SEQ * 768;

    const int qrow0 = qbase + wid * 16 + r;
    const int qrow1 = qrow0 + 8;

    // Q fragments (fp16, loaded once from gmem)
    uint32_t aq[4][4];
    {
        const __half* q0 = baseh + (size_t)qrow0 * 768 + h * 64;
        const __half* q1 = baseh + (size_t)qrow1 * 768 + h * 64;
        #pragma unroll
        for (int ks = 0; ks < 4; ks++) {
            aq[ks][0] = *(const uint32_t*)(q0 + ks * 16 + 2 * t);
            aq[ks][1] = *(const uint32_t*)(q1 + ks * 16 + 2 * t);
            aq[ks][2] = *(const uint32_t*)(q0 + ks * 16 + 8 + 2 * t);
            aq[ks][3] = *(const uint32_t*)(q1 + ks * 16 + 8 + 2 * t);
        }
    }

    float oacc[8][4];
    #pragma unroll
    for (int ni = 0; ni < 8; ni++)
        #pragma unroll
        for (int c = 0; c < 4; c++) oacc[ni][c] = 0.0f;
    float lsum0 = 0.0f, lsum1 = 0.0f;

    const int ntiles   = 2 * qx + 2;
    const int wrow_max = qbase + wid * 16 + 15;
    const unsigned FULL = 0xffffffffu;

    AT_ISSUE(0, 0);

    for (int jt = 0; jt < ntiles; jt++) {
        const int j0 = jt * 64;
        asm volatile("cp.async.wait_group 0;");
        __syncthreads();

        if (jt + 1 < ntiles) AT_ISSUE(jt + 1, (jt + 1) & 1);

        if (j0 > wrow_max) continue;

        const uint32_t* Ks32 = dsm + (jt & 1) * KV_STG_U32;
        const __half*   Vh   = (const __half*)(Ks32 + 2304);

        // S = Q @ K^T  (16 x 64 per warp), fp16 mma
        float sc[8][4];
        #pragma unroll
        for (int ni = 0; ni < 8; ni++)
            #pragma unroll
            for (int c = 0; c < 4; c++) sc[ni][c] = 0.0f;
        #pragma unroll
        for (int ks = 0; ks < 4; ks++) {
            #pragma unroll
            for (int ni = 0; ni < 8; ni++) {
                uint32_t bfr[2];
                const int key = ni * 8 + r;
                bfr[0] = Ks32[key * 36 + ks * 8 + t];
                bfr[1] = Ks32[key * 36 + ks * 8 + t + 4];
                MMA_F16(sc[ni], aq[ks], bfr);
            }
        }

        // P = exp(S/8) with causal mask; accumulate row sums
        #pragma unroll
        for (int ni = 0; ni < 8; ni++) {
            const int col0 = j0 + ni * 8 + 2 * t;
            float p0 = (col0     <= qrow0) ? fexp_s8(sc[ni][0]) : 0.0f;
            float p1 = (col0 + 1 <= qrow0) ? fexp_s8(sc[ni][1]) : 0.0f;
            float p2 = (col0     <= qrow1) ? fexp_s8(sc[ni][2]) : 0.0f;
            float p3 = (col0 + 1 <= qrow1) ? fexp_s8(sc[ni][3]) : 0.0f;
            lsum0 += p0 + p1;
            lsum1 += p2 + p3;
            sc[ni][0] = p0; sc[ni][1] = p1; sc[ni][2] = p2; sc[ni][3] = p3;
        }

        // O += P @ V : P fragments = S accumulator layout (no shuffles)
        #pragma unroll
        for (int c = 0; c < 4; c++) {
            uint32_t ap[4];
            ap[0] = h2u(__floats2half2_rn(sc[2*c][0],   sc[2*c][1]));
            ap[1] = h2u(__floats2half2_rn(sc[2*c][2],   sc[2*c][3]));
            ap[2] = h2u(__floats2half2_rn(sc[2*c+1][0], sc[2*c+1][1]));
            ap[3] = h2u(__floats2half2_rn(sc[2*c+1][2], sc[2*c+1][3]));
            const __half* vp = Vh + (c * 16 + 2 * t) * 72;
            #pragma unroll
            for (int ni = 0; ni < 8; ni++) {
                const int n = ni * 8 + r;
                uint32_t bfr[2];
                bfr[0] = h2u(__halves2half2(vp[n],          vp[n + 72]));
                bfr[1] = h2u(__halves2half2(vp[n + 8 * 72], vp[n + 9 * 72]));
                MMA_F16(oacc[ni], ap, bfr);
            }
        }
    }

    lsum0 += __shfl_xor_sync(FULL, lsum0, 1);
    lsum0 += __shfl_xor_sync(FULL, lsum0, 2);
    lsum1 += __shfl_xor_sync(FULL, lsum1, 1);
    lsum1 += __shfl_xor_sync(FULL, lsum1, 2);
    const float inv0 = 1.0f / lsum0;
    const float inv1 = 1.0f / lsum1;

    __half* op0 = attn_out + ((size_t)b * T_SEQ + qrow0) * 256 + h * 64;
    __half* op1 = attn_out + ((size_t)b * T_SEQ + qrow1) * 256 + h * 64;
    #pragma unroll
    for (int ni = 0; ni < 8; ni++) {
        *(__half2*)(op0 + ni * 8 + 2 * t) = __floats2half2_rn(oacc[ni][0] * inv0, oacc[ni][1] * inv0);
        *(__half2*)(op1 + ni * 8 + 2 * t) = __floats2half2_rn(oacc[ni][2] * inv1, oacc[ni][3] * inv1);
    }
}

// ---------------------------------------------------------------------------
// LayerNorm, 2 rows/warp; optional fp16 shadow output (unchanged).
// ---------------------------------------------------------------------------
__global__ void __launch_bounds__(256) ln_warp_kernel(
    const float* __restrict__ in, long ld_in,
    const float* __restrict__ gamma, const float* __restrict__ beta,
    float* __restrict__ out, long ld_out, int nrows,
    __half* __restrict__ out_h)
{
    const int wid = threadIdx.x >> 5, lane = threadIdx.x & 31;
    const int rowA = blockIdx.x * 16 + wid * 2;
    const int rowB = rowA + 1;
    if (rowA >= nrows) return;
    const bool hasB = (rowB < nrows);

    const float* ipA = in + (size_t)rowA * ld_in + lane * 8;
    const float* ipB = in + (size_t)(hasB ? rowB : rowA) * ld_in + lane * 8;
    float4 a0 = ((const float4*)ipA)[0];
    float4 a1 = ((const float4*)ipA)[1];
    float4 b0 = ((const float4*)ipB)[0];
    float4 b1 = ((const float4*)ipB)[1];

    float sA  = a0.x + a0.y + a0.z + a0.w + a1.x + a1.y + a1.z + a1.w;
    float qA  = a0.x*a0.x + a0.y*a0.y + a0.z*a0.z + a0.w*a0.w
              + a1.x*a1.x + a1.y*a1.y + a1.z*a1.z + a1.w*a1.w;
    float sB  = b0.x + b0.y + b0.z + b0.w + b1.x + b1.y + b1.z + b1.w;
    float qB  = b0.x*b0.x + b0.y*b0.y + b0.z*b0.z + b0.w*b0.w
              + b1.x*b1.x + b1.y*b1.y + b1.z*b1.z + b1.w*b1.w;
    #pragma unroll
    for (int o = 16; o > 0; o >>= 1) {
        sA += __shfl_xor_sync(0xffffffffu, sA, o);
        sB += __shfl_xor_sync(0xffffffffu, sB, o);
        qA += __shfl_xor_sync(0xffffffffu, qA, o);
        qB += __shfl_xor_sync(0xffffffffu, qB, o);
    }
    const float mA = sA * (1.0f / 256.0f);
    const float vA = qA * (1.0f / 256.0f) - mA * mA;
    const float rA = rsqrtf(vA + 1e-5f);
    const float mB = sB * (1.0f / 256.0f);
    const float vB = qB * (1.0f / 256.0f) - mB * mB;
    const float rB = rsqrtf(vB + 1e-5f);

    const float4 g0 = ((const float4*)(gamma + lane * 8))[0];
    const float4 g1 = ((const float4*)(gamma + lane * 8))[1];
    const float4 be0 = ((const float4*)(beta  + lane * 8))[0];
    const float4 be1 = ((const float4*)(beta  + lane * 8))[1];

    float4 o0, o1;
    o0.x = (a0.x - mA) * rA * g0.x + be0.x;
    o0.y = (a0.y - mA) * rA * g0.y + be0.y;
    o0.z = (a0.z - mA) * rA * g0.z + be0.z;
    o0.w = (a0.w - mA) * rA * g0.w + be0.w;
    o1.x = (a1.x - mA) * rA * g1.x + be1.x;
    o1.y = (a1.y - mA) * rA * g1.y + be1.y;
    o1.z = (a1.z - mA) * rA * g1.z + be1.z;
    o1.w = (a1.w - mA) * rA * g1.w + be1.w;
    float* opA = out + (size_t)rowA * ld_out + lane * 8;
    ((float4*)opA)[0] = o0;
    ((float4*)opA)[1] = o1;
    if (out_h) {
        __half2 hh[4];
        hh[0] = __floats2half2_rn(o0.x, o0.y);
        hh[1] = __floats2half2_rn(o0.z, o0.w);
        hh[2] = __floats2half2_rn(o1.x, o1.y);
        hh[3] = __floats2half2_rn(o1.z, o1.w);
        *(uint4*)(out_h + (size_t)rowA * ld_out + lane * 8) = *(uint4*)hh;
    }

    if (hasB) {
        float4 p0, p1;
        p0.x = (b0.x - mB) * rB * g0.x + be0.x;
        p0.y = (b0.y - mB) * rB * g0.y + be0.y;
        p0.z = (b0.z - mB) * rB * g0.z + be0.z;
        p0.w = (b0.w - mB) * rB * g0.w + be0.w;
        p1.x = (b1.x - mB) * rB * g1.x + be1.x;
        p1.y = (b1.y - mB) * rB * g1.y + be1.y;
        p1.z = (b1.z - mB) * rB * g1.z + be1.z;
        p1.w = (b1.w - mB) * rB * g1.w + be1.w;
        float* opB = out + (size_t)rowB * ld_out + lane * 8;
        ((float4*)opB)[0] = p0;
        ((float4*)opB)[1] = p1;
        if (out_h) {
            __half2 hh[4];
            hh[0] = __floats2half2_rn(p0.x, p0.y);
            hh[1] = __floats2half2_rn(p0.z, p0.w);
            hh[2] = __floats2half2_rn(p1.x, p1.y);
            hh[3] = __floats2half2_rn(p1.z, p1.w);
            *(uint4*)(out_h + (size_t)rowB * ld_out + lane * 8) = *(uint4*)hh;
        }
    }
}

// Depthwise causal conv -> comb_h[:, 256:512] (half)
__global__ void __launch_bounds__(256) conv_kernel(
    const float* __restrict__ x, const float* __restrict__ cw,
    const float* __restrict__ cb, __half* __restrict__ comb_h)
{
    const int idx = blockIdx.x * 256 + threadIdx.x;
    const int d = idx & 255;
    const int t = (idx >> 8) & 1023;
    const int b = idx >> 18;
    float r = cb[d];
    #pragma unroll
    for (int w = 0; w < 8; w++) {
        int tt = t - 7 + w;
        if (tt >= 0) r = fmaf(cw[d * 8 + w], x[((size_t)b * 1024 + tt) * 256 + d], r);
    }
    comb_h[((size_t)b * 1024 + t) * 768 + 256 + d] = __float2half_rn(r);
}

// EMA chunk-parallel -> comb_h[:, 512:768] (half) + trajectory (fp32)
__global__ void __launch_bounds__(256) ema_kernel(
    const float* __restrict__ x, __half* __restrict__ comb_h,
    float* __restrict__ traj_out)
{
    const int b = blockIdx.x, chunk = blockIdx.y, d = threadIdx.x;
    const int t0 = chunk * 128;
    int start = t0 - 256; if (start < 0) start = 0;
    const float* xp = x + (size_t)b * 1024 * 256 + d;
    float c = 0.0f;
    #pragma unroll 8
    for (int t = start; t < t0; t++)
        c = fmaf(0.9f, c, 0.1f * xp[(size_t)t * 256]);
    __half* op = comb_h + (size_t)b * 1024 * 768 + 512 + d;
    #pragma unroll 8
    for (int t = t0; t < t0 + 128; t++) {
        c = fmaf(0.9f, c, 0.1f * xp[(size_t)t * 256]);
        op[(size_t)t * 768] = __float2half_rn(c);
    }
    if (chunk == 7) traj_out[b * 256 + d] = c;
}

__global__ void __launch_bounds__(256) chunksum_kernel(
    const float* __restrict__ deltas, float* __restrict__ csum)
{
    const int b = blockIdx.x, chunk = blockIdx.y, d = threadIdx.x;
    const float* dp = deltas + ((size_t)b * 1024 + chunk * 128) * 256 + d;
    float s = 0.0f;
    #pragma unroll 8
    for (int t = 0; t < 128; t++) s += dp[(size_t)t * 256];
    csum[(b * 8 + chunk) * 256 + d] = s;
}

__global__ void __launch_bounds__(256) cumsum_kernel(
    const float* __restrict__ deltas, const float* __restrict__ seq,
    const float* __restrict__ csum, float* __restrict__ states)
{
    const int b = blockIdx.x, chunk = blockIdx.y, d = threadIdx.x;
    float c = seq[b * 256 + d];
    for (int cc = 0; cc < 8; cc++)
        if (cc < chunk) c = fmaf(0.5f, csum[(b * 8 + cc) * 256 + d], c);
    const float* dp = deltas + ((size_t)b * 1024 + chunk * 128) * 256 + d;
    float* sp = states + ((size_t)b * 1024 + chunk * 128) * 256 + d;
    #pragma unroll 8
    for (int t = 0; t < 128; t++) {
        c = fmaf(0.5f, dp[(size_t)t * 256], c);
        sp[(size_t)t * 256] = c;
    }
}

// ---------------------------------------------------------------------------
// Launch
// ---------------------------------------------------------------------------
extern "C" void kernel_launch(void* const* d_in, const int* in_sizes, int n_in,
                              void* d_out, int out_size)
{
    const float* x_in       = (const float*)d_in[0];
    const float* seq_state  = (const float*)d_in[1];
    const float* in_proj_w  = (const float*)d_in[3];
    const float* in_proj_b  = (const float*)d_in[4];
    const float* out_proj_w = (const float*)d_in[5];
    const float* out_proj_b = (const float*)d_in[6];
    const float* conv_w     = (const float*)d_in[7];
    const float* conv_b     = (const float*)d_in[8];
    const float* p2s_w      = (const float*)d_in[9];
    const float* p2s_b      = (const float*)d_in[10];
    const float* s2p_w      = (const float*)d_in[11];
    const float* s2p_b      = (const float*)d_in[12];
    const float* tw1        = (const float*)d_in[13];
    const float* tb1        = (const float*)d_in[14];
    const float* tw2        = (const float*)d_in[15];
    const float* tb2        = (const float*)d_in[16];
    const float* fw1        = (const float*)d_in[17];
    const float* fb1        = (const float*)d_in[18];
    const float* fw2        = (const float*)d_in[19];
    const float* fb2        = (const float*)d_in[20];
    const float* ln1s = (const float*)d_in[21];
    const float* ln1b = (const float*)d_in[22];
    const float* ln2s = (const float*)d_in[23];
    const float* ln2b = (const float*)d_in[24];
    const float* ln3s = (const float*)d_in[25];
    const float* ln3b = (const float*)d_in[26];
    const float* ln4s = (const float*)d_in[27];
    const float* ln4b = (const float*)d_in[28];
    float* out = (float*)d_out;

    float* scr = nullptr;
    cudaGetSymbolAddress((void**)&scr, d_scratch);
    float*  tmp      = scr + OFF_TMP;
    float*  xb       = scr + OFF_X;
    float*  states   = scr + OFF_STATES;
    float*  deltas   = scr + OFF_DELTAS;
    float*  csum     = scr + OFF_CSUM;
    __half* qkv_h    = (__half*)(scr + OFF_QKV_H);
    __half* xin_h    = (__half*)(scr + OFF_XIN_H);
    __half* attn_h   = (__half*)(scr + OFF_ATTN_H);
    __half* xb_h     = (__half*)(scr + OFF_XB_H);
    __half* comb_h   = (__half*)(scr + OFF_COMB_H);
    __half* hb_h     = (__half*)(scr + OFF_HB_H);
    __half* states_h = (__half*)(scr + OFF_STATES_H);
    __half* ffnin_h  = (__half*)(scr + OFF_FFNIN_H);
    __half* fbuf_h   = (__half*)(scr + OFF_FBUF_H);
    __half* w_h      = (__half*)(scr + OFF_WH);

    static bool attr_set = false;
    if (!attr_set) {
        cudaFuncSetAttribute(mma_gemm<0,true,128>,  cudaFuncAttributeMaxDynamicSharedMemorySize, GEMM_SMEM_128);
        cudaFuncSetAttribute(mma_gemm<2,true,128>,  cudaFuncAttributeMaxDynamicSharedMemorySize, GEMM_SMEM_128);
        cudaFuncSetAttribute(mma_gemm<1,false,64>,  cudaFuncAttributeMaxDynamicSharedMemorySize, GEMM_SMEM_64);
        cudaFuncSetAttribute(mma_gemm<3,true,64>,   cudaFuncAttributeMaxDynamicSharedMemorySize, GEMM_SMEM_64);
        cudaFuncSetAttribute(mma_gemm<0,false,64>,  cudaFuncAttributeMaxDynamicSharedMemorySize, GEMM_SMEM_64);
        cudaFuncSetAttribute(attn_mma_kernel, cudaFuncAttributeMaxDynamicSharedMemorySize, ATTN_SMEM);
        attr_set = true;
    }

    // 0. convert x_in + all weights to fp16
    cvt_all_kernel<<<1728, 256>>>(x_in, in_proj_w, out_proj_w, p2s_w, s2p_w,
                                  tw1, tw2, fw1, fw2, xin_h, w_h);

    // 1. qkv = x @ in_proj_w^T + b   (fp16 out)
    mma_gemm<0,true,128><<<dim3(6, 64), 256, GEMM_SMEM_128>>>(xin_h, 256, w_h + WH_IP, in_proj_b,
                                                              nullptr, 0, qkv_h, 768, 256);
    // 2. causal attention (full fp16) -> attn_h
    attn_mma_kernel<<<dim3(8, 32), 256, ATTN_SMEM>>>(qkv_h, attn_h);
    // 3. out_proj + residual(x_in) -> tmp fp32   [BM=64, grid 256]
    mma_gemm<1,false,64><<<dim3(2, 128), 256, GEMM_SMEM_64>>>(attn_h, 256, w_h + WH_OP, out_proj_b,
                                                              x_in, 256, tmp, 256, 256);
    // 4. x = LN1(tmp) -> xb fp32 + xb_h
    ln_warp_kernel<<<512, 256>>>(tmp, 256, ln1s, ln1b, xb, 256, 8192, xb_h);
    // 5. conv -> comb_h[:,256:512]
    conv_kernel<<<8192, 256>>>(xb, conv_w, conv_b, comb_h);
    // 6. EMA -> comb_h[:,512:768] + trajectory
    ema_kernel<<<dim3(8, 8), 256>>>(xb, comb_h, out + (size_t)M_ROWS * 256 + 2048);
    // 7. comb_h[:,0:256] = x + 0.3*(x @ p2s^T + b)   [BM=64]
    mma_gemm<3,true,64><<<dim3(2, 128), 256, GEMM_SMEM_64>>>(xb_h, 256, w_h + WH_P2S, p2s_b,
                                                             xb, 256, comb_h, 768, 256);
    // 8. h = gelu(comb @ tw1^T + b1) -> hb_h
    mma_gemm<2,true,128><<<dim3(4, 64), 256, GEMM_SMEM_128>>>(comb_h, 768, w_h + WH_TW1, tb1,
                                                              nullptr, 0, hb_h, 512, 768);
    // 9. deltas = h @ tw2^T + b2  (fp32)   [BM=64]
    mma_gemm<0,false,64><<<dim3(2, 128), 256, GEMM_SMEM_64>>>(hb_h, 512, w_h + WH_TW2, tb2,
                                                              nullptr, 0, deltas, 256, 512);
    // 10. states = seq + 0.5*cumsum(deltas)
    chunksum_kernel<<<dim3(8, 8), 256>>>(deltas, csum);
    cumsum_kernel<<<dim3(8, 8), 256>>>(deltas, seq_state, csum, states);
    // 11. states = LN3(states) -> fp32 + states_h
    ln_warp_kernel<<<512, 256>>>(states, 256, ln3s, ln3b, states, 256, 8192, states_h);
    // 12. ffn_in = x + 0.3*(states @ s2p^T + b) -> ffnin_h   [BM=64]
    mma_gemm<3,true,64><<<dim3(2, 128), 256, GEMM_SMEM_64>>>(states_h, 256, w_h + WH_S2P, s2p_b,
                                                             xb, 256, ffnin_h, 256, 256);
    // 13. f = gelu(ffn_in @ fw1^T + b1) -> fbuf_h
    mma_gemm<2,true,128><<<dim3(8, 64), 256, GEMM_SMEM_128>>>(ffnin_h, 256, w_h + WH_FW1, fb1,
                                                              nullptr, 0, fbuf_h, 1024, 256);
    // 14. tmp = x + f @ fw2^T + b2  (fp32)   [BM=64]
    mma_gemm<1,false,64><<<dim3(2, 128), 256, GEMM_SMEM_64>>>(fbuf_h, 1024, w_h + WH_FW2, fb2,
                                                              xb, 256, tmp, 256, 1024);
    // 15. LN2 -> out (fp32)
    ln_warp_kernel<<<512, 256>>>(tmp, 256, ln2s, ln2b, out, 256, 8192, nullptr);
    // 16. LN4(states[:, -1, :])
    ln_warp_kernel<<<1, 256>>>(states + (size_t)1023 * 256, (long)1024 * 256,
                               ln4s, ln4b, out + (size_t)M_ROWS * 256, 256, 8, nullptr);
}

// round 13
// speedup vs baseline: 1.6412x; 1.0748x over previous
#include <cuda_runtime.h>
#include <cuda_fp16.h>
#include <math.h>
#include <stdint.h>

#define B_SZ   8
#define T_SEQ  1024
#define D_MOD  256
#define M_ROWS (B_SZ * T_SEQ)   // 8192

// ---------------------------------------------------------------------------
// Scratch layout (float units)
// ---------------------------------------------------------------------------
#define OFF_TMP      0ul          // [8192,256] fp32
#define OFF_X        2097152ul    // [8192,256] fp32
#define OFF_STATES   4194304ul    // [8192,256] fp32
#define OFF_DELTAS   6291456ul    // [8192,256] fp32
#define OFF_CSUM     8388608ul    // [64,256]   fp32
#define OFF_QKV_H    8404992ul    // [8192,768] half
#define OFF_XIN_H    11550720ul   // [8192,256] half
#define OFF_ATTN_H   12599296ul   // [8192,256] half
#define OFF_XB_H     13647872ul   // [8192,256] half
#define OFF_COMB_H   14696448ul   // [8192,768] half
#define OFF_HB_H     17842176ul   // [8192,512] half
#define OFF_STATES_H 19939328ul   // [8192,256] half
#define OFF_FFNIN_H  20987904ul   // [8192,256] half
#define OFF_FBUF_H   22036480ul   // [8192,1024] half
#define OFF_WH       26230784ul   // all weights, half
#define SCRATCH_TOTAL 26853376ul

// weight offsets within W_H (half units)
#define WH_IP   0
#define WH_OP   196608
#define WH_P2S  262144
#define WH_S2P  327680
#define WH_TW1  393216
#define WH_TW2  786432
#define WH_FW1  917504
#define WH_FW2  1179648

__device__ float d_scratch[SCRATCH_TOTAL];

__device__ __forceinline__ float gelu_f(float x) {
    return 0.5f * x * (1.0f + erff(x * 0.70710678118654752f));
}

#define MMA_F16(d, a, b) \
    asm volatile("mma.sync.aligned.m16n8k16.row.col.f32.f16.f16.f32 " \
                 "{%0,%1,%2,%3}, {%4,%5,%6,%7}, {%8,%9}, {%0,%1,%2,%3};" \
                 : "+f"(d[0]), "+f"(d[1]), "+f"(d[2]), "+f"(d[3]) \
                 : "r"(a[0]), "r"(a[1]), "r"(a[2]), "r"(a[3]), \
                   "r"(b[0]), "r"(b[1]))

// Fast exp(s/8): FMA-pipe only, no MUFU.
__device__ __forceinline__ float fexp_s8(float s) {
    const float y = s * 0.1803368801111244f;
    const float rnd = y + 12582912.0f;
    const int   i   = __float_as_int(rnd);
    const float nf  = rnd - 12582912.0f;
    const float f   = y - nf;
    float p = 1.3333558146e-3f;
    p = fmaf(p, f, 9.6181291076e-3f);
    p = fmaf(p, f, 5.5504108665e-2f);
    p = fmaf(p, f, 2.4022650696e-1f);
    p = fmaf(p, f, 6.9314718056e-1f);
    p = fmaf(p, f, 1.0f);
    const float scale = __int_as_float((i << 23) + 0x3f800000);
    return p * scale;
}

__device__ __forceinline__ uint32_t h2u(__half2 v) {
    return *(uint32_t*)&v;
}

// ---------------------------------------------------------------------------
// fp32 -> fp16 bulk conversion (unchanged).
// ---------------------------------------------------------------------------
__global__ void __launch_bounds__(256) cvt_all_kernel(
    const float* __restrict__ xin,
    const float* __restrict__ w_ip, const float* __restrict__ w_op,
    const float* __restrict__ w_p2s, const float* __restrict__ w_s2p,
    const float* __restrict__ w_tw1, const float* __restrict__ w_tw2,
    const float* __restrict__ w_fw1, const float* __restrict__ w_fw2,
    __half* __restrict__ xin_h, __half* __restrict__ w_h)
{
    const size_t e = ((size_t)blockIdx.x * 256 + threadIdx.x) * 8;
    const float* src; __half* dst;
    if      (e < 2097152ul) { src = xin   + e;             dst = xin_h + e; }
    else if (e < 2293760ul) { src = w_ip  + (e - 2097152); dst = w_h + WH_IP  + (e - 2097152); }
    else if (e < 2359296ul) { src = w_op  + (e - 2293760); dst = w_h + WH_OP  + (e - 2293760); }
    else if (e < 2424832ul) { src = w_p2s + (e - 2359296); dst = w_h + WH_P2S + (e - 2359296); }
    else if (e < 2490368ul) { src = w_s2p + (e - 2424832); dst = w_h + WH_S2P + (e - 2424832); }
    else if (e < 2883584ul) { src = w_tw1 + (e - 2490368); dst = w_h + WH_TW1 + (e - 2490368); }
    else if (e < 3014656ul) { src = w_tw2 + (e - 2883584); dst = w_h + WH_TW2 + (e - 2883584); }
    else if (e < 3276800ul) { src = w_fw1 + (e - 3014656); dst = w_h + WH_FW1 + (e - 3014656); }
    else                    { src = w_fw2 + (e - 3276800); dst = w_h + WH_FW2 + (e - 3276800); }
    float4 f0 = ((const float4*)src)[0];
    float4 f1 = ((const float4*)src)[1];
    __half2 h[4];
    h[0] = __floats2half2_rn(f0.x, f0.y);
    h[1] = __floats2half2_rn(f0.z, f0.w);
    h[2] = __floats2half2_rn(f1.x, f1.y);
    h[3] = __floats2half2_rn(f1.z, f1.w);
    *(uint4*)dst = *(uint4*)h;
}

// ---------------------------------------------------------------------------
// FP16 GEMM, templated BM in {128, 64} (unchanged from R12).
// ---------------------------------------------------------------------------
#define ISSUE_TILE(k0, sidx)                                                   \
    {                                                                          \
        _Pragma("unroll")                                                      \
        for (int i = 0; i < BM / 64; i++) {                                    \
            int idx = tid + i * 256;                                           \
            int row = idx >> 2;                                                \
            int ch  = idx & 3;                                                 \
            uint32_t da = smem_base + (uint32_t)(((sidx) * STAGE + row * 36 + ch * 4) * 4); \
            const __half* ga = A + (size_t)(bm + row) * lda + (k0) + ch * 8;   \
            asm volatile("cp.async.cg.shared.global [%0], [%1], 16;" :: "r"(da), "l"(ga)); \
        }                                                                      \
        _Pragma("unroll")                                                      \
        for (int i = 0; i < 2; i++) {                                          \
            int idx = tid + i * 256;                                           \
            int row = idx >> 2;                                                \
            int ch  = idx & 3;                                                 \
            uint32_t db = smem_base + (uint32_t)(((sidx) * STAGE + A_TS + row * 36 + ch * 4) * 4); \
            const __half* gw = W + (size_t)(bn + row) * (size_t)K + (k0) + ch * 8; \
            asm volatile("cp.async.cg.shared.global [%0], [%1], 16;" :: "r"(db), "l"(gw)); \
        }                                                                      \
        asm volatile("cp.async.commit_group;");                                \
    }

template<int EPI, bool OUTH, int BM>
__global__ void __launch_bounds__(256, 2) mma_gemm(
    const __half* __restrict__ A, int lda,
    const __half* __restrict__ W,
    const float* __restrict__ bias,
    const float* __restrict__ addend, int ld_add,
    void* __restrict__ Cv, int ldc,
    int K)
{
    constexpr int MI    = BM / 32;
    constexpr int A_TS  = BM * 36;
    constexpr int STAGE = A_TS + 128 * 36;

    extern __shared__ uint32_t sm[];
    const uint32_t smem_base = (uint32_t)__cvta_generic_to_shared(sm);

    const int tid  = threadIdx.x;
    const int bm   = blockIdx.y * BM;
    const int bn   = blockIdx.x * 128;
    const int wid  = tid >> 5;
    const int lane = tid & 31;
    const int wm   = (wid & 1) * (BM / 2);
    const int wn32 = (wid >> 1) * 32;
    const int r    = lane >> 2;
    const int t    = lane & 3;

    float acc[MI][4][4];
    #pragma unroll
    for (int mi = 0; mi < MI; mi++)
        #pragma unroll
        for (int ni = 0; ni < 4; ni++)
            #pragma unroll
            for (int c = 0; c < 4; c++) acc[mi][ni][c] = 0.0f;

    const int ntiles = K >> 5;

    ISSUE_TILE(0, 0);
    ISSUE_TILE(32, 1);

    int sidx = 0;
    for (int kt = 0; kt < ntiles; kt++) {
        if (kt == ntiles - 1) {
            asm volatile("cp.async.wait_group 0;");
        } else {
            asm volatile("cp.async.wait_group 1;");
        }
        __syncthreads();

        if (kt + 2 < ntiles) {
            int ws = sidx + 2; if (ws >= 3) ws -= 3;
            ISSUE_TILE((kt + 2) * 32, ws);
        }

        const uint32_t* Ab = sm + sidx * STAGE;
        const uint32_t* Bb = Ab + A_TS;

        #pragma unroll
        for (int ks = 0; ks < 2; ks++) {
            const int kb = ks * 8;
            uint32_t a[MI][4], b[4][2];
            #pragma unroll
            for (int mi = 0; mi < MI; mi++) {
                int idx = (wm + mi * 16 + r) * 36 + kb + t;
                a[mi][0] = Ab[idx];
                a[mi][1] = Ab[idx + 8 * 36];
                a[mi][2] = Ab[idx + 4];
                a[mi][3] = Ab[idx + 8 * 36 + 4];
            }
            #pragma unroll
            for (int ni = 0; ni < 4; ni++) {
                int idx = (wn32 + ni * 8 + r) * 36 + kb + t;
                b[ni][0] = Bb[idx];
                b[ni][1] = Bb[idx + 4];
            }
            #pragma unroll
            for (int mi = 0; mi < MI; mi++)
                #pragma unroll
                for (int ni = 0; ni < 4; ni++)
                    MMA_F16(acc[mi][ni], a[mi], b[ni]);
        }
        sidx++; if (sidx == 3) sidx = 0;
    }

    float* Cf = (float*)Cv;
    __half* Ch = (__half*)Cv;

    #pragma unroll
    for (int mi = 0; mi < MI; mi++) {
        const int row0 = bm + wm + mi * 16 + r;
        const int row1 = row0 + 8;
        #pragma unroll
        for (int ni = 0; ni < 4; ni++) {
            const int col = bn + wn32 + ni * 8 + 2 * t;
            const float2 bb = *(const float2*)(bias + col);
            float v00 = acc[mi][ni][0] + bb.x;
            float v01 = acc[mi][ni][1] + bb.y;
            float v10 = acc[mi][ni][2] + bb.x;
            float v11 = acc[mi][ni][3] + bb.y;
            if (EPI == 1) {
                const float2 r0 = *(const float2*)(addend + (size_t)row0 * ld_add + col);
                const float2 r1 = *(const float2*)(addend + (size_t)row1 * ld_add + col);
                v00 += r0.x; v01 += r0.y; v10 += r1.x; v11 += r1.y;
            }
            if (EPI == 2) {
                v00 = gelu_f(v00); v01 = gelu_f(v01);
                v10 = gelu_f(v10); v11 = gelu_f(v11);
            }
            if (EPI == 3) {
                const float2 r0 = *(const float2*)(addend + (size_t)row0 * ld_add + col);
                const float2 r1 = *(const float2*)(addend + (size_t)row1 * ld_add + col);
                v00 = r0.x + 0.3f * v00; v01 = r0.y + 0.3f * v01;
                v10 = r1.x + 0.3f * v10; v11 = r1.y + 0.3f * v11;
            }
            if (OUTH) {
                *(__half2*)(Ch + (size_t)row0 * ldc + col) = __floats2half2_rn(v00, v01);
                *(__half2*)(Ch + (size_t)row1 * ldc + col) = __floats2half2_rn(v10, v11);
            } else {
                *(float2*)(Cf + (size_t)row0 * ldc + col) = make_float2(v00, v01);
                *(float2*)(Cf + (size_t)row1 * ldc + col) = make_float2(v10, v11);
            }
        }
    }
}

#define GEMM_SMEM_128 (3 * (128 + 128) * 36 * 4)   // 110592 B
#define GEMM_SMEM_64  (3 * (64 + 128) * 36 * 4)    // 82944 B

// ---------------------------------------------------------------------------
// FP16 mma causal flash-attention (unchanged from R12).
// ---------------------------------------------------------------------------
#define KV_STG_U32 4608
#define ATTN_SMEM (2 * KV_STG_U32 * 4)     // 36864 B

#define AT_ISSUE(jt, s)                                                        \
    {                                                                          \
        const int _j0 = (jt) * 64;                                             \
        _Pragma("unroll")                                                      \
        for (int _i = 0; _i < 2; _i++) {                                       \
            int _idx = tid + _i * 256;                                         \
            int _row = _idx >> 3;                                              \
            int _ch  = _idx & 7;                                               \
            const __half* _kp = baseh + (size_t)(_j0 + _row) * 768 + 256 + h * 64 + _ch * 8; \
            uint32_t _dk = smem_base + (uint32_t)(((s) * KV_STG_U32 + _row * 36 + _ch * 4) * 4); \
            asm volatile("cp.async.cg.shared.global [%0], [%1], 16;" :: "r"(_dk), "l"(_kp)); \
            uint32_t _dv = smem_base + (uint32_t)(((s) * KV_STG_U32 + 2304 + _row * 36 + _ch * 4) * 4); \
            asm volatile("cp.async.cg.shared.global [%0], [%1], 16;" :: "r"(_dv), "l"(_kp + 256)); \
        }                                                                      \
        asm volatile("cp.async.commit_group;");                                \
    }

__global__ void __launch_bounds__(256) attn_mma_kernel(
    const __half* __restrict__ qkvh, __half* __restrict__ attn_out)
{
    extern __shared__ uint32_t dsm[];
    const uint32_t smem_base = (uint32_t)__cvta_generic_to_shared(dsm);

    const int bh = blockIdx.y;
    const int b  = bh >> 2;
    const int h  = bh & 3;
    const int qx = gridDim.x - 1 - blockIdx.x;
    const int qbase = qx * 128;
    const int tid  = threadIdx.x;
    const int wid  = tid >> 5;
    const int lane = tid & 31;
    const int r    = lane >> 2;
    const int t    = lane & 3;
    const __half* baseh = qkvh + (size_t)b * T_SEQ * 768;

    const int qrow0 = qbase + wid * 16 + r;
    const int qrow1 = qrow0 + 8;

    uint32_t aq[4][4];
    {
        const __half* q0 = baseh + (size_t)qrow0 * 768 + h * 64;
        const __half* q1 = baseh + (size_t)qrow1 * 768 + h * 64;
        #pragma unroll
        for (int ks = 0; ks < 4; ks++) {
            aq[ks][0] = *(const uint32_t*)(q0 + ks * 16 + 2 * t);
            aq[ks][1] = *(const uint32_t*)(q1 + ks * 16 + 2 * t);
            aq[ks][2] = *(const uint32_t*)(q0 + ks * 16 + 8 + 2 * t);
            aq[ks][3] = *(const uint32_t*)(q1 + ks * 16 + 8 + 2 * t);
        }
    }

    float oacc[8][4];
    #pragma unroll
    for (int ni = 0; ni < 8; ni++)
        #pragma unroll
        for (int c = 0; c < 4; c++) oacc[ni][c] = 0.0f;
    float lsum0 = 0.0f, lsum1 = 0.0f;

    const int ntiles   = 2 * qx + 2;
    const int wrow_max = qbase + wid * 16 + 15;
    const unsigned FULL = 0xffffffffu;

    AT_ISSUE(0, 0);

    for (int jt = 0; jt < ntiles; jt++) {
        const int j0 = jt * 64;
        asm volatile("cp.async.wait_group 0;");
        __syncthreads();

        if (jt + 1 < ntiles) AT_ISSUE(jt + 1, (jt + 1) & 1);

        if (j0 > wrow_max) continue;

        const uint32_t* Ks32 = dsm + (jt & 1) * KV_STG_U32;
        const __half*   Vh   = (const __half*)(Ks32 + 2304);

        float sc[8][4];
        #pragma unroll
        for (int ni = 0; ni < 8; ni++)
            #pragma unroll
            for (int c = 0; c < 4; c++) sc[ni][c] = 0.0f;
        #pragma unroll
        for (int ks = 0; ks < 4; ks++) {
            #pragma unroll
            for (int ni = 0; ni < 8; ni++) {
                uint32_t bfr[2];
                const int key = ni * 8 + r;
                bfr[0] = Ks32[key * 36 + ks * 8 + t];
                bfr[1] = Ks32[key * 36 + ks * 8 + t + 4];
                MMA_F16(sc[ni], aq[ks], bfr);
            }
        }

        #pragma unroll
        for (int ni = 0; ni < 8; ni++) {
            const int col0 = j0 + ni * 8 + 2 * t;
            float p0 = (col0     <= qrow0) ? fexp_s8(sc[ni][0]) : 0.0f;
            float p1 = (col0 + 1 <= qrow0) ? fexp_s8(sc[ni][1]) : 0.0f;
            float p2 = (col0     <= qrow1) ? fexp_s8(sc[ni][2]) : 0.0f;
            float p3 = (col0 + 1 <= qrow1) ? fexp_s8(sc[ni][3]) : 0.0f;
            lsum0 += p0 + p1;
            lsum1 += p2 + p3;
            sc[ni][0] = p0; sc[ni][1] = p1; sc[ni][2] = p2; sc[ni][3] = p3;
        }

        #pragma unroll
        for (int c = 0; c < 4; c++) {
            uint32_t ap[4];
            ap[0] = h2u(__floats2half2_rn(sc[2*c][0],   sc[2*c][1]));
            ap[1] = h2u(__floats2half2_rn(sc[2*c][2],   sc[2*c][3]));
            ap[2] = h2u(__floats2half2_rn(sc[2*c+1][0], sc[2*c+1][1]));
            ap[3] = h2u(__floats2half2_rn(sc[2*c+1][2], sc[2*c+1][3]));
            const __half* vp = Vh + (c * 16 + 2 * t) * 72;
            #pragma unroll
            for (int ni = 0; ni < 8; ni++) {
                const int n = ni * 8 + r;
                uint32_t bfr[2];
                bfr[0] = h2u(__halves2half2(vp[n],          vp[n + 72]));
                bfr[1] = h2u(__halves2half2(vp[n + 8 * 72], vp[n + 9 * 72]));
                MMA_F16(oacc[ni], ap, bfr);
            }
        }
    }

    lsum0 += __shfl_xor_sync(FULL, lsum0, 1);
    lsum0 += __shfl_xor_sync(FULL, lsum0, 2);
    lsum1 += __shfl_xor_sync(FULL, lsum1, 1);
    lsum1 += __shfl_xor_sync(FULL, lsum1, 2);
    const float inv0 = 1.0f / lsum0;
    const float inv1 = 1.0f / lsum1;

    __half* op0 = attn_out + ((size_t)b * T_SEQ + qrow0) * 256 + h * 64;
    __half* op1 = attn_out + ((size_t)b * T_SEQ + qrow1) * 256 + h * 64;
    #pragma unroll
    for (int ni = 0; ni < 8; ni++) {
        *(__half2*)(op0 + ni * 8 + 2 * t) = __floats2half2_rn(oacc[ni][0] * inv0, oacc[ni][1] * inv0);
        *(__half2*)(op1 + ni * 8 + 2 * t) = __floats2half2_rn(oacc[ni][2] * inv1, oacc[ni][3] * inv1);
    }
}

// ---------------------------------------------------------------------------
// LayerNorm, 2 rows/warp; optional fp16 shadow output (unchanged).
// ---------------------------------------------------------------------------
__global__ void __launch_bounds__(256) ln_warp_kernel(
    const float* __restrict__ in, long ld_in,
    const float* __restrict__ gamma, const float* __restrict__ beta,
    float* __restrict__ out, long ld_out, int nrows,
    __half* __restrict__ out_h)
{
    const int wid = threadIdx.x >> 5, lane = threadIdx.x & 31;
    const int rowA = blockIdx.x * 16 + wid * 2;
    const int rowB = rowA + 1;
    if (rowA >= nrows) return;
    const bool hasB = (rowB < nrows);

    const float* ipA = in + (size_t)rowA * ld_in + lane * 8;
    const float* ipB = in + (size_t)(hasB ? rowB : rowA) * ld_in + lane * 8;
    float4 a0 = ((const float4*)ipA)[0];
    float4 a1 = ((const float4*)ipA)[1];
    float4 b0 = ((const float4*)ipB)[0];
    float4 b1 = ((const float4*)ipB)[1];

    float sA  = a0.x + a0.y + a0.z + a0.w + a1.x + a1.y + a1.z + a1.w;
    float qA  = a0.x*a0.x + a0.y*a0.y + a0.z*a0.z + a0.w*a0.w
              + a1.x*a1.x + a1.y*a1.y + a1.z*a1.z + a1.w*a1.w;
    float sB  = b0.x + b0.y + b0.z + b0.w + b1.x + b1.y + b1.z + b1.w;
    float qB  = b0.x*b0.x + b0.y*b0.y + b0.z*b0.z + b0.w*b0.w
              + b1.x*b1.x + b1.y*b1.y + b1.z*b1.z + b1.w*b1.w;
    #pragma unroll
    for (int o = 16; o > 0; o >>= 1) {
        sA += __shfl_xor_sync(0xffffffffu, sA, o);
        sB += __shfl_xor_sync(0xffffffffu, sB, o);
        qA += __shfl_xor_sync(0xffffffffu, qA, o);
        qB += __shfl_xor_sync(0xffffffffu, qB, o);
    }
    const float mA = sA * (1.0f / 256.0f);
    const float vA = qA * (1.0f / 256.0f) - mA * mA;
    const float rA = rsqrtf(vA + 1e-5f);
    const float mB = sB * (1.0f / 256.0f);
    const float vB = qB * (1.0f / 256.0f) - mB * mB;
    const float rB = rsqrtf(vB + 1e-5f);

    const float4 g0 = ((const float4*)(gamma + lane * 8))[0];
    const float4 g1 = ((const float4*)(gamma + lane * 8))[1];
    const float4 be0 = ((const float4*)(beta  + lane * 8))[0];
    const float4 be1 = ((const float4*)(beta  + lane * 8))[1];

    float4 o0, o1;
    o0.x = (a0.x - mA) * rA * g0.x + be0.x;
    o0.y = (a0.y - mA) * rA * g0.y + be0.y;
    o0.z = (a0.z - mA) * rA * g0.z + be0.z;
    o0.w = (a0.w - mA) * rA * g0.w + be0.w;
    o1.x = (a1.x - mA) * rA * g1.x + be1.x;
    o1.y = (a1.y - mA) * rA * g1.y + be1.y;
    o1.z = (a1.z - mA) * rA * g1.z + be1.z;
    o1.w = (a1.w - mA) * rA * g1.w + be1.w;
    float* opA = out + (size_t)rowA * ld_out + lane * 8;
    ((float4*)opA)[0] = o0;
    ((float4*)opA)[1] = o1;
    if (out_h) {
        __half2 hh[4];
        hh[0] = __floats2half2_rn(o0.x, o0.y);
        hh[1] = __floats2half2_rn(o0.z, o0.w);
        hh[2] = __floats2half2_rn(o1.x, o1.y);
        hh[3] = __floats2half2_rn(o1.z, o1.w);
        *(uint4*)(out_h + (size_t)rowA * ld_out + lane * 8) = *(uint4*)hh;
    }

    if (hasB) {
        float4 p0, p1;
        p0.x = (b0.x - mB) * rB * g0.x + be0.x;
        p0.y = (b0.y - mB) * rB * g0.y + be0.y;
        p0.z = (b0.z - mB) * rB * g0.z + be0.z;
        p0.w = (b0.w - mB) * rB * g0.w + be0.w;
        p1.x = (b1.x - mB) * rB * g1.x + be1.x;
        p1.y = (b1.y - mB) * rB * g1.y + be1.y;
        p1.z = (b1.z - mB) * rB * g1.z + be1.z;
        p1.w = (b1.w - mB) * rB * g1.w + be1.w;
        float* opB = out + (size_t)rowB * ld_out + lane * 8;
        ((float4*)opB)[0] = p0;
        ((float4*)opB)[1] = p1;
        if (out_h) {
            __half2 hh[4];
            hh[0] = __floats2half2_rn(p0.x, p0.y);
            hh[1] = __floats2half2_rn(p0.z, p0.w);
            hh[2] = __floats2half2_rn(p1.x, p1.y);
            hh[3] = __floats2half2_rn(p1.z, p1.w);
            *(uint4*)(out_h + (size_t)rowB * ld_out + lane * 8) = *(uint4*)hh;
        }
    }
}

// ---------------------------------------------------------------------------
// Fused EMA + depthwise conv (rolling 8-value window) -> comb_h[:,256:768],
// + trajectory summary. grid (B, 8), block 256 (=d). t0/start multiples of 8.
// ---------------------------------------------------------------------------
__global__ void __launch_bounds__(256) ema_conv_kernel(
    const float* __restrict__ x, const float* __restrict__ cw,
    const float* __restrict__ cb, __half* __restrict__ comb_h,
    float* __restrict__ traj_out)
{
    const int b = blockIdx.x, chunk = blockIdx.y, d = threadIdx.x;
    const int t0 = chunk * 128;
    int start = t0 - 256; if (start < 0) start = 0;
    const float* xp = x + (size_t)b * 1024 * 256 + d;

    float w[8];
    #pragma unroll
    for (int i = 0; i < 8; i++) w[i] = cw[d * 8 + i];
    const float cbd = cb[d];

    float buf[8];
    #pragma unroll
    for (int i = 0; i < 8; i++) buf[i] = 0.0f;

    float c = 0.0f;
    for (int t = start; t < t0; t += 8) {
        #pragma unroll
        for (int p = 0; p < 8; p++) {
            float v = xp[(size_t)(t + p) * 256];
            c = fmaf(0.9f, c, 0.1f * v);
            buf[p] = v;                       // (t+p)&7 == p (t % 8 == 0)
        }
    }

    __half* oe = comb_h + (size_t)b * 1024 * 768 + 512 + d;
    __half* oc = comb_h + (size_t)b * 1024 * 768 + 256 + d;
    for (int t = t0; t < t0 + 128; t += 8) {
        #pragma unroll
        for (int p = 0; p < 8; p++) {
            float v = xp[(size_t)(t + p) * 256];
            c = fmaf(0.9f, c, 0.1f * v);
            buf[p] = v;
            float r = cbd;
            #pragma unroll
            for (int q = 0; q < 8; q++)
                r = fmaf(w[q], buf[(p + 1 + q) & 7], r);
            oe[(size_t)(t + p) * 768] = __float2half_rn(c);
            oc[(size_t)(t + p) * 768] = __float2half_rn(r);
        }
    }
    if (chunk == 7) traj_out[b * 256 + d] = c;
}

__global__ void __launch_bounds__(256) chunksum_kernel(
    const float* __restrict__ deltas, float* __restrict__ csum)
{
    const int b = blockIdx.x, chunk = blockIdx.y, d = threadIdx.x;
    const float* dp = deltas + ((size_t)b * 1024 + chunk * 128) * 256 + d;
    float s = 0.0f;
    #pragma unroll 8
    for (int t = 0; t < 128; t++) s += dp[(size_t)t * 256];
    csum[(b * 8 + chunk) * 256 + d] = s;
}

__global__ void __launch_bounds__(256) cumsum_kernel(
    const float* __restrict__ deltas, const float* __restrict__ seq,
    const float* __restrict__ csum, float* __restrict__ states)
{
    const int b = blockIdx.x, chunk = blockIdx.y, d = threadIdx.x;
    float c = seq[b * 256 + d];
    for (int cc = 0; cc < 8; cc++)
        if (cc < chunk) c = fmaf(0.5f, csum[(b * 8 + cc) * 256 + d], c);
    const float* dp = deltas + ((size_t)b * 1024 + chunk * 128) * 256 + d;
    float* sp = states + ((size_t)b * 1024 + chunk * 128) * 256 + d;
    #pragma unroll 8
    for (int t = 0; t < 128; t++) {
        c = fmaf(0.5f, dp[(size_t)t * 256], c);
        sp[(size_t)t * 256] = c;
    }
}

// ---------------------------------------------------------------------------
// Launch — fork/join on a side stream (events = graph edges under capture).
// ---------------------------------------------------------------------------
extern "C" void kernel_launch(void* const* d_in, const int* in_sizes, int n_in,
                              void* d_out, int out_size)
{
    const float* x_in       = (const float*)d_in[0];
    const float* seq_state  = (const float*)d_in[1];
    const float* in_proj_w  = (const float*)d_in[3];
    const float* in_proj_b  = (const float*)d_in[4];
    const float* out_proj_w = (const float*)d_in[5];
    const float* out_proj_b = (const float*)d_in[6];
    const float* conv_w     = (const float*)d_in[7];
    const float* conv_b     = (const float*)d_in[8];
    const float* p2s_w      = (const float*)d_in[9];
    const float* p2s_b      = (const float*)d_in[10];
    const float* s2p_w      = (const float*)d_in[11];
    const float* s2p_b      = (const float*)d_in[12];
    const float* tw1        = (const float*)d_in[13];
    const float* tb1        = (const float*)d_in[14];
    const float* tw2        = (const float*)d_in[15];
    const float* tb2        = (const float*)d_in[16];
    const float* fw1        = (const float*)d_in[17];
    const float* fb1        = (const float*)d_in[18];
    const float* fw2        = (const float*)d_in[19];
    const float* fb2        = (const float*)d_in[20];
    const float* ln1s = (const float*)d_in[21];
    const float* ln1b = (const float*)d_in[22];
    const float* ln2s = (const float*)d_in[23];
    const float* ln2b = (const float*)d_in[24];
    const float* ln3s = (const float*)d_in[25];
    const float* ln3b = (const float*)d_in[26];
    const float* ln4s = (const float*)d_in[27];
    const float* ln4b = (const float*)d_in[28];
    float* out = (float*)d_out;

    float* scr = nullptr;
    cudaGetSymbolAddress((void**)&scr, d_scratch);
    float*  tmp      = scr + OFF_TMP;
    float*  xb       = scr + OFF_X;
    float*  states   = scr + OFF_STATES;
    float*  deltas   = scr + OFF_DELTAS;
    float*  csum     = scr + OFF_CSUM;
    __half* qkv_h    = (__half*)(scr + OFF_QKV_H);
    __half* xin_h    = (__half*)(scr + OFF_XIN_H);
    __half* attn_h   = (__half*)(scr + OFF_ATTN_H);
    __half* xb_h     = (__half*)(scr + OFF_XB_H);
    __half* comb_h   = (__half*)(scr + OFF_COMB_H);
    __half* hb_h     = (__half*)(scr + OFF_HB_H);
    __half* states_h = (__half*)(scr + OFF_STATES_H);
    __half* ffnin_h  = (__half*)(scr + OFF_FFNIN_H);
    __half* fbuf_h   = (__half*)(scr + OFF_FBUF_H);
    __half* w_h      = (__half*)(scr + OFF_WH);

    static cudaStream_t s2 = nullptr;
    static cudaEvent_t evA = nullptr, evB = nullptr, evC = nullptr, evD = nullptr;
    static bool init_done = false;
    if (!init_done) {
        cudaFuncSetAttribute(mma_gemm<0,true,128>,  cudaFuncAttributeMaxDynamicSharedMemorySize, GEMM_SMEM_128);
        cudaFuncSetAttribute(mma_gemm<2,true,128>,  cudaFuncAttributeMaxDynamicSharedMemorySize, GEMM_SMEM_128);
        cudaFuncSetAttribute(mma_gemm<1,false,64>,  cudaFuncAttributeMaxDynamicSharedMemorySize, GEMM_SMEM_64);
        cudaFuncSetAttribute(mma_gemm<3,true,64>,   cudaFuncAttributeMaxDynamicSharedMemorySize, GEMM_SMEM_64);
        cudaFuncSetAttribute(mma_gemm<0,false,64>,  cudaFuncAttributeMaxDynamicSharedMemorySize, GEMM_SMEM_64);
        cudaFuncSetAttribute(attn_mma_kernel, cudaFuncAttributeMaxDynamicSharedMemorySize, ATTN_SMEM);
        cudaStreamCreateWithFlags(&s2, cudaStreamNonBlocking);
        cudaEventCreateWithFlags(&evA, cudaEventDisableTiming);
        cudaEventCreateWithFlags(&evB, cudaEventDisableTiming);
        cudaEventCreateWithFlags(&evC, cudaEventDisableTiming);
        cudaEventCreateWithFlags(&evD, cudaEventDisableTiming);
        init_done = true;
    }

    // 0. convert x_in + all weights to fp16
    cvt_all_kernel<<<1728, 256>>>(x_in, in_proj_w, out_proj_w, p2s_w, s2p_w,
                                  tw1, tw2, fw1, fw2, xin_h, w_h);
    // 1. qkv = x @ in_proj_w^T + b
    mma_gemm<0,true,128><<<dim3(6, 64), 256, GEMM_SMEM_128>>>(xin_h, 256, w_h + WH_IP, in_proj_b,
                                                              nullptr, 0, qkv_h, 768, 256);
    // 2. causal attention
    attn_mma_kernel<<<dim3(8, 32), 256, ATTN_SMEM>>>(qkv_h, attn_h);
    // 3. out_proj + residual(x_in)
    mma_gemm<1,false,64><<<dim3(2, 128), 256, GEMM_SMEM_64>>>(attn_h, 256, w_h + WH_OP, out_proj_b,
                                                              x_in, 256, tmp, 256, 256);
    // 4. x = LN1(tmp)
    ln_warp_kernel<<<512, 256>>>(tmp, 256, ln1s, ln1b, xb, 256, 8192, xb_h);

    // fork: ema+conv (side) || p2s GEMM (main)
    cudaEventRecord(evA, 0);
    cudaStreamWaitEvent(s2, evA, 0);
    ema_conv_kernel<<<dim3(8, 8), 256, 0, s2>>>(xb, conv_w, conv_b, comb_h,
                                                out + (size_t)M_ROWS * 256 + 2048);
    cudaEventRecord(evB, s2);
    // 7. comb_h[:,0:256] = x + 0.3*(x @ p2s^T + b)   (main stream)
    mma_gemm<3,true,64><<<dim3(2, 128), 256, GEMM_SMEM_64>>>(xb_h, 256, w_h + WH_P2S, p2s_b,
                                                             xb, 256, comb_h, 768, 256);
    cudaStreamWaitEvent(0, evB, 0);   // join before trans1

    // 8. h = gelu(comb @ tw1^T + b1)
    mma_gemm<2,true,128><<<dim3(4, 64), 256, GEMM_SMEM_128>>>(comb_h, 768, w_h + WH_TW1, tb1,
                                                              nullptr, 0, hb_h, 512, 768);
    // 9. deltas = h @ tw2^T + b2
    mma_gemm<0,false,64><<<dim3(2, 128), 256, GEMM_SMEM_64>>>(hb_h, 512, w_h + WH_TW2, tb2,
                                                              nullptr, 0, deltas, 256, 512);
    // 10. states = seq + 0.5*cumsum(deltas)
    chunksum_kernel<<<dim3(8, 8), 256>>>(deltas, csum);
    cumsum_kernel<<<dim3(8, 8), 256>>>(deltas, seq_state, csum, states);
    // 11. states = LN3(states)
    ln_warp_kernel<<<512, 256>>>(states, 256, ln3s, ln3b, states, 256, 8192, states_h);

    // fork: LN4 (side) || ffn chain (main)
    cudaEventRecord(evC, 0);
    cudaStreamWaitEvent(s2, evC, 0);
    ln_warp_kernel<<<1, 256, 0, s2>>>(states + (size_t)1023 * 256, (long)1024 * 256,
                                      ln4s, ln4b, out + (size_t)M_ROWS * 256, 256, 8, nullptr);
    cudaEventRecord(evD, s2);

    // 12. ffn_in = x + 0.3*(states @ s2p^T + b)
    mma_gemm<3,true,64><<<dim3(2, 128), 256, GEMM_SMEM_64>>>(states_h, 256, w_h + WH_S2P, s2p_b,
                                                             xb, 256, ffnin_h, 256, 256);
    // 13. f = gelu(ffn_in @ fw1^T + b1)
    mma_gemm<2,true,128><<<dim3(8, 64), 256, GEMM_SMEM_128>>>(ffnin_h, 256, w_h + WH_FW1, fb1,
                                                              nullptr, 0, fbuf_h, 1024, 256);
    // 14. tmp = x + f @ fw2^T + b2
    mma_gemm<1,false,64><<<dim3(2, 128), 256, GEMM_SMEM_64>>>(fbuf_h, 1024, w_h + WH_FW2, fb2,
                                                              xb, 256, tmp, 256, 1024);
    // 15. LN2 -> out
    ln_warp_kernel<<<512, 256>>>(tmp, 256, ln2s, ln2b, out, 256, 8192, nullptr);

    cudaStreamWaitEvent(0, evD, 0);   // join LN4 before graph end
}

// round 15
// speedup vs baseline: 1.6631x; 1.0133x over previous
#include <cuda_runtime.h>
#include <cuda_fp16.h>
#include <math.h>
#include <stdint.h>

#define B_SZ   8
#define T_SEQ  1024
#define D_MOD  256
#define M_ROWS (B_SZ * T_SEQ)   // 8192

// ---------------------------------------------------------------------------
// Scratch layout (float units)
// ---------------------------------------------------------------------------
#define OFF_TMP      0ul          // [8192,256] fp32
#define OFF_X        2097152ul    // [8192,256] fp32
#define OFF_STATES   4194304ul    // [8192,256] fp32
#define OFF_DELTAS_H 6291456ul    // [8192,256] half
#define OFF_CSUM     8388608ul    // [64,256]   fp32
#define OFF_QKV_H    8404992ul    // [8192,768] half
#define OFF_XIN_H    11550720ul   // [8192,256] half
#define OFF_ATTN_H   12599296ul   // [8192,256] half
#define OFF_XB_H     13647872ul   // [8192,256] half
#define OFF_COMB_H   14696448ul   // [8192,768] half
#define OFF_HB_H     17842176ul   // [8192,512] half
#define OFF_STATES_H 19939328ul   // [8192,256] half
#define OFF_FFNIN_H  20987904ul   // [8192,256] half
#define OFF_FBUF_H   22036480ul   // [8192,1024] half
#define OFF_WH       26230784ul   // all weights, half
#define SCRATCH_TOTAL 26853376ul

// weight offsets within W_H (half units)
#define WH_IP   0
#define WH_OP   196608
#define WH_P2S  262144
#define WH_S2P  327680
#define WH_TW1  393216
#define WH_TW2  786432
#define WH_FW1  917504
#define WH_FW2  1179648

__device__ float d_scratch[SCRATCH_TOTAL];

__device__ __forceinline__ float gelu_f(float x) {
    return 0.5f * x * (1.0f + erff(x * 0.70710678118654752f));
}

#define MMA_F16(d, a, b) \
    asm volatile("mma.sync.aligned.m16n8k16.row.col.f32.f16.f16.f32 " \
                 "{%0,%1,%2,%3}, {%4,%5,%6,%7}, {%8,%9}, {%0,%1,%2,%3};" \
                 : "+f"(d[0]), "+f"(d[1]), "+f"(d[2]), "+f"(d[3]) \
                 : "r"(a[0]), "r"(a[1]), "r"(a[2]), "r"(a[3]), \
                   "r"(b[0]), "r"(b[1]))

// Fast exp(s/8): FMA-pipe only, no MUFU.
__device__ __forceinline__ float fexp_s8(float s) {
    const float y = s * 0.1803368801111244f;
    const float rnd = y + 12582912.0f;
    const int   i   = __float_as_int(rnd);
    const float nf  = rnd - 12582912.0f;
    const float f   = y - nf;
    float p = 1.3333558146e-3f;
    p = fmaf(p, f, 9.6181291076e-3f);
    p = fmaf(p, f, 5.5504108665e-2f);
    p = fmaf(p, f, 2.4022650696e-1f);
    p = fmaf(p, f, 6.9314718056e-1f);
    p = fmaf(p, f, 1.0f);
    const float scale = __int_as_float((i << 23) + 0x3f800000);
    return p * scale;
}

__device__ __forceinline__ uint32_t h2u(__half2 v) {
    return *(uint32_t*)&v;
}

// ---------------------------------------------------------------------------
// cvt phase 1: x_in + in_proj_w (2293760 elts -> 1120 blocks).
// ---------------------------------------------------------------------------
__global__ void __launch_bounds__(256) cvt_p1_kernel(
    const float* __restrict__ xin, const float* __restrict__ w_ip,
    __half* __restrict__ xin_h, __half* __restrict__ w_h)
{
    const size_t e = ((size_t)blockIdx.x * 256 + threadIdx.x) * 8;
    const float* src; __half* dst;
    if (e < 2097152ul) { src = xin + e;              dst = xin_h + e; }
    else               { src = w_ip + (e - 2097152); dst = w_h + WH_IP + (e - 2097152); }
    float4 f0 = ((const float4*)src)[0];
    float4 f1 = ((const float4*)src)[1];
    __half2 h[4];
    h[0] = __floats2half2_rn(f0.x, f0.y);
    h[1] = __floats2half2_rn(f0.z, f0.w);
    h[2] = __floats2half2_rn(f1.x, f1.y);
    h[3] = __floats2half2_rn(f1.z, f1.w);
    *(uint4*)dst = *(uint4*)h;
}

// ---------------------------------------------------------------------------
// cvt phase 2: remaining 7 weights (1245184 elts -> 608 blocks).
// ---------------------------------------------------------------------------
__global__ void __launch_bounds__(256) cvt_p2_kernel(
    const float* __restrict__ w_op,
    const float* __restrict__ w_p2s, const float* __restrict__ w_s2p,
    const float* __restrict__ w_tw1, const float* __restrict__ w_tw2,
    const float* __restrict__ w_fw1, const float* __restrict__ w_fw2,
    __half* __restrict__ w_h)
{
    const size_t e = ((size_t)blockIdx.x * 256 + threadIdx.x) * 8;
    const float* src; __half* dst;
    if      (e <  65536ul)  { src = w_op  + e;            dst = w_h + WH_OP  + e; }
    else if (e < 131072ul)  { src = w_p2s + (e -  65536); dst = w_h + WH_P2S + (e -  65536); }
    else if (e < 196608ul)  { src = w_s2p + (e - 131072); dst = w_h + WH_S2P + (e - 131072); }
    else if (e < 589824ul)  { src = w_tw1 + (e - 196608); dst = w_h + WH_TW1 + (e - 196608); }
    else if (e < 720896ul)  { src = w_tw2 + (e - 589824); dst = w_h + WH_TW2 + (e - 589824); }
    else if (e < 983040ul)  { src = w_fw1 + (e - 720896); dst = w_h + WH_FW1 + (e - 720896); }
    else                    { src = w_fw2 + (e - 983040); dst = w_h + WH_FW2 + (e - 983040); }
    float4 f0 = ((const float4*)src)[0];
    float4 f1 = ((const float4*)src)[1];
    __half2 h[4];
    h[0] = __floats2half2_rn(f0.x, f0.y);
    h[1] = __floats2half2_rn(f0.z, f0.w);
    h[2] = __floats2half2_rn(f1.x, f1.y);
    h[3] = __floats2half2_rn(f1.z, f1.w);
    *(uint4*)dst = *(uint4*)h;
}

// ---------------------------------------------------------------------------
// FP16 GEMM, templated BM in {128, 64} (unchanged).
// ---------------------------------------------------------------------------
#define ISSUE_TILE(k0, sidx)                                                   \
    {                                                                          \
        _Pragma("unroll")                                                      \
        for (int i = 0; i < BM / 64; i++) {                                    \
            int idx = tid + i * 256;                                           \
            int row = idx >> 2;                                                \
            int ch  = idx & 3;                                                 \
            uint32_t da = smem_base + (uint32_t)(((sidx) * STAGE + row * 36 + ch * 4) * 4); \
            const __half* ga = A + (size_t)(bm + row) * lda + (k0) + ch * 8;   \
            asm volatile("cp.async.cg.shared.global [%0], [%1], 16;" :: "r"(da), "l"(ga)); \
        }                                                                      \
        _Pragma("unroll")                                                      \
        for (int i = 0; i < 2; i++) {                                          \
            int idx = tid + i * 256;                                           \
            int row = idx >> 2;                                                \
            int ch  = idx & 3;                                                 \
            uint32_t db = smem_base + (uint32_t)(((sidx) * STAGE + A_TS + row * 36 + ch * 4) * 4); \
            const __half* gw = W + (size_t)(bn + row) * (size_t)K + (k0) + ch * 8; \
            asm volatile("cp.async.cg.shared.global [%0], [%1], 16;" :: "r"(db), "l"(gw)); \
        }                                                                      \
        asm volatile("cp.async.commit_group;");                                \
    }

template<int EPI, bool OUTH, int BM>
__global__ void __launch_bounds__(256, 2) mma_gemm(
    const __half* __restrict__ A, int lda,
    const __half* __restrict__ W,
    const float* __restrict__ bias,
    const float* __restrict__ addend, int ld_add,
    void* __restrict__ Cv, int ldc,
    int K)
{
    constexpr int MI    = BM / 32;
    constexpr int A_TS  = BM * 36;
    constexpr int STAGE = A_TS + 128 * 36;

    extern __shared__ uint32_t sm[];
    const uint32_t smem_base = (uint32_t)__cvta_generic_to_shared(sm);

    const int tid  = threadIdx.x;
    const int bm   = blockIdx.y * BM;
    const int bn   = blockIdx.x * 128;
    const int wid  = tid >> 5;
    const int lane = tid & 31;
    const int wm   = (wid & 1) * (BM / 2);
    const int wn32 = (wid >> 1) * 32;
    const int r    = lane >> 2;
    const int t    = lane & 3;

    float acc[MI][4][4];
    #pragma unroll
    for (int mi = 0; mi < MI; mi++)
        #pragma unroll
        for (int ni = 0; ni < 4; ni++)
            #pragma unroll
            for (int c = 0; c < 4; c++) acc[mi][ni][c] = 0.0f;

    const int ntiles = K >> 5;

    ISSUE_TILE(0, 0);
    ISSUE_TILE(32, 1);

    int sidx = 0;
    for (int kt = 0; kt < ntiles; kt++) {
        if (kt == ntiles - 1) {
            asm volatile("cp.async.wait_group 0;");
        } else {
            asm volatile("cp.async.wait_group 1;");
        }
        __syncthreads();

        if (kt + 2 < ntiles) {
            int ws = sidx + 2; if (ws >= 3) ws -= 3;
            ISSUE_TILE((kt + 2) * 32, ws);
        }

        const uint32_t* Ab = sm + sidx * STAGE;
        const uint32_t* Bb = Ab + A_TS;

        #pragma unroll
        for (int ks = 0; ks < 2; ks++) {
            const int kb = ks * 8;
            uint32_t a[MI][4], b[4][2];
            #pragma unroll
            for (int mi = 0; mi < MI; mi++) {
                int idx = (wm + mi * 16 + r) * 36 + kb + t;
                a[mi][0] = Ab[idx];
                a[mi][1] = Ab[idx + 8 * 36];
                a[mi][2] = Ab[idx + 4];
                a[mi][3] = Ab[idx + 8 * 36 + 4];
            }
            #pragma unroll
            for (int ni = 0; ni < 4; ni++) {
                int idx = (wn32 + ni * 8 + r) * 36 + kb + t;
                b[ni][0] = Bb[idx];
                b[ni][1] = Bb[idx + 4];
            }
            #pragma unroll
            for (int mi = 0; mi < MI; mi++)
                #pragma unroll
                for (int ni = 0; ni < 4; ni++)
                    MMA_F16(acc[mi][ni], a[mi], b[ni]);
        }
        sidx++; if (sidx == 3) sidx = 0;
    }

    float* Cf = (float*)Cv;
    __half* Ch = (__half*)Cv;

    #pragma unroll
    for (int mi = 0; mi < MI; mi++) {
        const int row0 = bm + wm + mi * 16 + r;
        const int row1 = row0 + 8;
        #pragma unroll
        for (int ni = 0; ni < 4; ni++) {
            const int col = bn + wn32 + ni * 8 + 2 * t;
            const float2 bb = *(const float2*)(bias + col);
            float v00 = acc[mi][ni][0] + bb.x;
            float v01 = acc[mi][ni][1] + bb.y;
            float v10 = acc[mi][ni][2] + bb.x;
            float v11 = acc[mi][ni][3] + bb.y;
            if (EPI == 1) {
                const float2 r0 = *(const float2*)(addend + (size_t)row0 * ld_add + col);
                const float2 r1 = *(const float2*)(addend + (size_t)row1 * ld_add + col);
                v00 += r0.x; v01 += r0.y; v10 += r1.x; v11 += r1.y;
            }
            if (EPI == 2) {
                v00 = gelu_f(v00); v01 = gelu_f(v01);
                v10 = gelu_f(v10); v11 = gelu_f(v11);
            }
            if (EPI == 3) {
                const float2 r0 = *(const float2*)(addend + (size_t)row0 * ld_add + col);
                const float2 r1 = *(const float2*)(addend + (size_t)row1 * ld_add + col);
                v00 = r0.x + 0.3f * v00; v01 = r0.y + 0.3f * v01;
                v10 = r1.x + 0.3f * v10; v11 = r1.y + 0.3f * v11;
            }
            if (OUTH) {
                *(__half2*)(Ch + (size_t)row0 * ldc + col) = __floats2half2_rn(v00, v01);
                *(__half2*)(Ch + (size_t)row1 * ldc + col) = __floats2half2_rn(v10, v11);
            } else {
                *(float2*)(Cf + (size_t)row0 * ldc + col) = make_float2(v00, v01);
                *(float2*)(Cf + (size_t)row1 * ldc + col) = make_float2(v10, v11);
            }
        }
    }
}

#define GEMM_SMEM_128 (3 * (128 + 128) * 36 * 4)   // 110592 B
#define GEMM_SMEM_64  (3 * (64 + 128) * 36 * 4)    // 82944 B

// ---------------------------------------------------------------------------
// FP16 mma causal flash-attention (unchanged).
// ---------------------------------------------------------------------------
#define KV_STG_U32 4608
#define ATTN_SMEM (2 * KV_STG_U32 * 4)     // 36864 B

#define AT_ISSUE(jt, s)                                                        \
    {                                                                          \
        const int _j0 = (jt) * 64;                                             \
        _Pragma("unroll")                                                      \
        for (int _i = 0; _i < 2; _i++) {                                       \
            int _idx = tid + _i * 256;                                         \
            int _row = _idx >> 3;                                              \
            int _ch  = _idx & 7;                                               \
            const __half* _kp = baseh + (size_t)(_j0 + _row) * 768 + 256 + h * 64 + _ch * 8; \
            uint32_t _dk = smem_base + (uint32_t)(((s) * KV_STG_U32 + _row * 36 + _ch * 4) * 4); \
            asm volatile("cp.async.cg.shared.global [%0], [%1], 16;" :: "r"(_dk), "l"(_kp)); \
            uint32_t _dv = smem_base + (uint32_t)(((s) * KV_STG_U32 + 2304 + _row * 36 + _ch * 4) * 4); \
            asm volatile("cp.async.cg.shared.global [%0], [%1], 16;" :: "r"(_dv), "l"(_kp + 256)); \
        }                                                                      \
        asm volatile("cp.async.commit_group;");                                \
    }

__global__ void __launch_bounds__(256) attn_mma_kernel(
    const __half* __restrict__ qkvh, __half* __restrict__ attn_out)
{
    extern __shared__ uint32_t dsm[];
    const uint32_t smem_base = (uint32_t)__cvta_generic_to_shared(dsm);

    const int bh = blockIdx.y;
    const int b  = bh >> 2;
    const int h  = bh & 3;
    const int qx = gridDim.x - 1 - blockIdx.x;
    const int qbase = qx * 128;
    const int tid  = threadIdx.x;
    const int wid  = tid >> 5;
    const int lane = tid & 31;
    const int r    = lane >> 2;
    const int t    = lane & 3;
    const __half* baseh = qkvh + (size_t)b * T_SEQ * 768;

    const int qrow0 = qbase + wid * 16 + r;
    const int qrow1 = qrow0 + 8;

    uint32_t aq[4][4];
    {
        const __half* q0 = baseh + (size_t)qrow0 * 768 + h * 64;
        const __half* q1 = baseh + (size_t)qrow1 * 768 + h * 64;
        #pragma unroll
        for (int ks = 0; ks < 4; ks++) {
            aq[ks][0] = *(const uint32_t*)(q0 + ks * 16 + 2 * t);
            aq[ks][1] = *(const uint32_t*)(q1 + ks * 16 + 2 * t);
            aq[ks][2] = *(const uint32_t*)(q0 + ks * 16 + 8 + 2 * t);
            aq[ks][3] = *(const uint32_t*)(q1 + ks * 16 + 8 + 2 * t);
        }
    }

    float oacc[8][4];
    #pragma unroll
    for (int ni = 0; ni < 8; ni++)
        #pragma unroll
        for (int c = 0; c < 4; c++) oacc[ni][c] = 0.0f;
    float lsum0 = 0.0f, lsum1 = 0.0f;

    const int ntiles   = 2 * qx + 2;
    const int wrow_max = qbase + wid * 16 + 15;
    const unsigned FULL = 0xffffffffu;

    AT_ISSUE(0, 0);

    for (int jt = 0; jt < ntiles; jt++) {
        const int j0 = jt * 64;
        asm volatile("cp.async.wait_group 0;");
        __syncthreads();

        if (jt + 1 < ntiles) AT_ISSUE(jt + 1, (jt + 1) & 1);

        if (j0 > wrow_max) continue;

        const uint32_t* Ks32 = dsm + (jt & 1) * KV_STG_U32;
        const __half*   Vh   = (const __half*)(Ks32 + 2304);

        float sc[8][4];
        #pragma unroll
        for (int ni = 0; ni < 8; ni++)
            #pragma unroll
            for (int c = 0; c < 4; c++) sc[ni][c] = 0.0f;
        #pragma unroll
        for (int ks = 0; ks < 4; ks++) {
            #pragma unroll
            for (int ni = 0; ni < 8; ni++) {
                uint32_t bfr[2];
                const int key = ni * 8 + r;
                bfr[0] = Ks32[key * 36 + ks * 8 + t];
                bfr[1] = Ks32[key * 36 + ks * 8 + t + 4];
                MMA_F16(sc[ni], aq[ks], bfr);
            }
        }

        #pragma unroll
        for (int ni = 0; ni < 8; ni++) {
            const int col0 = j0 + ni * 8 + 2 * t;
            float p0 = (col0     <= qrow0) ? fexp_s8(sc[ni][0]) : 0.0f;
            float p1 = (col0 + 1 <= qrow0) ? fexp_s8(sc[ni][1]) : 0.0f;
            float p2 = (col0     <= qrow1) ? fexp_s8(sc[ni][2]) : 0.0f;
            float p3 = (col0 + 1 <= qrow1) ? fexp_s8(sc[ni][3]) : 0.0f;
            lsum0 += p0 + p1;
            lsum1 += p2 + p3;
            sc[ni][0] = p0; sc[ni][1] = p1; sc[ni][2] = p2; sc[ni][3] = p3;
        }

        #pragma unroll
        for (int c = 0; c < 4; c++) {
            uint32_t ap[4];
            ap[0] = h2u(__floats2half2_rn(sc[2*c][0],   sc[2*c][1]));
            ap[1] = h2u(__floats2half2_rn(sc[2*c][2],   sc[2*c][3]));
            ap[2] = h2u(__floats2half2_rn(sc[2*c+1][0], sc[2*c+1][1]));
            ap[3] = h2u(__floats2half2_rn(sc[2*c+1][2], sc[2*c+1][3]));
            const __half* vp = Vh + (c * 16 + 2 * t) * 72;
            #pragma unroll
            for (int ni = 0; ni < 8; ni++) {
                const int n = ni * 8 + r;
                uint32_t bfr[2];
                bfr[0] = h2u(__halves2half2(vp[n],          vp[n + 72]));
                bfr[1] = h2u(__halves2half2(vp[n + 8 * 72], vp[n + 9 * 72]));
                MMA_F16(oacc[ni], ap, bfr);
            }
        }
    }

    lsum0 += __shfl_xor_sync(FULL, lsum0, 1);
    lsum0 += __shfl_xor_sync(FULL, lsum0, 2);
    lsum1 += __shfl_xor_sync(FULL, lsum1, 1);
    lsum1 += __shfl_xor_sync(FULL, lsum1, 2);
    const float inv0 = 1.0f / lsum0;
    const float inv1 = 1.0f / lsum1;

    __half* op0 = attn_out + ((size_t)b * T_SEQ + qrow0) * 256 + h * 64;
    __half* op1 = attn_out + ((size_t)b * T_SEQ + qrow1) * 256 + h * 64;
    #pragma unroll
    for (int ni = 0; ni < 8; ni++) {
        *(__half2*)(op0 + ni * 8 + 2 * t) = __floats2half2_rn(oacc[ni][0] * inv0, oacc[ni][1] * inv0);
        *(__half2*)(op1 + ni * 8 + 2 * t) = __floats2half2_rn(oacc[ni][2] * inv1, oacc[ni][3] * inv1);
    }
}

// ---------------------------------------------------------------------------
// LayerNorm, 2 rows/warp; optional fp16 shadow output (unchanged).
// ---------------------------------------------------------------------------
__global__ void __launch_bounds__(256) ln_warp_kernel(
    const float* __restrict__ in, long ld_in,
    const float* __restrict__ gamma, const float* __restrict__ beta,
    float* __restrict__ out, long ld_out, int nrows,
    __half* __restrict__ out_h)
{
    const int wid = threadIdx.x >> 5, lane = threadIdx.x & 31;
    const int rowA = blockIdx.x * 16 + wid * 2;
    const int rowB = rowA + 1;
    if (rowA >= nrows) return;
    const bool hasB = (rowB < nrows);

    const float* ipA = in + (size_t)rowA * ld_in + lane * 8;
    const float* ipB = in + (size_t)(hasB ? rowB : rowA) * ld_in + lane * 8;
    float4 a0 = ((const float4*)ipA)[0];
    float4 a1 = ((const float4*)ipA)[1];
    float4 b0 = ((const float4*)ipB)[0];
    float4 b1 = ((const float4*)ipB)[1];

    float sA  = a0.x + a0.y + a0.z + a0.w + a1.x + a1.y + a1.z + a1.w;
    float qA  = a0.x*a0.x + a0.y*a0.y + a0.z*a0.z + a0.w*a0.w
              + a1.x*a1.x + a1.y*a1.y + a1.z*a1.z + a1.w*a1.w;
    float sB  = b0.x + b0.y + b0.z + b0.w + b1.x + b1.y + b1.z + b1.w;
    float qB  = b0.x*b0.x + b0.y*b0.y + b0.z*b0.z + b0.w*b0.w
              + b1.x*b1.x + b1.y*b1.y + b1.z*b1.z + b1.w*b1.w;
    #pragma unroll
    for (int o = 16; o > 0; o >>= 1) {
        sA += __shfl_xor_sync(0xffffffffu, sA, o);
        sB += __shfl_xor_sync(0xffffffffu, sB, o);
        qA += __shfl_xor_sync(0xffffffffu, qA, o);
        qB += __shfl_xor_sync(0xffffffffu, qB, o);
    }
    const float mA = sA * (1.0f / 256.0f);
    const float vA = qA * (1.0f / 256.0f) - mA * mA;
    const float rA = rsqrtf(vA + 1e-5f);
    const float mB = sB * (1.0f / 256.0f);
    const float vB = qB * (1.0f / 256.0f) - mB * mB;
    const float rB = rsqrtf(vB + 1e-5f);

    const float4 g0 = ((const float4*)(gamma + lane * 8))[0];
    const float4 g1 = ((const float4*)(gamma + lane * 8))[1];
    const float4 be0 = ((const float4*)(beta  + lane * 8))[0];
    const float4 be1 = ((const float4*)(beta  + lane * 8))[1];

    float4 o0, o1;
    o0.x = (a0.x - mA) * rA * g0.x + be0.x;
    o0.y = (a0.y - mA) * rA * g0.y + be0.y;
    o0.z = (a0.z - mA) * rA * g0.z + be0.z;
    o0.w = (a0.w - mA) * rA * g0.w + be0.w;
    o1.x = (a1.x - mA) * rA * g1.x + be1.x;
    o1.y = (a1.y - mA) * rA * g1.y + be1.y;
    o1.z = (a1.z - mA) * rA * g1.z + be1.z;
    o1.w = (a1.w - mA) * rA * g1.w + be1.w;
    float* opA = out + (size_t)rowA * ld_out + lane * 8;
    ((float4*)opA)[0] = o0;
    ((float4*)opA)[1] = o1;
    if (out_h) {
        __half2 hh[4];
        hh[0] = __floats2half2_rn(o0.x, o0.y);
        hh[1] = __floats2half2_rn(o0.z, o0.w);
        hh[2] = __floats2half2_rn(o1.x, o1.y);
        hh[3] = __floats2half2_rn(o1.z, o1.w);
        *(uint4*)(out_h + (size_t)rowA * ld_out + lane * 8) = *(uint4*)hh;
    }

    if (hasB) {
        float4 p0, p1;
        p0.x = (b0.x - mB) * rB * g0.x + be0.x;
        p0.y = (b0.y - mB) * rB * g0.y + be0.y;
        p0.z = (b0.z - mB) * rB * g0.z + be0.z;
        p0.w = (b0.w - mB) * rB * g0.w + be0.w;
        p1.x = (b1.x - mB) * rB * g1.x + be1.x;
        p1.y = (b1.y - mB) * rB * g1.y + be1.y;
        p1.z = (b1.z - mB) * rB * g1.z + be1.z;
        p1.w = (b1.w - mB) * rB * g1.w + be1.w;
        float* opB = out + (size_t)rowB * ld_out + lane * 8;
        ((float4*)opB)[0] = p0;
        ((float4*)opB)[1] = p1;
        if (out_h) {
            __half2 hh[4];
            hh[0] = __floats2half2_rn(p0.x, p0.y);
            hh[1] = __floats2half2_rn(p0.z, p0.w);
            hh[2] = __floats2half2_rn(p1.x, p1.y);
            hh[3] = __floats2half2_rn(p1.z, p1.w);
            *(uint4*)(out_h + (size_t)rowB * ld_out + lane * 8) = *(uint4*)hh;
        }
    }
}

// ---------------------------------------------------------------------------
// Fused EMA + depthwise conv (unchanged).
// ---------------------------------------------------------------------------
__global__ void __launch_bounds__(256) ema_conv_kernel(
    const float* __restrict__ x, const float* __restrict__ cw,
    const float* __restrict__ cb, __half* __restrict__ comb_h,
    float* __restrict__ traj_out)
{
    const int b = blockIdx.x, chunk = blockIdx.y, d = threadIdx.x;
    const int t0 = chunk * 128;
    int start = t0 - 256; if (start < 0) start = 0;
    const float* xp = x + (size_t)b * 1024 * 256 + d;

    float w[8];
    #pragma unroll
    for (int i = 0; i < 8; i++) w[i] = cw[d * 8 + i];
    const float cbd = cb[d];

    float buf[8];
    #pragma unroll
    for (int i = 0; i < 8; i++) buf[i] = 0.0f;

    float c = 0.0f;
    for (int t = start; t < t0; t += 8) {
        #pragma unroll
        for (int p = 0; p < 8; p++) {
            float v = xp[(size_t)(t + p) * 256];
            c = fmaf(0.9f, c, 0.1f * v);
            buf[p] = v;
        }
    }

    __half* oe = comb_h + (size_t)b * 1024 * 768 + 512 + d;
    __half* oc = comb_h + (size_t)b * 1024 * 768 + 256 + d;
    for (int t = t0; t < t0 + 128; t += 8) {
        #pragma unroll
        for (int p = 0; p < 8; p++) {
            float v = xp[(size_t)(t + p) * 256];
            c = fmaf(0.9f, c, 0.1f * v);
            buf[p] = v;
            float r = cbd;
            #pragma unroll
            for (int q = 0; q < 8; q++)
                r = fmaf(w[q], buf[(p + 1 + q) & 7], r);
            oe[(size_t)(t + p) * 768] = __float2half_rn(c);
            oc[(size_t)(t + p) * 768] = __float2half_rn(r);
        }
    }
    if (chunk == 7) traj_out[b * 256 + d] = c;
}

// ---------------------------------------------------------------------------
// Scans over fp16 deltas (fp32 accumulate).
// ---------------------------------------------------------------------------
__global__ void __launch_bounds__(256) chunksum_kernel(
    const __half* __restrict__ deltas, float* __restrict__ csum)
{
    const int b = blockIdx.x, chunk = blockIdx.y, d = threadIdx.x;
    const __half* dp = deltas + ((size_t)b * 1024 + chunk * 128) * 256 + d;
    float s = 0.0f;
    #pragma unroll 8
    for (int t = 0; t < 128; t++) s += __half2float(dp[(size_t)t * 256]);
    csum[(b * 8 + chunk) * 256 + d] = s;
}

__global__ void __launch_bounds__(256) cumsum_kernel(
    const __half* __restrict__ deltas, const float* __restrict__ seq,
    const float* __restrict__ csum, float* __restrict__ states)
{
    const int b = blockIdx.x, chunk = blockIdx.y, d = threadIdx.x;
    float c = seq[b * 256 + d];
    for (int cc = 0; cc < 8; cc++)
        if (cc < chunk) c = fmaf(0.5f, csum[(b * 8 + cc) * 256 + d], c);
    const __half* dp = deltas + ((size_t)b * 1024 + chunk * 128) * 256 + d;
    float* sp = states + ((size_t)b * 1024 + chunk * 128) * 256 + d;
    #pragma unroll 8
    for (int t = 0; t < 128; t++) {
        c = fmaf(0.5f, __half2float(dp[(size_t)t * 256]), c);
        sp[(size_t)t * 256] = c;
    }
}

// ---------------------------------------------------------------------------
// Launch — fork/join side stream; split cvt overlaps weight conversion.
// ---------------------------------------------------------------------------
extern "C" void kernel_launch(void* const* d_in, const int* in_sizes, int n_in,
                              void* d_out, int out_size)
{
    const float* x_in       = (const float*)d_in[0];
    const float* seq_state  = (const float*)d_in[1];
    const float* in_proj_w  = (const float*)d_in[3];
    const float* in_proj_b  = (const float*)d_in[4];
    const float* out_proj_w = (const float*)d_in[5];
    const float* out_proj_b = (const float*)d_in[6];
    const float* conv_w     = (const float*)d_in[7];
    const float* conv_b     = (const float*)d_in[8];
    const float* p2s_w      = (const float*)d_in[9];
    const float* p2s_b      = (const float*)d_in[10];
    const float* s2p_w      = (const float*)d_in[11];
    const float* s2p_b      = (const float*)d_in[12];
    const float* tw1        = (const float*)d_in[13];
    const float* tb1        = (const float*)d_in[14];
    const float* tw2        = (const float*)d_in[15];
    const float* tb2        = (const float*)d_in[16];
    const float* fw1        = (const float*)d_in[17];
    const float* fb1        = (const float*)d_in[18];
    const float* fw2        = (const float*)d_in[19];
    const float* fb2        = (const float*)d_in[20];
    const float* ln1s = (const float*)d_in[21];
    const float* ln1b = (const float*)d_in[22];
    const float* ln2s = (const float*)d_in[23];
    const float* ln2b = (const float*)d_in[24];
    const float* ln3s = (const float*)d_in[25];
    const float* ln3b = (const float*)d_in[26];
    const float* ln4s = (const float*)d_in[27];
    const float* ln4b = (const float*)d_in[28];
    float* out = (float*)d_out;

    float* scr = nullptr;
    cudaGetSymbolAddress((void**)&scr, d_scratch);
    float*  tmp      = scr + OFF_TMP;
    float*  xb       = scr + OFF_X;
    float*  states   = scr + OFF_STATES;
    float*  csum     = scr + OFF_CSUM;
    __half* deltas_h = (__half*)(scr + OFF_DELTAS_H);
    __half* qkv_h    = (__half*)(scr + OFF_QKV_H);
    __half* xin_h    = (__half*)(scr + OFF_XIN_H);
    __half* attn_h   = (__half*)(scr + OFF_ATTN_H);
    __half* xb_h     = (__half*)(scr + OFF_XB_H);
    __half* comb_h   = (__half*)(scr + OFF_COMB_H);
    __half* hb_h     = (__half*)(scr + OFF_HB_H);
    __half* states_h = (__half*)(scr + OFF_STATES_H);
    __half* ffnin_h  = (__half*)(scr + OFF_FFNIN_H);
    __half* fbuf_h   = (__half*)(scr + OFF_FBUF_H);
    __half* w_h      = (__half*)(scr + OFF_WH);

    static cudaStream_t s2 = nullptr;
    static cudaEvent_t evA = nullptr, evB = nullptr, evC = nullptr, evD = nullptr;
    static cudaEvent_t evE = nullptr, evF = nullptr;
    static bool init_done = false;
    if (!init_done) {
        cudaFuncSetAttribute(mma_gemm<0,true,128>,  cudaFuncAttributeMaxDynamicSharedMemorySize, GEMM_SMEM_128);
        cudaFuncSetAttribute(mma_gemm<2,true,128>,  cudaFuncAttributeMaxDynamicSharedMemorySize, GEMM_SMEM_128);
        cudaFuncSetAttribute(mma_gemm<1,false,64>,  cudaFuncAttributeMaxDynamicSharedMemorySize, GEMM_SMEM_64);
        cudaFuncSetAttribute(mma_gemm<3,true,64>,   cudaFuncAttributeMaxDynamicSharedMemorySize, GEMM_SMEM_64);
        cudaFuncSetAttribute(mma_gemm<0,true,64>,   cudaFuncAttributeMaxDynamicSharedMemorySize, GEMM_SMEM_64);
        cudaFuncSetAttribute(attn_mma_kernel, cudaFuncAttributeMaxDynamicSharedMemorySize, ATTN_SMEM);
        cudaStreamCreateWithFlags(&s2, cudaStreamNonBlocking);
        cudaEventCreateWithFlags(&evA, cudaEventDisableTiming);
        cudaEventCreateWithFlags(&evB, cudaEventDisableTiming);
        cudaEventCreateWithFlags(&evC, cudaEventDisableTiming);
        cudaEventCreateWithFlags(&evD, cudaEventDisableTiming);
        cudaEventCreateWithFlags(&evE, cudaEventDisableTiming);
        cudaEventCreateWithFlags(&evF, cudaEventDisableTiming);
        init_done = true;
    }

    // 0a. convert x_in + w_ip (qkv inputs)
    cvt_p1_kernel<<<1120, 256>>>(x_in, in_proj_w, xin_h, w_h);
    // fork: remaining weights on side stream (overlaps qkv + attention)
    cudaEventRecord(evE, 0);
    cudaStreamWaitEvent(s2, evE, 0);
    cvt_p2_kernel<<<608, 256, 0, s2>>>(out_proj_w, p2s_w, s2p_w, tw1, tw2,
                                       fw1, fw2, w_h);
    cudaEventRecord(evF, s2);

    // 1. qkv = x @ in_proj_w^T + b
    mma_gemm<0,true,128><<<dim3(6, 64), 256, GEMM_SMEM_128>>>(xin_h, 256, w_h + WH_IP, in_proj_b,
                                                              nullptr, 0, qkv_h, 768, 256);
    // 2. causal attention
    attn_mma_kernel<<<dim3(8, 32), 256, ATTN_SMEM>>>(qkv_h, attn_h);
    cudaStreamWaitEvent(0, evF, 0);   // weights ready before out_proj
    // 3. out_proj + residual(x_in)
    mma_gemm<1,false,64><<<dim3(2, 128), 256, GEMM_SMEM_64>>>(attn_h, 256, w_h + WH_OP, out_proj_b,
                                                              x_in, 256, tmp, 256, 256);
    // 4. x = LN1(tmp)
    ln_warp_kernel<<<512, 256>>>(tmp, 256, ln1s, ln1b, xb, 256, 8192, xb_h);

    // fork: ema+conv (side) || p2s GEMM (main)
    cudaEventRecord(evA, 0);
    cudaStreamWaitEvent(s2, evA, 0);
    ema_conv_kernel<<<dim3(8, 8), 256, 0, s2>>>(xb, conv_w, conv_b, comb_h,
                                                out + (size_t)M_ROWS * 256 + 2048);
    cudaEventRecord(evB, s2);
    // 7. comb_h[:,0:256] = x + 0.3*(x @ p2s^T + b)
    mma_gemm<3,true,64><<<dim3(2, 128), 256, GEMM_SMEM_64>>>(xb_h, 256, w_h + WH_P2S, p2s_b,
                                                             xb, 256, comb_h, 768, 256);
    cudaStreamWaitEvent(0, evB, 0);

    // 8. h = gelu(comb @ tw1^T + b1)
    mma_gemm<2,true,128><<<dim3(4, 64), 256, GEMM_SMEM_128>>>(comb_h, 768, w_h + WH_TW1, tb1,
                                                              nullptr, 0, hb_h, 512, 768);
    // 9. deltas = h @ tw2^T + b2  (fp16)
    mma_gemm<0,true,64><<<dim3(2, 128), 256, GEMM_SMEM_64>>>(hb_h, 512, w_h + WH_TW2, tb2,
                                                             nullptr, 0, deltas_h, 256, 512);
    // 10. states = seq + 0.5*cumsum(deltas)
    chunksum_kernel<<<dim3(8, 8), 256>>>(deltas_h, csum);
    cumsum_kernel<<<dim3(8, 8), 256>>>(deltas_h, seq_state, csum, states);
    // 11. states = LN3(states)
    ln_warp_kernel<<<512, 256>>>(states, 256, ln3s, ln3b, states, 256, 8192, states_h);

    // fork: LN4 (side) || ffn chain (main)
    cudaEventRecord(evC, 0);
    cudaStreamWaitEvent(s2, evC, 0);
    ln_warp_kernel<<<1, 256, 0, s2>>>(states + (size_t)1023 * 256, (long)1024 * 256,
                                      ln4s, ln4b, out + (size_t)M_ROWS * 256, 256, 8, nullptr);
    cudaEventRecord(evD, s2);

    // 12. ffn_in = x + 0.3*(states @ s2p^T + b)
    mma_gemm<3,true,64><<<dim3(2, 128), 256, GEMM_SMEM_64>>>(states_h, 256, w_h + WH_S2P, s2p_b,
                                                             xb, 256, ffnin_h, 256, 256);
    // 13. f = gelu(ffn_in @ fw1^T + b1)
    mma_gemm<2,true,128><<<dim3(8, 64), 256, GEMM_SMEM_128>>>(ffnin_h, 256, w_h + WH_FW1, fb1,
                                                              nullptr, 0, fbuf_h, 1024, 256);
    // 14. tmp = x + f @ fw2^T + b2
    mma_gemm<1,false,64><<<dim3(2, 128), 256, GEMM_SMEM_64>>>(fbuf_h, 1024, w_h + WH_FW2, fb2,
                                                              xb, 256, tmp, 256, 1024);
    // 15. LN2 -> out
    ln_warp_kernel<<<512, 256>>>(tmp, 256, ln2s, ln2b, out, 256, 8192, nullptr);

    cudaStreamWaitEvent(0, evD, 0);
}

// round 16
// speedup vs baseline: 1.6917x; 1.0172x over previous
#include <cuda_runtime.h>
#include <cuda_fp16.h>
#include <math.h>
#include <stdint.h>

#define B_SZ   8
#define T_SEQ  1024
#define D_MOD  256
#define M_ROWS (B_SZ * T_SEQ)   // 8192

// ---------------------------------------------------------------------------
// Scratch layout (float units)
// ---------------------------------------------------------------------------
#define OFF_TMP      0ul          // [8192,256] fp32
#define OFF_X        2097152ul    // [8192,256] fp32
#define OFF_STATES   4194304ul    // [8192,256] fp32
#define OFF_DELTAS_H 6291456ul    // [8192,256] half
#define OFF_CSUM     8388608ul    // [64,256]   fp32
#define OFF_QKV_H    8404992ul    // [8192,768] half
#define OFF_XIN_H    11550720ul   // [8192,256] half
#define OFF_ATTN_H   12599296ul   // [8192,256] half
#define OFF_XB_H     13647872ul   // [8192,256] half
#define OFF_COMB_H   14696448ul   // [8192,768] half
#define OFF_HB_H     17842176ul   // [8192,512] half
#define OFF_STATES_H 19939328ul   // [8192,256] half
#define OFF_FFNIN_H  20987904ul   // [8192,256] half
#define OFF_FBUF_H   22036480ul   // [8192,1024] half
#define OFF_WH       26230784ul   // all weights, half
#define SCRATCH_TOTAL 26853376ul

// weight offsets within W_H (half units)
#define WH_IP   0
#define WH_OP   196608
#define WH_P2S  262144
#define WH_S2P  327680
#define WH_TW1  393216
#define WH_TW2  786432
#define WH_FW1  917504
#define WH_FW2  1179648

__device__ float d_scratch[SCRATCH_TOTAL];

__device__ __forceinline__ float gelu_f(float x) {
    return 0.5f * x * (1.0f + erff(x * 0.70710678118654752f));
}

#define MMA_F16(d, a, b) \
    asm volatile("mma.sync.aligned.m16n8k16.row.col.f32.f16.f16.f32 " \
                 "{%0,%1,%2,%3}, {%4,%5,%6,%7}, {%8,%9}, {%0,%1,%2,%3};" \
                 : "+f"(d[0]), "+f"(d[1]), "+f"(d[2]), "+f"(d[3]) \
                 : "r"(a[0]), "r"(a[1]), "r"(a[2]), "r"(a[3]), \
                   "r"(b[0]), "r"(b[1]))

// Fast exp(s/8): FMA-pipe only, no MUFU.
__device__ __forceinline__ float fexp_s8(float s) {
    const float y = s * 0.1803368801111244f;
    const float rnd = y + 12582912.0f;
    const int   i   = __float_as_int(rnd);
    const float nf  = rnd - 12582912.0f;
    const float f   = y - nf;
    float p = 1.3333558146e-3f;
    p = fmaf(p, f, 9.6181291076e-3f);
    p = fmaf(p, f, 5.5504108665e-2f);
    p = fmaf(p, f, 2.4022650696e-1f);
    p = fmaf(p, f, 6.9314718056e-1f);
    p = fmaf(p, f, 1.0f);
    const float scale = __int_as_float((i << 23) + 0x3f800000);
    return p * scale;
}

__device__ __forceinline__ uint32_t h2u(__half2 v) {
    return *(uint32_t*)&v;
}

// ---------------------------------------------------------------------------
// cvt phase 1: x_in + in_proj_w (2293760 elts -> 1120 blocks).
// ---------------------------------------------------------------------------
__global__ void __launch_bounds__(256) cvt_p1_kernel(
    const float* __restrict__ xin, const float* __restrict__ w_ip,
    __half* __restrict__ xin_h, __half* __restrict__ w_h)
{
    const size_t e = ((size_t)blockIdx.x * 256 + threadIdx.x) * 8;
    const float* src; __half* dst;
    if (e < 2097152ul) { src = xin + e;              dst = xin_h + e; }
    else               { src = w_ip + (e - 2097152); dst = w_h + WH_IP + (e - 2097152); }
    float4 f0 = ((const float4*)src)[0];
    float4 f1 = ((const float4*)src)[1];
    __half2 h[4];
    h[0] = __floats2half2_rn(f0.x, f0.y);
    h[1] = __floats2half2_rn(f0.z, f0.w);
    h[2] = __floats2half2_rn(f1.x, f1.y);
    h[3] = __floats2half2_rn(f1.z, f1.w);
    *(uint4*)dst = *(uint4*)h;
}

// ---------------------------------------------------------------------------
// cvt phase 2: remaining 7 weights (1245184 elts -> 608 blocks).
// ---------------------------------------------------------------------------
__global__ void __launch_bounds__(256) cvt_p2_kernel(
    const float* __restrict__ w_op,
    const float* __restrict__ w_p2s, const float* __restrict__ w_s2p,
    const float* __restrict__ w_tw1, const float* __restrict__ w_tw2,
    const float* __restrict__ w_fw1, const float* __restrict__ w_fw2,
    __half* __restrict__ w_h)
{
    const size_t e = ((size_t)blockIdx.x * 256 + threadIdx.x) * 8;
    const float* src; __half* dst;
    if      (e <  65536ul)  { src = w_op  + e;            dst = w_h + WH_OP  + e; }
    else if (e < 131072ul)  { src = w_p2s + (e -  65536); dst = w_h + WH_P2S + (e -  65536); }
    else if (e < 196608ul)  { src = w_s2p + (e - 131072); dst = w_h + WH_S2P + (e - 131072); }
    else if (e < 589824ul)  { src = w_tw1 + (e - 196608); dst = w_h + WH_TW1 + (e - 196608); }
    else if (e < 720896ul)  { src = w_tw2 + (e - 589824); dst = w_h + WH_TW2 + (e - 589824); }
    else if (e < 983040ul)  { src = w_fw1 + (e - 720896); dst = w_h + WH_FW1 + (e - 720896); }
    else                    { src = w_fw2 + (e - 983040); dst = w_h + WH_FW2 + (e - 983040); }
    float4 f0 = ((const float4*)src)[0];
    float4 f1 = ((const float4*)src)[1];
    __half2 h[4];
    h[0] = __floats2half2_rn(f0.x, f0.y);
    h[1] = __floats2half2_rn(f0.z, f0.w);
    h[2] = __floats2half2_rn(f1.x, f1.y);
    h[3] = __floats2half2_rn(f1.z, f1.w);
    *(uint4*)dst = *(uint4*)h;
}

// ---------------------------------------------------------------------------
// FP16 GEMM, templated BM in {128, 64} (unchanged).
// ---------------------------------------------------------------------------
#define ISSUE_TILE(k0, sidx)                                                   \
    {                                                                          \
        _Pragma("unroll")                                                      \
        for (int i = 0; i < BM / 64; i++) {                                    \
            int idx = tid + i * 256;                                           \
            int row = idx >> 2;                                                \
            int ch  = idx & 3;                                                 \
            uint32_t da = smem_base + (uint32_t)(((sidx) * STAGE + row * 36 + ch * 4) * 4); \
            const __half* ga = A + (size_t)(bm + row) * lda + (k0) + ch * 8;   \
            asm volatile("cp.async.cg.shared.global [%0], [%1], 16;" :: "r"(da), "l"(ga)); \
        }                                                                      \
        _Pragma("unroll")                                                      \
        for (int i = 0; i < 2; i++) {                                          \
            int idx = tid + i * 256;                                           \
            int row = idx >> 2;                                                \
            int ch  = idx & 3;                                                 \
            uint32_t db = smem_base + (uint32_t)(((sidx) * STAGE + A_TS + row * 36 + ch * 4) * 4); \
            const __half* gw = W + (size_t)(bn + row) * (size_t)K + (k0) + ch * 8; \
            asm volatile("cp.async.cg.shared.global [%0], [%1], 16;" :: "r"(db), "l"(gw)); \
        }                                                                      \
        asm volatile("cp.async.commit_group;");                                \
    }

template<int EPI, bool OUTH, int BM>
__global__ void __launch_bounds__(256, 2) mma_gemm(
    const __half* __restrict__ A, int lda,
    const __half* __restrict__ W,
    const float* __restrict__ bias,
    const float* __restrict__ addend, int ld_add,
    void* __restrict__ Cv, int ldc,
    int K)
{
    constexpr int MI    = BM / 32;
    constexpr int A_TS  = BM * 36;
    constexpr int STAGE = A_TS + 128 * 36;

    extern __shared__ uint32_t sm[];
    const uint32_t smem_base = (uint32_t)__cvta_generic_to_shared(sm);

    const int tid  = threadIdx.x;
    const int bm   = blockIdx.y * BM;
    const int bn   = blockIdx.x * 128;
    const int wid  = tid >> 5;
    const int lane = tid & 31;
    const int wm   = (wid & 1) * (BM / 2);
    const int wn32 = (wid >> 1) * 32;
    const int r    = lane >> 2;
    const int t    = lane & 3;

    float acc[MI][4][4];
    #pragma unroll
    for (int mi = 0; mi < MI; mi++)
        #pragma unroll
        for (int ni = 0; ni < 4; ni++)
            #pragma unroll
            for (int c = 0; c < 4; c++) acc[mi][ni][c] = 0.0f;

    const int ntiles = K >> 5;

    ISSUE_TILE(0, 0);
    ISSUE_TILE(32, 1);

    int sidx = 0;
    for (int kt = 0; kt < ntiles; kt++) {
        if (kt == ntiles - 1) {
            asm volatile("cp.async.wait_group 0;");
        } else {
            asm volatile("cp.async.wait_group 1;");
        }
        __syncthreads();

        if (kt + 2 < ntiles) {
            int ws = sidx + 2; if (ws >= 3) ws -= 3;
            ISSUE_TILE((kt + 2) * 32, ws);
        }

        const uint32_t* Ab = sm + sidx * STAGE;
        const uint32_t* Bb = Ab + A_TS;

        #pragma unroll
        for (int ks = 0; ks < 2; ks++) {
            const int kb = ks * 8;
            uint32_t a[MI][4], b[4][2];
            #pragma unroll
            for (int mi = 0; mi < MI; mi++) {
                int idx = (wm + mi * 16 + r) * 36 + kb + t;
                a[mi][0] = Ab[idx];
                a[mi][1] = Ab[idx + 8 * 36];
                a[mi][2] = Ab[idx + 4];
                a[mi][3] = Ab[idx + 8 * 36 + 4];
            }
            #pragma unroll
            for (int ni = 0; ni < 4; ni++) {
                int idx = (wn32 + ni * 8 + r) * 36 + kb + t;
                b[ni][0] = Bb[idx];
                b[ni][1] = Bb[idx + 4];
            }
            #pragma unroll
            for (int mi = 0; mi < MI; mi++)
                #pragma unroll
                for (int ni = 0; ni < 4; ni++)
                    MMA_F16(acc[mi][ni], a[mi], b[ni]);
        }
        sidx++; if (sidx == 3) sidx = 0;
    }

    float* Cf = (float*)Cv;
    __half* Ch = (__half*)Cv;

    #pragma unroll
    for (int mi = 0; mi < MI; mi++) {
        const int row0 = bm + wm + mi * 16 + r;
        const int row1 = row0 + 8;
        #pragma unroll
        for (int ni = 0; ni < 4; ni++) {
            const int col = bn + wn32 + ni * 8 + 2 * t;
            const float2 bb = *(const float2*)(bias + col);
            float v00 = acc[mi][ni][0] + bb.x;
            float v01 = acc[mi][ni][1] + bb.y;
            float v10 = acc[mi][ni][2] + bb.x;
            float v11 = acc[mi][ni][3] + bb.y;
            if (EPI == 1) {
                const float2 r0 = *(const float2*)(addend + (size_t)row0 * ld_add + col);
                const float2 r1 = *(const float2*)(addend + (size_t)row1 * ld_add + col);
                v00 += r0.x; v01 += r0.y; v10 += r1.x; v11 += r1.y;
            }
            if (EPI == 2) {
                v00 = gelu_f(v00); v01 = gelu_f(v01);
                v10 = gelu_f(v10); v11 = gelu_f(v11);
            }
            if (EPI == 3) {
                const float2 r0 = *(const float2*)(addend + (size_t)row0 * ld_add + col);
                const float2 r1 = *(const float2*)(addend + (size_t)row1 * ld_add + col);
                v00 = r0.x + 0.3f * v00; v01 = r0.y + 0.3f * v01;
                v10 = r1.x + 0.3f * v10; v11 = r1.y + 0.3f * v11;
            }
            if (OUTH) {
                *(__half2*)(Ch + (size_t)row0 * ldc + col) = __floats2half2_rn(v00, v01);
                *(__half2*)(Ch + (size_t)row1 * ldc + col) = __floats2half2_rn(v10, v11);
            } else {
                *(float2*)(Cf + (size_t)row0 * ldc + col) = make_float2(v00, v01);
                *(float2*)(Cf + (size_t)row1 * ldc + col) = make_float2(v10, v11);
            }
        }
    }
}

#define GEMM_SMEM_128 (3 * (128 + 128) * 36 * 4)   // 110592 B
#define GEMM_SMEM_64  (3 * (64 + 128) * 36 * 4)    // 82944 B

// ---------------------------------------------------------------------------
// FP16 mma causal flash-attention; PV B-fragments via ldmatrix.x4.trans
// (V stored [key][72] halves row-major; canonical transposed fragment layout
// matches the hand-built one verified in R12-R15).
// ---------------------------------------------------------------------------
#define KV_STG_U32 4608
#define ATTN_SMEM (2 * KV_STG_U32 * 4)     // 36864 B

#define AT_ISSUE(jt, s)                                                        \
    {                                                                          \
        const int _j0 = (jt) * 64;                                             \
        _Pragma("unroll")                                                      \
        for (int _i = 0; _i < 2; _i++) {                                       \
            int _idx = tid + _i * 256;                                         \
            int _row = _idx >> 3;                                              \
            int _ch  = _idx & 7;                                               \
            const __half* _kp = baseh + (size_t)(_j0 + _row) * 768 + 256 + h * 64 + _ch * 8; \
            uint32_t _dk = smem_base + (uint32_t)(((s) * KV_STG_U32 + _row * 36 + _ch * 4) * 4); \
            asm volatile("cp.async.cg.shared.global [%0], [%1], 16;" :: "r"(_dk), "l"(_kp)); \
            uint32_t _dv = smem_base + (uint32_t)(((s) * KV_STG_U32 + 2304 + _row * 36 + _ch * 4) * 4); \
            asm volatile("cp.async.cg.shared.global [%0], [%1], 16;" :: "r"(_dv), "l"(_kp + 256)); \
        }                                                                      \
        asm volatile("cp.async.commit_group;");                                \
    }

__global__ void __launch_bounds__(256) attn_mma_kernel(
    const __half* __restrict__ qkvh, __half* __restrict__ attn_out)
{
    extern __shared__ uint32_t dsm[];
    const uint32_t smem_base = (uint32_t)__cvta_generic_to_shared(dsm);

    const int bh = blockIdx.y;
    const int b  = bh >> 2;
    const int h  = bh & 3;
    const int qx = gridDim.x - 1 - blockIdx.x;
    const int qbase = qx * 128;
    const int tid  = threadIdx.x;
    const int wid  = tid >> 5;
    const int lane = tid & 31;
    const int r    = lane >> 2;
    const int t    = lane & 3;
    const __half* baseh = qkvh + (size_t)b * T_SEQ * 768;

    const int qrow0 = qbase + wid * 16 + r;
    const int qrow1 = qrow0 + 8;

    uint32_t aq[4][4];
    {
        const __half* q0 = baseh + (size_t)qrow0 * 768 + h * 64;
        const __half* q1 = baseh + (size_t)qrow1 * 768 + h * 64;
        #pragma unroll
        for (int ks = 0; ks < 4; ks++) {
            aq[ks][0] = *(const uint32_t*)(q0 + ks * 16 + 2 * t);
            aq[ks][1] = *(const uint32_t*)(q1 + ks * 16 + 2 * t);
            aq[ks][2] = *(const uint32_t*)(q0 + ks * 16 + 8 + 2 * t);
            aq[ks][3] = *(const uint32_t*)(q1 + ks * 16 + 8 + 2 * t);
        }
    }

    float oacc[8][4];
    #pragma unroll
    for (int ni = 0; ni < 8; ni++)
        #pragma unroll
        for (int c = 0; c < 4; c++) oacc[ni][c] = 0.0f;
    float lsum0 = 0.0f, lsum1 = 0.0f;

    const int ntiles   = 2 * qx + 2;
    const int wrow_max = qbase + wid * 16 + 15;
    const unsigned FULL = 0xffffffffu;
    const int mrow = lane & 7;          // ldmatrix row within 8x8
    const int mat  = lane >> 3;         // ldmatrix matrix index (0..3)

    AT_ISSUE(0, 0);

    for (int jt = 0; jt < ntiles; jt++) {
        const int j0 = jt * 64;
        asm volatile("cp.async.wait_group 0;");
        __syncthreads();

        if (jt + 1 < ntiles) AT_ISSUE(jt + 1, (jt + 1) & 1);

        if (j0 > wrow_max) continue;

        const uint32_t* Ks32 = dsm + (jt & 1) * KV_STG_U32;
        const uint32_t vbase = smem_base + (uint32_t)(((jt & 1) * KV_STG_U32 + 2304) * 4);

        // S = Q @ K^T
        float sc[8][4];
        #pragma unroll
        for (int ni = 0; ni < 8; ni++)
            #pragma unroll
            for (int c = 0; c < 4; c++) sc[ni][c] = 0.0f;
        #pragma unroll
        for (int ks = 0; ks < 4; ks++) {
            #pragma unroll
            for (int ni = 0; ni < 8; ni++) {
                uint32_t bfr[2];
                const int key = ni * 8 + r;
                bfr[0] = Ks32[key * 36 + ks * 8 + t];
                bfr[1] = Ks32[key * 36 + ks * 8 + t + 4];
                MMA_F16(sc[ni], aq[ks], bfr);
            }
        }

        // P = exp(S/8) with causal mask; accumulate row sums
        #pragma unroll
        for (int ni = 0; ni < 8; ni++) {
            const int col0 = j0 + ni * 8 + 2 * t;
            float p0 = (col0     <= qrow0) ? fexp_s8(sc[ni][0]) : 0.0f;
            float p1 = (col0 + 1 <= qrow0) ? fexp_s8(sc[ni][1]) : 0.0f;
            float p2 = (col0     <= qrow1) ? fexp_s8(sc[ni][2]) : 0.0f;
            float p3 = (col0 + 1 <= qrow1) ? fexp_s8(sc[ni][3]) : 0.0f;
            lsum0 += p0 + p1;
            lsum1 += p2 + p3;
            sc[ni][0] = p0; sc[ni][1] = p1; sc[ni][2] = p2; sc[ni][3] = p3;
        }

        // O += P @ V : B-fragments via ldmatrix.x4.trans (2 n-tiles per op)
        #pragma unroll
        for (int c = 0; c < 4; c++) {
            uint32_t ap[4];
            ap[0] = h2u(__floats2half2_rn(sc[2*c][0],   sc[2*c][1]));
            ap[1] = h2u(__floats2half2_rn(sc[2*c][2],   sc[2*c][3]));
            ap[2] = h2u(__floats2half2_rn(sc[2*c+1][0], sc[2*c+1][1]));
            ap[3] = h2u(__floats2half2_rn(sc[2*c+1][2], sc[2*c+1][3]));
            #pragma unroll
            for (int np = 0; np < 4; np++) {
                // matrices: 0 = (k0..7, n), 1 = (k8..15, n), 2/3 = same at n+8
                const uint32_t addr = vbase + (uint32_t)(
                    ((c * 16 + (mat & 1) * 8 + mrow) * 72
                     + np * 16 + (mat >> 1) * 8) * 2);
                uint32_t b0, b1, b2, b3;
                asm volatile(
                    "ldmatrix.sync.aligned.m8n8.x4.trans.shared.b16 "
                    "{%0,%1,%2,%3}, [%4];"
                    : "=r"(b0), "=r"(b1), "=r"(b2), "=r"(b3) : "r"(addr));
                uint32_t bfrA[2] = {b0, b1};
                uint32_t bfrB[2] = {b2, b3};
                MMA_F16(oacc[2 * np],     ap, bfrA);
                MMA_F16(oacc[2 * np + 1], ap, bfrB);
            }
        }
    }

    lsum0 += __shfl_xor_sync(FULL, lsum0, 1);
    lsum0 += __shfl_xor_sync(FULL, lsum0, 2);
    lsum1 += __shfl_xor_sync(FULL, lsum1, 1);
    lsum1 += __shfl_xor_sync(FULL, lsum1, 2);
    const float inv0 = 1.0f / lsum0;
    const float inv1 = 1.0f / lsum1;

    __half* op0 = attn_out + ((size_t)b * T_SEQ + qrow0) * 256 + h * 64;
    __half* op1 = attn_out + ((size_t)b * T_SEQ + qrow1) * 256 + h * 64;
    #pragma unroll
    for (int ni = 0; ni < 8; ni++) {
        *(__half2*)(op0 + ni * 8 + 2 * t) = __floats2half2_rn(oacc[ni][0] * inv0, oacc[ni][1] * inv0);
        *(__half2*)(op1 + ni * 8 + 2 * t) = __floats2half2_rn(oacc[ni][2] * inv1, oacc[ni][3] * inv1);
    }
}

// ---------------------------------------------------------------------------
// LayerNorm, 2 rows/warp; optional fp16 shadow output (unchanged).
// ---------------------------------------------------------------------------
__global__ void __launch_bounds__(256) ln_warp_kernel(
    const float* __restrict__ in, long ld_in,
    const float* __restrict__ gamma, const float* __restrict__ beta,
    float* __restrict__ out, long ld_out, int nrows,
    __half* __restrict__ out_h)
{
    const int wid = threadIdx.x >> 5, lane = threadIdx.x & 31;
    const int rowA = blockIdx.x * 16 + wid * 2;
    const int rowB = rowA + 1;
    if (rowA >= nrows) return;
    const bool hasB = (rowB < nrows);

    const float* ipA = in + (size_t)rowA * ld_in + lane * 8;
    const float* ipB = in + (size_t)(hasB ? rowB : rowA) * ld_in + lane * 8;
    float4 a0 = ((const float4*)ipA)[0];
    float4 a1 = ((const float4*)ipA)[1];
    float4 b0 = ((const float4*)ipB)[0];
    float4 b1 = ((const float4*)ipB)[1];

    float sA  = a0.x + a0.y + a0.z + a0.w + a1.x + a1.y + a1.z + a1.w;
    float qA  = a0.x*a0.x + a0.y*a0.y + a0.z*a0.z + a0.w*a0.w
              + a1.x*a1.x + a1.y*a1.y + a1.z*a1.z + a1.w*a1.w;
    float sB  = b0.x + b0.y + b0.z + b0.w + b1.x + b1.y + b1.z + b1.w;
    float qB  = b0.x*b0.x + b0.y*b0.y + b0.z*b0.z + b0.w*b0.w
              + b1.x*b1.x + b1.y*b1.y + b1.z*b1.z + b1.w*b1.w;
    #pragma unroll
    for (int o = 16; o > 0; o >>= 1) {
        sA += __shfl_xor_sync(0xffffffffu, sA, o);
        sB += __shfl_xor_sync(0xffffffffu, sB, o);
        qA += __shfl_xor_sync(0xffffffffu, qA, o);
        qB += __shfl_xor_sync(0xffffffffu, qB, o);
    }
    const float mA = sA * (1.0f / 256.0f);
    const float vA = qA * (1.0f / 256.0f) - mA * mA;
    const float rA = rsqrtf(vA + 1e-5f);
    const float mB = sB * (1.0f / 256.0f);
    const float vB = qB * (1.0f / 256.0f) - mB * mB;
    const float rB = rsqrtf(vB + 1e-5f);

    const float4 g0 = ((const float4*)(gamma + lane * 8))[0];
    const float4 g1 = ((const float4*)(gamma + lane * 8))[1];
    const float4 be0 = ((const float4*)(beta  + lane * 8))[0];
    const float4 be1 = ((const float4*)(beta  + lane * 8))[1];

    float4 o0, o1;
    o0.x = (a0.x - mA) * rA * g0.x + be0.x;
    o0.y = (a0.y - mA) * rA * g0.y + be0.y;
    o0.z = (a0.z - mA) * rA * g0.z + be0.z;
    o0.w = (a0.w - mA) * rA * g0.w + be0.w;
    o1.x = (a1.x - mA) * rA * g1.x + be1.x;
    o1.y = (a1.y - mA) * rA * g1.y + be1.y;
    o1.z = (a1.z - mA) * rA * g1.z + be1.z;
    o1.w = (a1.w - mA) * rA * g1.w + be1.w;
    float* opA = out + (size_t)rowA * ld_out + lane * 8;
    ((float4*)opA)[0] = o0;
    ((float4*)opA)[1] = o1;
    if (out_h) {
        __half2 hh[4];
        hh[0] = __floats2half2_rn(o0.x, o0.y);
        hh[1] = __floats2half2_rn(o0.z, o0.w);
        hh[2] = __floats2half2_rn(o1.x, o1.y);
        hh[3] = __floats2half2_rn(o1.z, o1.w);
        *(uint4*)(out_h + (size_t)rowA * ld_out + lane * 8) = *(uint4*)hh;
    }

    if (hasB) {
        float4 p0, p1;
        p0.x = (b0.x - mB) * rB * g0.x + be0.x;
        p0.y = (b0.y - mB) * rB * g0.y + be0.y;
        p0.z = (b0.z - mB) * rB * g0.z + be0.z;
        p0.w = (b0.w - mB) * rB * g0.w + be0.w;
        p1.x = (b1.x - mB) * rB * g1.x + be1.x;
        p1.y = (b1.y - mB) * rB * g1.y + be1.y;
        p1.z = (b1.z - mB) * rB * g1.z + be1.z;
        p1.w = (b1.w - mB) * rB * g1.w + be1.w;
        float* opB = out + (size_t)rowB * ld_out + lane * 8;
        ((float4*)opB)[0] = p0;
        ((float4*)opB)[1] = p1;
        if (out_h) {
            __half2 hh[4];
            hh[0] = __floats2half2_rn(p0.x, p0.y);
            hh[1] = __floats2half2_rn(p0.z, p0.w);
            hh[2] = __floats2half2_rn(p1.x, p1.y);
            hh[3] = __floats2half2_rn(p1.z, p1.w);
            *(uint4*)(out_h + (size_t)rowB * ld_out + lane * 8) = *(uint4*)hh;
        }
    }
}

// ---------------------------------------------------------------------------
// Fused EMA + depthwise conv (unchanged).
// ---------------------------------------------------------------------------
__global__ void __launch_bounds__(256) ema_conv_kernel(
    const float* __restrict__ x, const float* __restrict__ cw,
    const float* __restrict__ cb, __half* __restrict__ comb_h,
    float* __restrict__ traj_out)
{
    const int b = blockIdx.x, chunk = blockIdx.y, d = threadIdx.x;
    const int t0 = chunk * 128;
    int start = t0 - 256; if (start < 0) start = 0;
    const float* xp = x + (size_t)b * 1024 * 256 + d;

    float w[8];
    #pragma unroll
    for (int i = 0; i < 8; i++) w[i] = cw[d * 8 + i];
    const float cbd = cb[d];

    float buf[8];
    #pragma unroll
    for (int i = 0; i < 8; i++) buf[i] = 0.0f;

    float c = 0.0f;
    for (int t = start; t < t0; t += 8) {
        #pragma unroll
        for (int p = 0; p < 8; p++) {
            float v = xp[(size_t)(t + p) * 256];
            c = fmaf(0.9f, c, 0.1f * v);
            buf[p] = v;
        }
    }

    __half* oe = comb_h + (size_t)b * 1024 * 768 + 512 + d;
    __half* oc = comb_h + (size_t)b * 1024 * 768 + 256 + d;
    for (int t = t0; t < t0 + 128; t += 8) {
        #pragma unroll
        for (int p = 0; p < 8; p++) {
            float v = xp[(size_t)(t + p) * 256];
            c = fmaf(0.9f, c, 0.1f * v);
            buf[p] = v;
            float r = cbd;
            #pragma unroll
            for (int q = 0; q < 8; q++)
                r = fmaf(w[q], buf[(p + 1 + q) & 7], r);
            oe[(size_t)(t + p) * 768] = __float2half_rn(c);
            oc[(size_t)(t + p) * 768] = __float2half_rn(r);
        }
    }
    if (chunk == 7) traj_out[b * 256 + d] = c;
}

// ---------------------------------------------------------------------------
// Scans over fp16 deltas (fp32 accumulate).
// ---------------------------------------------------------------------------
__global__ void __launch_bounds__(256) chunksum_kernel(
    const __half* __restrict__ deltas, float* __restrict__ csum)
{
    const int b = blockIdx.x, chunk = blockIdx.y, d = threadIdx.x;
    const __half* dp = deltas + ((size_t)b * 1024 + chunk * 128) * 256 + d;
    float s = 0.0f;
    #pragma unroll 8
    for (int t = 0; t < 128; t++) s += __half2float(dp[(size_t)t * 256]);
    csum[(b * 8 + chunk) * 256 + d] = s;
}

__global__ void __launch_bounds__(256) cumsum_kernel(
    const __half* __restrict__ deltas, const float* __restrict__ seq,
    const float* __restrict__ csum, float* __restrict__ states)
{
    const int b = blockIdx.x, chunk = blockIdx.y, d = threadIdx.x;
    float c = seq[b * 256 + d];
    for (int cc = 0; cc < 8; cc++)
        if (cc < chunk) c = fmaf(0.5f, csum[(b * 8 + cc) * 256 + d], c);
    const __half* dp = deltas + ((size_t)b * 1024 + chunk * 128) * 256 + d;
    float* sp = states + ((size_t)b * 1024 + chunk * 128) * 256 + d;
    #pragma unroll 8
    for (int t = 0; t < 128; t++) {
        c = fmaf(0.5f, __half2float(dp[(size_t)t * 256]), c);
        sp[(size_t)t * 256] = c;
    }
}

// ---------------------------------------------------------------------------
// Launch — fork/join side stream; split cvt overlaps weight conversion.
// ---------------------------------------------------------------------------
extern "C" void kernel_launch(void* const* d_in, const int* in_sizes, int n_in,
                              void* d_out, int out_size)
{
    const float* x_in       = (const float*)d_in[0];
    const float* seq_state  = (const float*)d_in[1];
    const float* in_proj_w  = (const float*)d_in[3];
    const float* in_proj_b  = (const float*)d_in[4];
    const float* out_proj_w = (const float*)d_in[5];
    const float* out_proj_b = (const float*)d_in[6];
    const float* conv_w     = (const float*)d_in[7];
    const float* conv_b     = (const float*)d_in[8];
    const float* p2s_w      = (const float*)d_in[9];
    const float* p2s_b      = (const float*)d_in[10];
    const float* s2p_w      = (const float*)d_in[11];
    const float* s2p_b      = (const float*)d_in[12];
    const float* tw1        = (const float*)d_in[13];
    const float* tb1        = (const float*)d_in[14];
    const float* tw2        = (const float*)d_in[15];
    const float* tb2        = (const float*)d_in[16];
    const float* fw1        = (const float*)d_in[17];
    const float* fb1        = (const float*)d_in[18];
    const float* fw2        = (const float*)d_in[19];
    const float* fb2        = (const float*)d_in[20];
    const float* ln1s = (const float*)d_in[21];
    const float* ln1b = (const float*)d_in[22];
    const float* ln2s = (const float*)d_in[23];
    const float* ln2b = (const float*)d_in[24];
    const float* ln3s = (const float*)d_in[25];
    const float* ln3b = (const float*)d_in[26];
    const float* ln4s = (const float*)d_in[27];
    const float* ln4b = (const float*)d_in[28];
    float* out = (float*)d_out;

    float* scr = nullptr;
    cudaGetSymbolAddress((void**)&scr, d_scratch);
    float*  tmp      = scr + OFF_TMP;
    float*  xb       = scr + OFF_X;
    float*  states   = scr + OFF_STATES;
    float*  csum     = scr + OFF_CSUM;
    __half* deltas_h = (__half*)(scr + OFF_DELTAS_H);
    __half* qkv_h    = (__half*)(scr + OFF_QKV_H);
    __half* xin_h    = (__half*)(scr + OFF_XIN_H);
    __half* attn_h   = (__half*)(scr + OFF_ATTN_H);
    __half* xb_h     = (__half*)(scr + OFF_XB_H);
    __half* comb_h   = (__half*)(scr + OFF_COMB_H);
    __half* hb_h     = (__half*)(scr + OFF_HB_H);
    __half* states_h = (__half*)(scr + OFF_STATES_H);
    __half* ffnin_h  = (__half*)(scr + OFF_FFNIN_H);
    __half* fbuf_h   = (__half*)(scr + OFF_FBUF_H);
    __half* w_h      = (__half*)(scr + OFF_WH);

    static cudaStream_t s2 = nullptr;
    static cudaEvent_t evA = nullptr, evB = nullptr, evC = nullptr, evD = nullptr;
    static cudaEvent_t evE = nullptr, evF = nullptr;
    static bool init_done = false;
    if (!init_done) {
        cudaFuncSetAttribute(mma_gemm<0,true,128>,  cudaFuncAttributeMaxDynamicSharedMemorySize, GEMM_SMEM_128);
        cudaFuncSetAttribute(mma_gemm<2,true,128>,  cudaFuncAttributeMaxDynamicSharedMemorySize, GEMM_SMEM_128);
        cudaFuncSetAttribute(mma_gemm<1,false,64>,  cudaFuncAttributeMaxDynamicSharedMemorySize, GEMM_SMEM_64);
        cudaFuncSetAttribute(mma_gemm<3,true,64>,   cudaFuncAttributeMaxDynamicSharedMemorySize, GEMM_SMEM_64);
        cudaFuncSetAttribute(mma_gemm<0,true,64>,   cudaFuncAttributeMaxDynamicSharedMemorySize, GEMM_SMEM_64);
        cudaFuncSetAttribute(attn_mma_kernel, cudaFuncAttributeMaxDynamicSharedMemorySize, ATTN_SMEM);
        cudaStreamCreateWithFlags(&s2, cudaStreamNonBlocking);
        cudaEventCreateWithFlags(&evA, cudaEventDisableTiming);
        cudaEventCreateWithFlags(&evB, cudaEventDisableTiming);
        cudaEventCreateWithFlags(&evC, cudaEventDisableTiming);
        cudaEventCreateWithFlags(&evD, cudaEventDisableTiming);
        cudaEventCreateWithFlags(&evE, cudaEventDisableTiming);
        cudaEventCreateWithFlags(&evF, cudaEventDisableTiming);
        init_done = true;
    }

    // 0a. convert x_in + w_ip (qkv inputs)
    cvt_p1_kernel<<<1120, 256>>>(x_in, in_proj_w, xin_h, w_h);
    // fork: remaining weights on side stream (overlaps qkv + attention)
    cudaEventRecord(evE, 0);
    cudaStreamWaitEvent(s2, evE, 0);
    cvt_p2_kernel<<<608, 256, 0, s2>>>(out_proj_w, p2s_w, s2p_w, tw1, tw2,
                                       fw1, fw2, w_h);
    cudaEventRecord(evF, s2);

    // 1. qkv = x @ in_proj_w^T + b
    mma_gemm<0,true,128><<<dim3(6, 64), 256, GEMM_SMEM_128>>>(xin_h, 256, w_h + WH_IP, in_proj_b,
                                                              nullptr, 0, qkv_h, 768, 256);
    // 2. causal attention
    attn_mma_kernel<<<dim3(8, 32), 256, ATTN_SMEM>>>(qkv_h, attn_h);
    cudaStreamWaitEvent(0, evF, 0);   // weights ready before out_proj
    // 3. out_proj + residual(x_in)
    mma_gemm<1,false,64><<<dim3(2, 128), 256, GEMM_SMEM_64>>>(attn_h, 256, w_h + WH_OP, out_proj_b,
                                                              x_in, 256, tmp, 256, 256);
    // 4. x = LN1(tmp)
    ln_warp_kernel<<<512, 256>>>(tmp, 256, ln1s, ln1b, xb, 256, 8192, xb_h);

    // fork: ema+conv (side) || p2s GEMM (main)
    cudaEventRecord(evA, 0);
    cudaStreamWaitEvent(s2, evA, 0);
    ema_conv_kernel<<<dim3(8, 8), 256, 0, s2>>>(xb, conv_w, conv_b, comb_h,
                                                out + (size_t)M_ROWS * 256 + 2048);
    cudaEventRecord(evB, s2);
    // 7. comb_h[:,0:256] = x + 0.3*(x @ p2s^T + b)
    mma_gemm<3,true,64><<<dim3(2, 128), 256, GEMM_SMEM_64>>>(xb_h, 256, w_h + WH_P2S, p2s_b,
                                                             xb, 256, comb_h, 768, 256);
    cudaStreamWaitEvent(0, evB, 0);

    // 8. h = gelu(comb @ tw1^T + b1)
    mma_gemm<2,true,128><<<dim3(4, 64), 256, GEMM_SMEM_128>>>(comb_h, 768, w_h + WH_TW1, tb1,
                                                              nullptr, 0, hb_h, 512, 768);
    // 9. deltas = h @ tw2^T + b2  (fp16)
    mma_gemm<0,true,64><<<dim3(2, 128), 256, GEMM_SMEM_64>>>(hb_h, 512, w_h + WH_TW2, tb2,
                                                             nullptr, 0, deltas_h, 256, 512);
    // 10. states = seq + 0.5*cumsum(deltas)
    chunksum_kernel<<<dim3(8, 8), 256>>>(deltas_h, csum);
    cumsum_kernel<<<dim3(8, 8), 256>>>(deltas_h, seq_state, csum, states);
    // 11. states = LN3(states)
    ln_warp_kernel<<<512, 256>>>(states, 256, ln3s, ln3b, states, 256, 8192, states_h);

    // fork: LN4 (side) || ffn chain (main)
    cudaEventRecord(evC, 0);
    cudaStreamWaitEvent(s2, evC, 0);
    ln_warp_kernel<<<1, 256, 0, s2>>>(states + (size_t)1023 * 256, (long)1024 * 256,
                                      ln4s, ln4b, out + (size_t)M_ROWS * 256, 256, 8, nullptr);
    cudaEventRecord(evD, s2);

    // 12. ffn_in = x + 0.3*(states @ s2p^T + b)
    mma_gemm<3,true,64><<<dim3(2, 128), 256, GEMM_SMEM_64>>>(states_h, 256, w_h + WH_S2P, s2p_b,
                                                             xb, 256, ffnin_h, 256, 256);
    // 13. f = gelu(ffn_in @ fw1^T + b1)
    mma_gemm<2,true,128><<<dim3(8, 64), 256, GEMM_SMEM_128>>>(ffnin_h, 256, w_h + WH_FW1, fb1,
                                                              nullptr, 0, fbuf_h, 1024, 256);
    // 14. tmp = x + f @ fw2^T + b2
    mma_gemm<1,false,64><<<dim3(2, 128), 256, GEMM_SMEM_64>>>(fbuf_h, 1024, w_h + WH_FW2, fb2,
                                                              xb, 256, tmp, 256, 1024);
    // 15. LN2 -> out
    ln_warp_kernel<<<512, 256>>>(tmp, 256, ln2s, ln2b, out, 256, 8192, nullptr);

    cudaStreamWaitEvent(0, evD, 0);
}

// round 17
// speedup vs baseline: 1.7568x; 1.0385x over previous
#include <cuda_runtime.h>
#include <cuda_fp16.h>
#include <math.h>
#include <stdint.h>

#define B_SZ   8
#define T_SEQ  1024
#define D_MOD  256
#define M_ROWS (B_SZ * T_SEQ)   // 8192

// ---------------------------------------------------------------------------
// Scratch layout (float units)
// ---------------------------------------------------------------------------
#define OFF_TMP      0ul          // [8192,256] fp32
#define OFF_X        2097152ul    // [8192,256] fp32
#define OFF_STATES   4194304ul    // [8192,256] fp32
#define OFF_DELTAS_H 6291456ul    // [8192,256] half
#define OFF_CSUM     8388608ul    // [64,256]   fp32
#define OFF_QKV_H    8404992ul    // [8192,768] half
#define OFF_XIN_H    11550720ul   // [8192,256] half
#define OFF_ATTN_H   12599296ul   // [8192,256] half
#define OFF_XB_H     13647872ul   // [8192,256] half
#define OFF_COMB_H   14696448ul   // [8192,768] half
#define OFF_HB_H     17842176ul   // [8192,512] half
#define OFF_STATES_H 19939328ul   // [8192,256] half
#define OFF_FFNIN_H  20987904ul   // [8192,256] half
#define OFF_FBUF_H   22036480ul   // [8192,1024] half
#define OFF_WH       26230784ul   // all weights, half (1441792 halves = 720896 floats)
#define OFF_APART    26951680ul   // [2][8192,256] half partial O (2097152 floats)
#define OFF_LSUM     29048832ul   // [2][8,4,1024] fp32 partial sums (65536 floats)
#define SCRATCH_TOTAL 29114368ul

// weight offsets within W_H (half units)
#define WH_IP   0
#define WH_OP   196608
#define WH_P2S  262144
#define WH_S2P  327680
#define WH_TW1  393216
#define WH_TW2  786432
#define WH_FW1  917504
#define WH_FW2  1179648

__device__ float d_scratch[SCRATCH_TOTAL];

__device__ __forceinline__ float gelu_f(float x) {
    return 0.5f * x * (1.0f + erff(x * 0.70710678118654752f));
}

#define MMA_F16(d, a, b) \
    asm volatile("mma.sync.aligned.m16n8k16.row.col.f32.f16.f16.f32 " \
                 "{%0,%1,%2,%3}, {%4,%5,%6,%7}, {%8,%9}, {%0,%1,%2,%3};" \
                 : "+f"(d[0]), "+f"(d[1]), "+f"(d[2]), "+f"(d[3]) \
                 : "r"(a[0]), "r"(a[1]), "r"(a[2]), "r"(a[3]), \
                   "r"(b[0]), "r"(b[1]))

// Fast exp(s/8): FMA-pipe only, no MUFU.
__device__ __forceinline__ float fexp_s8(float s) {
    const float y = s * 0.1803368801111244f;
    const float rnd = y + 12582912.0f;
    const int   i   = __float_as_int(rnd);
    const float nf  = rnd - 12582912.0f;
    const float f   = y - nf;
    float p = 1.3333558146e-3f;
    p = fmaf(p, f, 9.6181291076e-3f);
    p = fmaf(p, f, 5.5504108665e-2f);
    p = fmaf(p, f, 2.4022650696e-1f);
    p = fmaf(p, f, 6.9314718056e-1f);
    p = fmaf(p, f, 1.0f);
    const float scale = __int_as_float((i << 23) + 0x3f800000);
    return p * scale;
}

__device__ __forceinline__ uint32_t h2u(__half2 v) {
    return *(uint32_t*)&v;
}

// ---------------------------------------------------------------------------
// cvt phase 1: x_in + in_proj_w (2293760 elts -> 1120 blocks).
// ---------------------------------------------------------------------------
__global__ void __launch_bounds__(256) cvt_p1_kernel(
    const float* __restrict__ xin, const float* __restrict__ w_ip,
    __half* __restrict__ xin_h, __half* __restrict__ w_h)
{
    const size_t e = ((size_t)blockIdx.x * 256 + threadIdx.x) * 8;
    const float* src; __half* dst;
    if (e < 2097152ul) { src = xin + e;              dst = xin_h + e; }
    else               { src = w_ip + (e - 2097152); dst = w_h + WH_IP + (e - 2097152); }
    float4 f0 = ((const float4*)src)[0];
    float4 f1 = ((const float4*)src)[1];
    __half2 h[4];
    h[0] = __floats2half2_rn(f0.x, f0.y);
    h[1] = __floats2half2_rn(f0.z, f0.w);
    h[2] = __floats2half2_rn(f1.x, f1.y);
    h[3] = __floats2half2_rn(f1.z, f1.w);
    *(uint4*)dst = *(uint4*)h;
}

// ---------------------------------------------------------------------------
// cvt phase 2: remaining 7 weights (1245184 elts -> 608 blocks).
// ---------------------------------------------------------------------------
__global__ void __launch_bounds__(256) cvt_p2_kernel(
    const float* __restrict__ w_op,
    const float* __restrict__ w_p2s, const float* __restrict__ w_s2p,
    const float* __restrict__ w_tw1, const float* __restrict__ w_tw2,
    const float* __restrict__ w_fw1, const float* __restrict__ w_fw2,
    __half* __restrict__ w_h)
{
    const size_t e = ((size_t)blockIdx.x * 256 + threadIdx.x) * 8;
    const float* src; __half* dst;
    if      (e <  65536ul)  { src = w_op  + e;            dst = w_h + WH_OP  + e; }
    else if (e < 131072ul)  { src = w_p2s + (e -  65536); dst = w_h + WH_P2S + (e -  65536); }
    else if (e < 196608ul)  { src = w_s2p + (e - 131072); dst = w_h + WH_S2P + (e - 131072); }
    else if (e < 589824ul)  { src = w_tw1 + (e - 196608); dst = w_h + WH_TW1 + (e - 196608); }
    else if (e < 720896ul)  { src = w_tw2 + (e - 589824); dst = w_h + WH_TW2 + (e - 589824); }
    else if (e < 983040ul)  { src = w_fw1 + (e - 720896); dst = w_h + WH_FW1 + (e - 720896); }
    else                    { src = w_fw2 + (e - 983040); dst = w_h + WH_FW2 + (e - 983040); }
    float4 f0 = ((const float4*)src)[0];
    float4 f1 = ((const float4*)src)[1];
    __half2 h[4];
    h[0] = __floats2half2_rn(f0.x, f0.y);
    h[1] = __floats2half2_rn(f0.z, f0.w);
    h[2] = __floats2half2_rn(f1.x, f1.y);
    h[3] = __floats2half2_rn(f1.z, f1.w);
    *(uint4*)dst = *(uint4*)h;
}

// ---------------------------------------------------------------------------
// FP16 GEMM, templated BM in {128, 64} (unchanged).
// ---------------------------------------------------------------------------
#define ISSUE_TILE(k0, sidx)                                                   \
    {                                                                          \
        _Pragma("unroll")                                                      \
        for (int i = 0; i < BM / 64; i++) {                                    \
            int idx = tid + i * 256;                                           \
            int row = idx >> 2;                                                \
            int ch  = idx & 3;                                                 \
            uint32_t da = smem_base + (uint32_t)(((sidx) * STAGE + row * 36 + ch * 4) * 4); \
            const __half* ga = A + (size_t)(bm + row) * lda + (k0) + ch * 8;   \
            asm volatile("cp.async.cg.shared.global [%0], [%1], 16;" :: "r"(da), "l"(ga)); \
        }                                                                      \
        _Pragma("unroll")                                                      \
        for (int i = 0; i < 2; i++) {                                          \
            int idx = tid + i * 256;                                           \
            int row = idx >> 2;                                                \
            int ch  = idx & 3;                                                 \
            uint32_t db = smem_base + (uint32_t)(((sidx) * STAGE + A_TS + row * 36 + ch * 4) * 4); \
            const __half* gw = W + (size_t)(bn + row) * (size_t)K + (k0) + ch * 8; \
            asm volatile("cp.async.cg.shared.global [%0], [%1], 16;" :: "r"(db), "l"(gw)); \
        }                                                                      \
        asm volatile("cp.async.commit_group;");                                \
    }

template<int EPI, bool OUTH, int BM>
__global__ void __launch_bounds__(256, 2) mma_gemm(
    const __half* __restrict__ A, int lda,
    const __half* __restrict__ W,
    const float* __restrict__ bias,
    const float* __restrict__ addend, int ld_add,
    void* __restrict__ Cv, int ldc,
    int K)
{
    constexpr int MI    = BM / 32;
    constexpr int A_TS  = BM * 36;
    constexpr int STAGE = A_TS + 128 * 36;

    extern __shared__ uint32_t sm[];
    const uint32_t smem_base = (uint32_t)__cvta_generic_to_shared(sm);

    const int tid  = threadIdx.x;
    const int bm   = blockIdx.y * BM;
    const int bn   = blockIdx.x * 128;
    const int wid  = tid >> 5;
    const int lane = tid & 31;
    const int wm   = (wid & 1) * (BM / 2);
    const int wn32 = (wid >> 1) * 32;
    const int r    = lane >> 2;
    const int t    = lane & 3;

    float acc[MI][4][4];
    #pragma unroll
    for (int mi = 0; mi < MI; mi++)
        #pragma unroll
        for (int ni = 0; ni < 4; ni++)
            #pragma unroll
            for (int c = 0; c < 4; c++) acc[mi][ni][c] = 0.0f;

    const int ntiles = K >> 5;

    ISSUE_TILE(0, 0);
    ISSUE_TILE(32, 1);

    int sidx = 0;
    for (int kt = 0; kt < ntiles; kt++) {
        if (kt == ntiles - 1) {
            asm volatile("cp.async.wait_group 0;");
        } else {
            asm volatile("cp.async.wait_group 1;");
        }
        __syncthreads();

        if (kt + 2 < ntiles) {
            int ws = sidx + 2; if (ws >= 3) ws -= 3;
            ISSUE_TILE((kt + 2) * 32, ws);
        }

        const uint32_t* Ab = sm + sidx * STAGE;
        const uint32_t* Bb = Ab + A_TS;

        #pragma unroll
        for (int ks = 0; ks < 2; ks++) {
            const int kb = ks * 8;
            uint32_t a[MI][4], b[4][2];
            #pragma unroll
            for (int mi = 0; mi < MI; mi++) {
                int idx = (wm + mi * 16 + r) * 36 + kb + t;
                a[mi][0] = Ab[idx];
                a[mi][1] = Ab[idx + 8 * 36];
                a[mi][2] = Ab[idx + 4];
                a[mi][3] = Ab[idx + 8 * 36 + 4];
            }
            #pragma unroll
            for (int ni = 0; ni < 4; ni++) {
                int idx = (wn32 + ni * 8 + r) * 36 + kb + t;
                b[ni][0] = Bb[idx];
                b[ni][1] = Bb[idx + 4];
            }
            #pragma unroll
            for (int mi = 0; mi < MI; mi++)
                #pragma unroll
                for (int ni = 0; ni < 4; ni++)
                    MMA_F16(acc[mi][ni], a[mi], b[ni]);
        }
        sidx++; if (sidx == 3) sidx = 0;
    }

    float* Cf = (float*)Cv;
    __half* Ch = (__half*)Cv;

    #pragma unroll
    for (int mi = 0; mi < MI; mi++) {
        const int row0 = bm + wm + mi * 16 + r;
        const int row1 = row0 + 8;
        #pragma unroll
        for (int ni = 0; ni < 4; ni++) {
            const int col = bn + wn32 + ni * 8 + 2 * t;
            const float2 bb = *(const float2*)(bias + col);
            float v00 = acc[mi][ni][0] + bb.x;
            float v01 = acc[mi][ni][1] + bb.y;
            float v10 = acc[mi][ni][2] + bb.x;
            float v11 = acc[mi][ni][3] + bb.y;
            if (EPI == 1) {
                const float2 r0 = *(const float2*)(addend + (size_t)row0 * ld_add + col);
                const float2 r1 = *(const float2*)(addend + (size_t)row1 * ld_add + col);
                v00 += r0.x; v01 += r0.y; v10 += r1.x; v11 += r1.y;
            }
            if (EPI == 2) {
                v00 = gelu_f(v00); v01 = gelu_f(v01);
                v10 = gelu_f(v10); v11 = gelu_f(v11);
            }
            if (EPI == 3) {
                const float2 r0 = *(const float2*)(addend + (size_t)row0 * ld_add + col);
                const float2 r1 = *(const float2*)(addend + (size_t)row1 * ld_add + col);
                v00 = r0.x + 0.3f * v00; v01 = r0.y + 0.3f * v01;
                v10 = r1.x + 0.3f * v10; v11 = r1.y + 0.3f * v11;
            }
            if (OUTH) {
                *(__half2*)(Ch + (size_t)row0 * ldc + col) = __floats2half2_rn(v00, v01);
                *(__half2*)(Ch + (size_t)row1 * ldc + col) = __floats2half2_rn(v10, v11);
            } else {
                *(float2*)(Cf + (size_t)row0 * ldc + col) = make_float2(v00, v01);
                *(float2*)(Cf + (size_t)row1 * ldc + col) = make_float2(v10, v11);
            }
        }
    }
}

#define GEMM_SMEM_128 (3 * (128 + 128) * 36 * 4)   // 110592 B
#define GEMM_SMEM_64  (3 * (64 + 128) * 36 * 4)    // 82944 B

// ---------------------------------------------------------------------------
// FP16 mma causal flash-attention, SPLIT-K over key tiles.
// grid (8, 32, 2): blockIdx.z = key-split; unnormalized partial O (fp16)
// + partial row-sums (fp32); exact additivity (no running max in softmax).
// ---------------------------------------------------------------------------
#define KV_STG_U32 4608
#define ATTN_SMEM (2 * KV_STG_U32 * 4)     // 36864 B

#define AT_ISSUE(jt, s)                                                        \
    {                                                                          \
        const int _j0 = (jt) * 64;                                             \
        _Pragma("unroll")                                                      \
        for (int _i = 0; _i < 2; _i++) {                                       \
            int _idx = tid + _i * 256;                                         \
            int _row = _idx >> 3;                                              \
            int _ch  = _idx & 7;                                               \
            const __half* _kp = baseh + (size_t)(_j0 + _row) * 768 + 256 + h * 64 + _ch * 8; \
            uint32_t _dk = smem_base + (uint32_t)(((s) * KV_STG_U32 + _row * 36 + _ch * 4) * 4); \
            asm volatile("cp.async.cg.shared.global [%0], [%1], 16;" :: "r"(_dk), "l"(_kp)); \
            uint32_t _dv = smem_base + (uint32_t)(((s) * KV_STG_U32 + 2304 + _row * 36 + _ch * 4) * 4); \
            asm volatile("cp.async.cg.shared.global [%0], [%1], 16;" :: "r"(_dv), "l"(_kp + 256)); \
        }                                                                      \
        asm volatile("cp.async.commit_group;");                                \
    }

__global__ void __launch_bounds__(256) attn_mma_kernel(
    const __half* __restrict__ qkvh, __half* __restrict__ opart,
    float* __restrict__ lsum_part)
{
    extern __shared__ uint32_t dsm[];
    const uint32_t smem_base = (uint32_t)__cvta_generic_to_shared(dsm);

    const int bh = blockIdx.y;
    const int b  = bh >> 2;
    const int h  = bh & 3;
    const int qx = gridDim.x - 1 - blockIdx.x;   // heavy-first
    const int sp = blockIdx.z;                   // key split
    const int qbase = qx * 128;
    const int tid  = threadIdx.x;
    const int wid  = tid >> 5;
    const int lane = tid & 31;
    const int r    = lane >> 2;
    const int t    = lane & 3;
    const __half* baseh = qkvh + (size_t)b * T_SEQ * 768;

    const int qrow0 = qbase + wid * 16 + r;
    const int qrow1 = qrow0 + 8;

    uint32_t aq[4][4];
    {
        const __half* q0 = baseh + (size_t)qrow0 * 768 + h * 64;
        const __half* q1 = baseh + (size_t)qrow1 * 768 + h * 64;
        #pragma unroll
        for (int ks = 0; ks < 4; ks++) {
            aq[ks][0] = *(const uint32_t*)(q0 + ks * 16 + 2 * t);
            aq[ks][1] = *(const uint32_t*)(q1 + ks * 16 + 2 * t);
            aq[ks][2] = *(const uint32_t*)(q0 + ks * 16 + 8 + 2 * t);
            aq[ks][3] = *(const uint32_t*)(q1 + ks * 16 + 8 + 2 * t);
        }
    }

    float oacc[8][4];
    #pragma unroll
    for (int ni = 0; ni < 8; ni++)
        #pragma unroll
        for (int c = 0; c < 4; c++) oacc[ni][c] = 0.0f;
    float lsum0 = 0.0f, lsum1 = 0.0f;

    const int nlocal   = qx + 1;          // tiles per split
    const int jt_begin = sp * nlocal;
    const int wrow_max = qbase + wid * 16 + 15;
    const unsigned FULL = 0xffffffffu;
    const int mrow = lane & 7;
    const int mat  = lane >> 3;

    AT_ISSUE(jt_begin, 0);

    for (int ji = 0; ji < nlocal; ji++) {
        const int jt = jt_begin + ji;
        const int j0 = jt * 64;
        asm volatile("cp.async.wait_group 0;");
        __syncthreads();

        if (ji + 1 < nlocal) AT_ISSUE(jt + 1, (ji + 1) & 1);

        if (j0 > wrow_max) continue;

        const uint32_t* Ks32 = dsm + (ji & 1) * KV_STG_U32;
        const uint32_t vbase = smem_base + (uint32_t)(((ji & 1) * KV_STG_U32 + 2304) * 4);

        float sc[8][4];
        #pragma unroll
        for (int ni = 0; ni < 8; ni++)
            #pragma unroll
            for (int c = 0; c < 4; c++) sc[ni][c] = 0.0f;
        #pragma unroll
        for (int ks = 0; ks < 4; ks++) {
            #pragma unroll
            for (int ni = 0; ni < 8; ni++) {
                uint32_t bfr[2];
                const int key = ni * 8 + r;
                bfr[0] = Ks32[key * 36 + ks * 8 + t];
                bfr[1] = Ks32[key * 36 + ks * 8 + t + 4];
                MMA_F16(sc[ni], aq[ks], bfr);
            }
        }

        #pragma unroll
        for (int ni = 0; ni < 8; ni++) {
            const int col0 = j0 + ni * 8 + 2 * t;
            float p0 = (col0     <= qrow0) ? fexp_s8(sc[ni][0]) : 0.0f;
            float p1 = (col0 + 1 <= qrow0) ? fexp_s8(sc[ni][1]) : 0.0f;
            float p2 = (col0     <= qrow1) ? fexp_s8(sc[ni][2]) : 0.0f;
            float p3 = (col0 + 1 <= qrow1) ? fexp_s8(sc[ni][3]) : 0.0f;
            lsum0 += p0 + p1;
            lsum1 += p2 + p3;
            sc[ni][0] = p0; sc[ni][1] = p1; sc[ni][2] = p2; sc[ni][3] = p3;
        }

        #pragma unroll
        for (int c = 0; c < 4; c++) {
            uint32_t ap[4];
            ap[0] = h2u(__floats2half2_rn(sc[2*c][0],   sc[2*c][1]));
            ap[1] = h2u(__floats2half2_rn(sc[2*c][2],   sc[2*c][3]));
            ap[2] = h2u(__floats2half2_rn(sc[2*c+1][0], sc[2*c+1][1]));
            ap[3] = h2u(__floats2half2_rn(sc[2*c+1][2], sc[2*c+1][3]));
            #pragma unroll
            for (int np = 0; np < 4; np++) {
                const uint32_t addr = vbase + (uint32_t)(
                    ((c * 16 + (mat & 1) * 8 + mrow) * 72
                     + np * 16 + (mat >> 1) * 8) * 2);
                uint32_t b0, b1, b2, b3;
                asm volatile(
                    "ldmatrix.sync.aligned.m8n8.x4.trans.shared.b16 "
                    "{%0,%1,%2,%3}, [%4];"
                    : "=r"(b0), "=r"(b1), "=r"(b2), "=r"(b3) : "r"(addr));
                uint32_t bfrA[2] = {b0, b1};
                uint32_t bfrB[2] = {b2, b3};
                MMA_F16(oacc[2 * np],     ap, bfrA);
                MMA_F16(oacc[2 * np + 1], ap, bfrB);
            }
        }
    }

    lsum0 += __shfl_xor_sync(FULL, lsum0, 1);
    lsum0 += __shfl_xor_sync(FULL, lsum0, 2);
    lsum1 += __shfl_xor_sync(FULL, lsum1, 1);
    lsum1 += __shfl_xor_sync(FULL, lsum1, 2);

    // store UNNORMALIZED partial O + partial row sums
    __half* op0 = opart + ((size_t)sp * 8192 + (size_t)b * T_SEQ + qrow0) * 256 + h * 64;
    __half* op1 = opart + ((size_t)sp * 8192 + (size_t)b * T_SEQ + qrow1) * 256 + h * 64;
    #pragma unroll
    for (int ni = 0; ni < 8; ni++) {
        *(__half2*)(op0 + ni * 8 + 2 * t) = __floats2half2_rn(oacc[ni][0], oacc[ni][1]);
        *(__half2*)(op1 + ni * 8 + 2 * t) = __floats2half2_rn(oacc[ni][2], oacc[ni][3]);
    }
    if (t == 0) {
        float* lp = lsum_part + sp * 32768 + (b * 4 + h) * 1024;
        lp[qrow0] = lsum0;
        lp[qrow1] = lsum1;
    }
}

// Combine: attn_h = (O0 + O1) / (l0 + l1).  2097152 elts / 8 / 256 = 1024 blocks.
__global__ void __launch_bounds__(256) attn_combine_kernel(
    const __half* __restrict__ opart, const float* __restrict__ lsp,
    __half* __restrict__ attn_h)
{
    const size_t e = ((size_t)blockIdx.x * 256 + threadIdx.x) * 8;
    const int row = (int)(e >> 8);
    const int col = (int)(e & 255);
    const int h   = col >> 6;
    const int b   = row >> 10;
    const int tq  = row & 1023;
    const float l0 = lsp[(b * 4 + h) * 1024 + tq];
    const float l1 = lsp[32768 + (b * 4 + h) * 1024 + tq];
    const float inv = 1.0f / (l0 + l1);

    uint4 u0 = *(const uint4*)(opart + e);
    uint4 u1 = *(const uint4*)(opart + 2097152ul + e);
    const __half2* p0 = (const __half2*)&u0;
    const __half2* p1 = (const __half2*)&u1;
    __half2 ov[4];
    #pragma unroll
    for (int i = 0; i < 4; i++) {
        float2 a = __half22float2(p0[i]);
        float2 c = __half22float2(p1[i]);
        ov[i] = __floats2half2_rn((a.x + c.x) * inv, (a.y + c.y) * inv);
    }
    *(uint4*)(attn_h + e) = *(uint4*)ov;
}

// ---------------------------------------------------------------------------
// LayerNorm, 2 rows/warp; optional fp16 shadow output (unchanged).
// ---------------------------------------------------------------------------
__global__ void __launch_bounds__(256) ln_warp_kernel(
    const float* __restrict__ in, long ld_in,
    const float* __restrict__ gamma, const float* __restrict__ beta,
    float* __restrict__ out, long ld_out, int nrows,
    __half* __restrict__ out_h)
{
    const int wid = threadIdx.x >> 5, lane = threadIdx.x & 31;
    const int rowA = blockIdx.x * 16 + wid * 2;
    const int rowB = rowA + 1;
    if (rowA >= nrows) return;
    const bool hasB = (rowB < nrows);

    const float* ipA = in + (size_t)rowA * ld_in + lane * 8;
    const float* ipB = in + (size_t)(hasB ? rowB : rowA) * ld_in + lane * 8;
    float4 a0 = ((const float4*)ipA)[0];
    float4 a1 = ((const float4*)ipA)[1];
    float4 b0 = ((const float4*)ipB)[0];
    float4 b1 = ((const float4*)ipB)[1];

    float sA  = a0.x + a0.y + a0.z + a0.w + a1.x + a1.y + a1.z + a1.w;
    float qA  = a0.x*a0.x + a0.y*a0.y + a0.z*a0.z + a0.w*a0.w
              + a1.x*a1.x + a1.y*a1.y + a1.z*a1.z + a1.w*a1.w;
    float sB  = b0.x + b0.y + b0.z + b0.w + b1.x + b1.y + b1.z + b1.w;
    float qB  = b0.x*b0.x + b0.y*b0.y + b0.z*b0.z + b0.w*b0.w
              + b1.x*b1.x + b1.y*b1.y + b1.z*b1.z + b1.w*b1.w;
    #pragma unroll
    for (int o = 16; o > 0; o >>= 1) {
        sA += __shfl_xor_sync(0xffffffffu, sA, o);
        sB += __shfl_xor_sync(0xffffffffu, sB, o);
        qA += __shfl_xor_sync(0xffffffffu, qA, o);
        qB += __shfl_xor_sync(0xffffffffu, qB, o);
    }
    const float mA = sA * (1.0f / 256.0f);
    const float vA = qA * (1.0f / 256.0f) - mA * mA;
    const float rA = rsqrtf(vA + 1e-5f);
    const float mB = sB * (1.0f / 256.0f);
    const float vB = qB * (1.0f / 256.0f) - mB * mB;
    const float rB = rsqrtf(vB + 1e-5f);

    const float4 g0 = ((const float4*)(gamma + lane * 8))[0];
    const float4 g1 = ((const float4*)(gamma + lane * 8))[1];
    const float4 be0 = ((const float4*)(beta  + lane * 8))[0];
    const float4 be1 = ((const float4*)(beta  + lane * 8))[1];

    float4 o0, o1;
    o0.x = (a0.x - mA) * rA * g0.x + be0.x;
    o0.y = (a0.y - mA) * rA * g0.y + be0.y;
    o0.z = (a0.z - mA) * rA * g0.z + be0.z;
    o0.w = (a0.w - mA) * rA * g0.w + be0.w;
    o1.x = (a1.x - mA) * rA * g1.x + be1.x;
    o1.y = (a1.y - mA) * rA * g1.y + be1.y;
    o1.z = (a1.z - mA) * rA * g1.z + be1.z;
    o1.w = (a1.w - mA) * rA * g1.w + be1.w;
    float* opA = out + (size_t)rowA * ld_out + lane * 8;
    ((float4*)opA)[0] = o0;
    ((float4*)opA)[1] = o1;
    if (out_h) {
        __half2 hh[4];
        hh[0] = __floats2half2_rn(o0.x, o0.y);
        hh[1] = __floats2half2_rn(o0.z, o0.w);
        hh[2] = __floats2half2_rn(o1.x, o1.y);
        hh[3] = __floats2half2_rn(o1.z, o1.w);
        *(uint4*)(out_h + (size_t)rowA * ld_out + lane * 8) = *(uint4*)hh;
    }

    if (hasB) {
        float4 p0, p1;
        p0.x = (b0.x - mB) * rB * g0.x + be0.x;
        p0.y = (b0.y - mB) * rB * g0.y + be0.y;
        p0.z = (b0.z - mB) * rB * g0.z + be0.z;
        p0.w = (b0.w - mB) * rB * g0.w + be0.w;
        p1.x = (b1.x - mB) * rB * g1.x + be1.x;
        p1.y = (b1.y - mB) * rB * g1.y + be1.y;
        p1.z = (b1.z - mB) * rB * g1.z + be1.z;
        p1.w = (b1.w - mB) * rB * g1.w + be1.w;
        float* opB = out + (size_t)rowB * ld_out + lane * 8;
        ((float4*)opB)[0] = p0;
        ((float4*)opB)[1] = p1;
        if (out_h) {
            __half2 hh[4];
            hh[0] = __floats2half2_rn(p0.x, p0.y);
            hh[1] = __floats2half2_rn(p0.z, p0.w);
            hh[2] = __floats2half2_rn(p1.x, p1.y);
            hh[3] = __floats2half2_rn(p1.z, p1.w);
            *(uint4*)(out_h + (size_t)rowB * ld_out + lane * 8) = *(uint4*)hh;
        }
    }
}

// ---------------------------------------------------------------------------
// Fused EMA + depthwise conv (unchanged).
// ---------------------------------------------------------------------------
__global__ void __launch_bounds__(256) ema_conv_kernel(
    const float* __restrict__ x, const float* __restrict__ cw,
    const float* __restrict__ cb, __half* __restrict__ comb_h,
    float* __restrict__ traj_out)
{
    const int b = blockIdx.x, chunk = blockIdx.y, d = threadIdx.x;
    const int t0 = chunk * 128;
    int start = t0 - 256; if (start < 0) start = 0;
    const float* xp = x + (size_t)b * 1024 * 256 + d;

    float w[8];
    #pragma unroll
    for (int i = 0; i < 8; i++) w[i] = cw[d * 8 + i];
    const float cbd = cb[d];

    float buf[8];
    #pragma unroll
    for (int i = 0; i < 8; i++) buf[i] = 0.0f;

    float c = 0.0f;
    for (int t = start; t < t0; t += 8) {
        #pragma unroll
        for (int p = 0; p < 8; p++) {
            float v = xp[(size_t)(t + p) * 256];
            c = fmaf(0.9f, c, 0.1f * v);
            buf[p] = v;
        }
    }

    __half* oe = comb_h + (size_t)b * 1024 * 768 + 512 + d;
    __half* oc = comb_h + (size_t)b * 1024 * 768 + 256 + d;
    for (int t = t0; t < t0 + 128; t += 8) {
        #pragma unroll
        for (int p = 0; p < 8; p++) {
            float v = xp[(size_t)(t + p) * 256];
            c = fmaf(0.9f, c, 0.1f * v);
            buf[p] = v;
            float r = cbd;
            #pragma unroll
            for (int q = 0; q < 8; q++)
                r = fmaf(w[q], buf[(p + 1 + q) & 7], r);
            oe[(size_t)(t + p) * 768] = __float2half_rn(c);
            oc[(size_t)(t + p) * 768] = __float2half_rn(r);
        }
    }
    if (chunk == 7) traj_out[b * 256 + d] = c;
}

// ---------------------------------------------------------------------------
// Scans over fp16 deltas (fp32 accumulate).
// ---------------------------------------------------------------------------
__global__ void __launch_bounds__(256) chunksum_kernel(
    const __half* __restrict__ deltas, float* __restrict__ csum)
{
    const int b = blockIdx.x, chunk = blockIdx.y, d = threadIdx.x;
    const __half* dp = deltas + ((size_t)b * 1024 + chunk * 128) * 256 + d;
    float s = 0.0f;
    #pragma unroll 8
    for (int t = 0; t < 128; t++) s += __half2float(dp[(size_t)t * 256]);
    csum[(b * 8 + chunk) * 256 + d] = s;
}

__global__ void __launch_bounds__(256) cumsum_kernel(
    const __half* __restrict__ deltas, const float* __restrict__ seq,
    const float* __restrict__ csum, float* __restrict__ states)
{
    const int b = blockIdx.x, chunk = blockIdx.y, d = threadIdx.x;
    float c = seq[b * 256 + d];
    for (int cc = 0; cc < 8; cc++)
        if (cc < chunk) c = fmaf(0.5f, csum[(b * 8 + cc) * 256 + d], c);
    const __half* dp = deltas + ((size_t)b * 1024 + chunk * 128) * 256 + d;
    float* sp = states + ((size_t)b * 1024 + chunk * 128) * 256 + d;
    #pragma unroll 8
    for (int t = 0; t < 128; t++) {
        c = fmaf(0.5f, __half2float(dp[(size_t)t * 256]), c);
        sp[(size_t)t * 256] = c;
    }
}

// ---------------------------------------------------------------------------
// Launch — fork/join side stream; split cvt; split-K attention + combine.
// ---------------------------------------------------------------------------
extern "C" void kernel_launch(void* const* d_in, const int* in_sizes, int n_in,
                              void* d_out, int out_size)
{
    const float* x_in       = (const float*)d_in[0];
    const float* seq_state  = (const float*)d_in[1];
    const float* in_proj_w  = (const float*)d_in[3];
    const float* in_proj_b  = (const float*)d_in[4];
    const float* out_proj_w = (const float*)d_in[5];
    const float* out_proj_b = (const float*)d_in[6];
    const float* conv_w     = (const float*)d_in[7];
    const float* conv_b     = (const float*)d_in[8];
    const float* p2s_w      = (const float*)d_in[9];
    const float* p2s_b      = (const float*)d_in[10];
    const float* s2p_w      = (const float*)d_in[11];
    const float* s2p_b      = (const float*)d_in[12];
    const float* tw1        = (const float*)d_in[13];
    const float* tb1        = (const float*)d_in[14];
    const float* tw2        = (const float*)d_in[15];
    const float* tb2        = (const float*)d_in[16];
    const float* fw1        = (const float*)d_in[17];
    const float* fb1        = (const float*)d_in[18];
    const float* fw2        = (const float*)d_in[19];
    const float* fb2        = (const float*)d_in[20];
    const float* ln1s = (const float*)d_in[21];
    const float* ln1b = (const float*)d_in[22];
    const float* ln2s = (const float*)d_in[23];
    const float* ln2b = (const float*)d_in[24];
    const float* ln3s = (const float*)d_in[25];
    const float* ln3b = (const float*)d_in[26];
    const float* ln4s = (const float*)d_in[27];
    const float* ln4b = (const float*)d_in[28];
    float* out = (float*)d_out;

    float* scr = nullptr;
    cudaGetSymbolAddress((void**)&scr, d_scratch);
    float*  tmp      = scr + OFF_TMP;
    float*  xb       = scr + OFF_X;
    float*  states   = scr + OFF_STATES;
    float*  csum     = scr + OFF_CSUM;
    __half* deltas_h = (__half*)(scr + OFF_DELTAS_H);
    __half* qkv_h    = (__half*)(scr + OFF_QKV_H);
    __half* xin_h    = (__half*)(scr + OFF_XIN_H);
    __half* attn_h   = (__half*)(scr + OFF_ATTN_H);
    __half* xb_h     = (__half*)(scr + OFF_XB_H);
    __half* comb_h   = (__half*)(scr + OFF_COMB_H);
    __half* hb_h     = (__half*)(scr + OFF_HB_H);
    __half* states_h = (__half*)(scr + OFF_STATES_H);
    __half* ffnin_h  = (__half*)(scr + OFF_FFNIN_H);
    __half* fbuf_h   = (__half*)(scr + OFF_FBUF_H);
    __half* w_h      = (__half*)(scr + OFF_WH);
    __half* opart    = (__half*)(scr + OFF_APART);
    float*  lsum_p   = scr + OFF_LSUM;

    static cudaStream_t s2 = nullptr;
    static cudaEvent_t evA = nullptr, evB = nullptr, evC = nullptr, evD = nullptr;
    static cudaEvent_t evE = nullptr, evF = nullptr;
    static bool init_done = false;
    if (!init_done) {
        cudaFuncSetAttribute(mma_gemm<0,true,128>,  cudaFuncAttributeMaxDynamicSharedMemorySize, GEMM_SMEM_128);
        cudaFuncSetAttribute(mma_gemm<2,true,128>,  cudaFuncAttributeMaxDynamicSharedMemorySize, GEMM_SMEM_128);
        cudaFuncSetAttribute(mma_gemm<1,false,64>,  cudaFuncAttributeMaxDynamicSharedMemorySize, GEMM_SMEM_64);
        cudaFuncSetAttribute(mma_gemm<3,true,64>,   cudaFuncAttributeMaxDynamicSharedMemorySize, GEMM_SMEM_64);
        cudaFuncSetAttribute(mma_gemm<0,true,64>,   cudaFuncAttributeMaxDynamicSharedMemorySize, GEMM_SMEM_64);
        cudaFuncSetAttribute(attn_mma_kernel, cudaFuncAttributeMaxDynamicSharedMemorySize, ATTN_SMEM);
        cudaStreamCreateWithFlags(&s2, cudaStreamNonBlocking);
        cudaEventCreateWithFlags(&evA, cudaEventDisableTiming);
        cudaEventCreateWithFlags(&evB, cudaEventDisableTiming);
        cudaEventCreateWithFlags(&evC, cudaEventDisableTiming);
        cudaEventCreateWithFlags(&evD, cudaEventDisableTiming);
        cudaEventCreateWithFlags(&evE, cudaEventDisableTiming);
        cudaEventCreateWithFlags(&evF, cudaEventDisableTiming);
        init_done = true;
    }

    // 0a. convert x_in + w_ip (qkv inputs)
    cvt_p1_kernel<<<1120, 256>>>(x_in, in_proj_w, xin_h, w_h);
    // fork: remaining weights on side stream (overlaps qkv + attention)
    cudaEventRecord(evE, 0);
    cudaStreamWaitEvent(s2, evE, 0);
    cvt_p2_kernel<<<608, 256, 0, s2>>>(out_proj_w, p2s_w, s2p_w, tw1, tw2,
                                       fw1, fw2, w_h);
    cudaEventRecord(evF, s2);

    // 1. qkv = x @ in_proj_w^T + b
    mma_gemm<0,true,128><<<dim3(6, 64), 256, GEMM_SMEM_128>>>(xin_h, 256, w_h + WH_IP, in_proj_b,
                                                              nullptr, 0, qkv_h, 768, 256);
    // 2. causal attention, split-K=2, then combine
    attn_mma_kernel<<<dim3(8, 32, 2), 256, ATTN_SMEM>>>(qkv_h, opart, lsum_p);
    attn_combine_kernel<<<1024, 256>>>(opart, lsum_p, attn_h);
    cudaStreamWaitEvent(0, evF, 0);   // weights ready before out_proj
    // 3. out_proj + residual(x_in)
    mma_gemm<1,false,64><<<dim3(2, 128), 256, GEMM_SMEM_64>>>(attn_h, 256, w_h + WH_OP, out_proj_b,
                                                              x_in, 256, tmp, 256, 256);
    // 4. x = LN1(tmp)
    ln_warp_kernel<<<512, 256>>>(tmp, 256, ln1s, ln1b, xb, 256, 8192, xb_h);

    // fork: ema+conv (side) || p2s GEMM (main)
    cudaEventRecord(evA, 0);
    cudaStreamWaitEvent(s2, evA, 0);
    ema_conv_kernel<<<dim3(8, 8), 256, 0, s2>>>(xb, conv_w, conv_b, comb_h,
                                                out + (size_t)M_ROWS * 256 + 2048);
    cudaEventRecord(evB, s2);
    // 7. comb_h[:,0:256] = x + 0.3*(x @ p2s^T + b)
    mma_gemm<3,true,64><<<dim3(2, 128), 256, GEMM_SMEM_64>>>(xb_h, 256, w_h + WH_P2S, p2s_b,
                                                             xb, 256, comb_h, 768, 256);
    cudaStreamWaitEvent(0, evB, 0);

    // 8. h = gelu(comb @ tw1^T + b1)
    mma_gemm<2,true,128><<<dim3(4, 64), 256, GEMM_SMEM_128>>>(comb_h, 768, w_h + WH_TW1, tb1,
                                                              nullptr, 0, hb_h, 512, 768);
    // 9. deltas = h @ tw2^T + b2  (fp16)
    mma_gemm<0,true,64><<<dim3(2, 128), 256, GEMM_SMEM_64>>>(hb_h, 512, w_h + WH_TW2, tb2,
                                                             nullptr, 0, deltas_h, 256, 512);
    // 10. states = seq + 0.5*cumsum(deltas)
    chunksum_kernel<<<dim3(8, 8), 256>>>(deltas_h, csum);
    cumsum_kernel<<<dim3(8, 8), 256>>>(deltas_h, seq_state, csum, states);
    // 11. states = LN3(states)
    ln_warp_kernel<<<512, 256>>>(states, 256, ln3s, ln3b, states, 256, 8192, states_h);

    // fork: LN4 (side) || ffn chain (main)
    cudaEventRecord(evC, 0);
    cudaStreamWaitEvent(s2, evC, 0);
    ln_warp_kernel<<<1, 256, 0, s2>>>(states + (size_t)1023 * 256, (long)1024 * 256,
                                      ln4s, ln4b, out + (size_t)M_ROWS * 256, 256, 8, nullptr);
    cudaEventRecord(evD, s2);

    // 12. ffn_in = x + 0.3*(states @ s2p^T + b)
    mma_gemm<3,true,64><<<dim3(2, 128), 256, GEMM_SMEM_64>>>(states_h, 256, w_h + WH_S2P, s2p_b,
                                                             xb, 256, ffnin_h, 256, 256);
    // 13. f = gelu(ffn_in @ fw1^T + b1)
    mma_gemm<2,true,128><<<dim3(8, 64), 256, GEMM_SMEM_128>>>(ffnin_h, 256, w_h + WH_FW1, fb1,
                                                              nullptr, 0, fbuf_h, 1024, 256);
    // 14. tmp = x + f @ fw2^T + b2
    mma_gemm<1,false,64><<<dim3(2, 128), 256, GEMM_SMEM_64>>>(fbuf_h, 1024, w_h + WH_FW2, fb2,
                                                              xb, 256, tmp, 256, 1024);
    // 15. LN2 -> out
    ln_warp_kernel<<<512, 256>>>(tmp, 256, ln2s, ln2b, out, 256, 8192, nullptr);

    cudaStreamWaitEvent(0, evD, 0);
}